// round 6
// baseline (speedup 1.0000x reference)
#include <cuda_runtime.h>
#include <cuda_bf16.h>
#include <math.h>
#include <stdint.h>

// Problem constants
constexpr int BATCH = 2, SEQ = 2048, HID = 2048;
constexpr int NHEADS = 16, GRP = 4, HDIM = 128;
constexpr int MROWS = BATCH * SEQ;        // 4096
constexpr int KVDIM = GRP * HDIM;         // 512

// ---------------------------------------------------------------------------
// Device-global scratch
// ---------------------------------------------------------------------------
__device__ __nv_bfloat16 g_Xhi[MROWS * HID];
__device__ __nv_bfloat16 g_Xlo[MROWS * HID];
__device__ __nv_bfloat16 g_Qhi[MROWS * HID];
__device__ __nv_bfloat16 g_Qlo[MROWS * HID];
__device__ __nv_bfloat16 g_Khi[MROWS * KVDIM];
__device__ __nv_bfloat16 g_Klo[MROWS * KVDIM];
__device__ __nv_bfloat16 g_Vhi[MROWS * KVDIM];
__device__ __nv_bfloat16 g_Vlo[MROWS * KVDIM];
__device__ __nv_bfloat16 g_AOhi[MROWS * HID];
__device__ __nv_bfloat16 g_AOlo[MROWS * HID];
// Transposed weights, [N][K] K-major
__device__ __nv_bfloat16 g_WqThi[HID * HID];
__device__ __nv_bfloat16 g_WqTlo[HID * HID];
__device__ __nv_bfloat16 g_WkThi[KVDIM * HID];
__device__ __nv_bfloat16 g_WkTlo[KVDIM * HID];
__device__ __nv_bfloat16 g_WvThi[KVDIM * HID];
__device__ __nv_bfloat16 g_WvTlo[KVDIM * HID];
__device__ __nv_bfloat16 g_WoThi[HID * HID];
__device__ __nv_bfloat16 g_WoTlo[HID * HID];

// ---------------------------------------------------------------------------
// Helpers
// ---------------------------------------------------------------------------
__device__ __forceinline__ uint32_t smem_u32(const void* p) {
    uint32_t a;
    asm("{ .reg .u64 t; cvta.to.shared.u64 t, %1; cvt.u32.u64 %0, t; }"
        : "=r"(a) : "l"(p));
    return a;
}
__device__ __forceinline__ void cp16(uint32_t saddr, const void* gaddr) {
    asm volatile("cp.async.cg.shared.global [%0], [%1], 16;"
                 :: "r"(saddr), "l"(gaddr));
}
__device__ __forceinline__ void mma_bf16(float* c, const uint32_t* a, const uint32_t* b) {
    asm volatile("mma.sync.aligned.m16n8k16.row.col.f32.bf16.bf16.f32 "
                 "{%0,%1,%2,%3}, {%4,%5,%6,%7}, {%8,%9}, {%0,%1,%2,%3};"
                 : "+f"(c[0]), "+f"(c[1]), "+f"(c[2]), "+f"(c[3])
                 : "r"(a[0]), "r"(a[1]), "r"(a[2]), "r"(a[3]),
                   "r"(b[0]), "r"(b[1]));
}
#define LDMX4(r0, r1, r2, r3, addr) \
    asm volatile("ldmatrix.sync.aligned.m8n8.x4.shared.b16 {%0,%1,%2,%3}, [%4];" \
                 : "=r"(r0), "=r"(r1), "=r"(r2), "=r"(r3) : "r"(addr))
#define LDMX4T(r0, r1, r2, r3, addr) \
    asm volatile("ldmatrix.sync.aligned.m8n8.x4.trans.shared.b16 {%0,%1,%2,%3}, [%4];" \
                 : "=r"(r0), "=r"(r1), "=r"(r2), "=r"(r3) : "r"(addr))

__device__ __forceinline__ uint32_t packbf(float x, float y) {
    __nv_bfloat162 t = __floats2bfloat162_rn(x, y);
    return *(uint32_t*)&t;
}

// ---------------------------------------------------------------------------
// Split fp32 -> hi/lo bf16
// ---------------------------------------------------------------------------
__global__ __launch_bounds__(256)
void split_kernel(const float* __restrict__ x, __nv_bfloat16* __restrict__ hi,
                  __nv_bfloat16* __restrict__ lo, int n4)
{
    int i = blockIdx.x * blockDim.x + threadIdx.x;
    if (i >= n4) return;
    float4 v = ((const float4*)x)[i];
    __nv_bfloat16 h0 = __float2bfloat16(v.x), h1 = __float2bfloat16(v.y);
    __nv_bfloat16 h2 = __float2bfloat16(v.z), h3 = __float2bfloat16(v.w);
    ((__nv_bfloat162*)hi)[i * 2 + 0] = __nv_bfloat162(h0, h1);
    ((__nv_bfloat162*)hi)[i * 2 + 1] = __nv_bfloat162(h2, h3);
    ((__nv_bfloat162*)lo)[i * 2 + 0] =
        __nv_bfloat162(__float2bfloat16(v.x - __bfloat162float(h0)),
                       __float2bfloat16(v.y - __bfloat162float(h1)));
    ((__nv_bfloat162*)lo)[i * 2 + 1] =
        __nv_bfloat162(__float2bfloat16(v.z - __bfloat162float(h2)),
                       __float2bfloat16(v.w - __bfloat162float(h3)));
}

// ---------------------------------------------------------------------------
// Transpose W[K][N] -> T[N][K] with hi/lo bf16 split
// ---------------------------------------------------------------------------
__global__ __launch_bounds__(256)
void transpose_split_kernel(const float* __restrict__ W,
                            __nv_bfloat16* __restrict__ Thi,
                            __nv_bfloat16* __restrict__ Tlo, int K, int N)
{
    __shared__ float tile[32][33];
    int n0 = blockIdx.x * 32, k0 = blockIdx.y * 32;
    int tx = threadIdx.x & 31, ty = threadIdx.x >> 5;
    for (int j = ty; j < 32; j += 8)
        tile[j][tx] = W[(size_t)(k0 + j) * N + n0 + tx];
    __syncthreads();
    for (int j = ty; j < 32; j += 8) {
        float v = tile[tx][j];
        __nv_bfloat16 h = __float2bfloat16(v);
        size_t o = (size_t)(n0 + j) * K + k0 + tx;
        Thi[o] = h;
        Tlo[o] = __float2bfloat16(v - __bfloat162float(h));
    }
}

// ---------------------------------------------------------------------------
// HMMA GEMM body: C = (Ahi+Alo)[M,K] @ (Bhi+Blo)[N,K]^T + bias
// 128x128 CTA tile, 8 warps (2x4), ldmatrix fragment loads, cp.async 2-stage.
// ---------------------------------------------------------------------------
constexpr int BK = 32;
constexpr int RSTRIDE = 40;                         // bf16 per smem row (80 B)
constexpr int TILE_BYTES2 = 128 * RSTRIDE * 2;      // 10240 B per tile
constexpr int GEMM_SMEM = 2 * 4 * TILE_BYTES2;      // 81920 B

template <bool SPLIT>
__device__ __forceinline__ void gemm_body(
    const __nv_bfloat16* __restrict__ Ahi, const __nv_bfloat16* __restrict__ Alo,
    const __nv_bfloat16* __restrict__ Bhi, const __nv_bfloat16* __restrict__ Blo,
    const float* __restrict__ bias, float* __restrict__ C,
    __nv_bfloat16* __restrict__ Chi, __nv_bfloat16* __restrict__ Clo,
    int N, int K, char* smptr)
{
    const uint32_t sbase = smem_u32(smptr);
    const int tid = threadIdx.x;
    const int wid = tid >> 5, lid = tid & 31;
    const int wm = wid >> 2, wn = wid & 3;
    const int m0 = blockIdx.y * 128, n0 = blockIdx.x * 128;

    const int tile = tid >> 6;
    const int tl = tid & 63;
    const __nv_bfloat16* tsrc =
        (tile == 0) ? Ahi + (size_t)m0 * K :
        (tile == 1) ? Alo + (size_t)m0 * K :
        (tile == 2) ? Bhi + (size_t)n0 * K :
                      Blo + (size_t)n0 * K;

    float acc[4][4][4];
#pragma unroll
    for (int mt = 0; mt < 4; mt++)
#pragma unroll
        for (int nt = 0; nt < 4; nt++)
#pragma unroll
            for (int j = 0; j < 4; j++) acc[mt][nt][j] = 0.f;

    const int nch = K / BK;

    auto issue = [&](int ch, int buf) {
        const __nv_bfloat16* src = tsrc + ch * BK;
        uint32_t base = sbase + (uint32_t)(buf * 4 + tile) * TILE_BYTES2;
#pragma unroll
        for (int it = 0; it < 8; it++) {
            int o = tl + it * 64;
            int row = o >> 2, seg = o & 3;
            cp16(base + row * 80 + seg * 16, src + (size_t)row * K + seg * 8);
        }
        asm volatile("cp.async.commit_group;" ::: "memory");
    };

    issue(0, 0);

    // ldmatrix lane addressing: matrices (rows0-7,k0-7),(rows8-15,k0-7),
    // (rows0-7,k8-15),(rows8-15,k8-15)
    const int laneRow = (lid & 7) + ((lid >> 3) & 1) * 8;
    const int laneCol = (lid >> 4) * 16;

    for (int ch = 0; ch < nch; ch++) {
        const int buf = ch & 1;
        if (ch + 1 < nch) {
            issue(ch + 1, buf ^ 1);
            asm volatile("cp.async.wait_group 1;" ::: "memory");
        } else {
            asm volatile("cp.async.wait_group 0;" ::: "memory");
        }
        __syncthreads();

        const uint32_t AbH = sbase + (uint32_t)(buf * 4 + 0) * TILE_BYTES2
                           + (wm * 64 + laneRow) * 80 + laneCol;
        const uint32_t AbL = AbH + TILE_BYTES2;
        const uint32_t BbH = sbase + (uint32_t)(buf * 4 + 2) * TILE_BYTES2
                           + (wn * 32 + laneRow) * 80 + laneCol;
        const uint32_t BbL = BbH + TILE_BYTES2;

#pragma unroll
        for (int ks = 0; ks < 2; ks++) {
            const uint32_t kb = ks * 32;
            uint32_t aHi[4][4], aLo[4][4], bHi[4][2], bLo[4][2];
#pragma unroll
            for (int mt = 0; mt < 4; mt++) {
                LDMX4(aHi[mt][0], aHi[mt][1], aHi[mt][2], aHi[mt][3],
                      AbH + mt * 16 * 80 + kb);
                LDMX4(aLo[mt][0], aLo[mt][1], aLo[mt][2], aLo[mt][3],
                      AbL + mt * 16 * 80 + kb);
            }
#pragma unroll
            for (int j = 0; j < 2; j++) {
                uint32_t t0, t1, t2, t3;
                // t0=(n j*16+0..7, k0-7) t1=(n j*16+8..15, k0-7)
                // t2=(n j*16+0..7, k8-15) t3=(n j*16+8..15, k8-15)
                LDMX4(t0, t1, t2, t3, BbH + j * 16 * 80 + kb);
                bHi[2 * j][0] = t0; bHi[2 * j][1] = t2;      // FIXED: t2 is k8-15
                bHi[2 * j + 1][0] = t1; bHi[2 * j + 1][1] = t3;
                LDMX4(t0, t1, t2, t3, BbL + j * 16 * 80 + kb);
                bLo[2 * j][0] = t0; bLo[2 * j][1] = t2;
                bLo[2 * j + 1][0] = t1; bLo[2 * j + 1][1] = t3;
            }
#pragma unroll
            for (int mt = 0; mt < 4; mt++)
#pragma unroll
                for (int nt = 0; nt < 4; nt++)
                    mma_bf16(acc[mt][nt], aHi[mt], bHi[nt]);
#pragma unroll
            for (int mt = 0; mt < 4; mt++)
#pragma unroll
                for (int nt = 0; nt < 4; nt++)
                    mma_bf16(acc[mt][nt], aHi[mt], bLo[nt]);
#pragma unroll
            for (int mt = 0; mt < 4; mt++)
#pragma unroll
                for (int nt = 0; nt < 4; nt++)
                    mma_bf16(acc[mt][nt], aLo[mt], bHi[nt]);
        }
        __syncthreads();
    }

    const int rbase = m0 + wm * 64 + (lid >> 2);
    const int cbase = n0 + wn * 32 + (lid & 3) * 2;
#pragma unroll
    for (int mt = 0; mt < 4; mt++) {
#pragma unroll
        for (int nt = 0; nt < 4; nt++) {
            int r = rbase + mt * 16;
            int c = cbase + nt * 8;
            float bx = __ldg(&bias[c]), by = __ldg(&bias[c + 1]);
            float v00 = acc[mt][nt][0] + bx, v01 = acc[mt][nt][1] + by;
            float v10 = acc[mt][nt][2] + bx, v11 = acc[mt][nt][3] + by;
            if (SPLIT) {
                __nv_bfloat16 h00 = __float2bfloat16(v00), h01 = __float2bfloat16(v01);
                __nv_bfloat16 h10 = __float2bfloat16(v10), h11 = __float2bfloat16(v11);
                *(__nv_bfloat162*)&Chi[(size_t)r * N + c] = __nv_bfloat162(h00, h01);
                *(__nv_bfloat162*)&Chi[(size_t)(r + 8) * N + c] = __nv_bfloat162(h10, h11);
                *(__nv_bfloat162*)&Clo[(size_t)r * N + c] =
                    __nv_bfloat162(__float2bfloat16(v00 - __bfloat162float(h00)),
                                   __float2bfloat16(v01 - __bfloat162float(h01)));
                *(__nv_bfloat162*)&Clo[(size_t)(r + 8) * N + c] =
                    __nv_bfloat162(__float2bfloat16(v10 - __bfloat162float(h10)),
                                   __float2bfloat16(v11 - __bfloat162float(h11)));
            } else {
                *(float2*)&C[(size_t)r * N + c] = make_float2(v00, v01);
                *(float2*)&C[(size_t)(r + 8) * N + c] = make_float2(v10, v11);
            }
        }
    }
}

template <bool SPLIT>
__global__ __launch_bounds__(256, 1)
void mma_gemm_kernel(const __nv_bfloat16* __restrict__ Ahi,
                     const __nv_bfloat16* __restrict__ Alo,
                     const __nv_bfloat16* __restrict__ Bhi,
                     const __nv_bfloat16* __restrict__ Blo,
                     const float* __restrict__ bias,
                     float* __restrict__ C,
                     __nv_bfloat16* __restrict__ Chi,
                     __nv_bfloat16* __restrict__ Clo,
                     int N, int K)
{
    extern __shared__ char smg[];
    gemm_body<SPLIT>(Ahi, Alo, Bhi, Blo, bias, C, Chi, Clo, N, K, smg);
}

// Fused K+V projection: blockIdx.z selects weight/output set.
__global__ __launch_bounds__(256, 1)
void mma_gemm_kv_kernel(const __nv_bfloat16* __restrict__ Ahi,
                        const __nv_bfloat16* __restrict__ Alo,
                        const __nv_bfloat16* __restrict__ BhiK,
                        const __nv_bfloat16* __restrict__ BloK,
                        const float* __restrict__ biasK,
                        __nv_bfloat16* __restrict__ KChi,
                        __nv_bfloat16* __restrict__ KClo,
                        const __nv_bfloat16* __restrict__ BhiV,
                        const __nv_bfloat16* __restrict__ BloV,
                        const float* __restrict__ biasV,
                        __nv_bfloat16* __restrict__ VChi,
                        __nv_bfloat16* __restrict__ VClo,
                        int N, int K)
{
    extern __shared__ char smg[];
    if (blockIdx.z == 0)
        gemm_body<true>(Ahi, Alo, BhiK, BloK, biasK, nullptr, KChi, KClo, N, K, smg);
    else
        gemm_body<true>(Ahi, Alo, BhiV, BloV, biasV, nullptr, VChi, VClo, N, K, smg);
}

// ---------------------------------------------------------------------------
// HMMA flash attention (causal GQA), double-buffered KV, ldmatrix fragments.
// CTA: 128 Q rows x one (head, batch). 8 warps x 16 Q rows.
// ---------------------------------------------------------------------------
constexpr int QT = 128, KT = 64;
constexpr int STRB = 272;                      // smem row stride bytes
constexpr int QTILE = QT * STRB;               // 34816
constexpr int KVT = KT * STRB;                 // 17408 per tile
constexpr int OFF_QHI = 0;
constexpr int OFF_QLO = QTILE;
constexpr int OFF_KV  = 2 * QTILE;             // 69632
constexpr int KVBUF   = 4 * KVT;               // 69632 (Khi,Klo,Vhi,Vlo)
constexpr int FLASH_SMEM = OFF_KV + 2 * KVBUF; // 208896
constexpr float SM_SCALE = 0.08838834764831845f;

__global__ __launch_bounds__(256, 1)
void flash_mma_kernel(const __nv_bfloat16* __restrict__ Qhi,
                      const __nv_bfloat16* __restrict__ Qlo,
                      const __nv_bfloat16* __restrict__ Khi,
                      const __nv_bfloat16* __restrict__ Klo,
                      const __nv_bfloat16* __restrict__ Vhi,
                      const __nv_bfloat16* __restrict__ Vlo,
                      __nv_bfloat16* __restrict__ Ohi,
                      __nv_bfloat16* __restrict__ Olo)
{
    extern __shared__ __nv_bfloat16 shb[];
    const uint32_t sb = smem_u32(shb);
    const int tid = threadIdx.x;
    const int w = tid >> 5, lid = tid & 31;
    const int rq = lid >> 2, cq = lid & 3;
    const int qt = blockIdx.x, h = blockIdx.y, b = blockIdx.z;
    const int g = h >> 2;
    const int q0 = qt * QT;

    // ---- load Q tile (hi+lo) ----
    {
        const __nv_bfloat16* srcs[2] = {Qhi, Qlo};
#pragma unroll
        for (int it = 0; it < 16; it++) {
            int idx = it * 256 + tid;
            int arr = idx >> 11, rem = idx & 2047;
            int row = rem >> 4, seg = rem & 15;
            const __nv_bfloat16* gp = srcs[arr]
                + (size_t)(b * SEQ + q0 + row) * HID + h * HDIM + seg * 8;
            cp16(sb + (arr ? OFF_QLO : OFF_QHI) + row * STRB + seg * 16, gp);
        }
        asm volatile("cp.async.commit_group;" ::: "memory");
    }

    const int nkt = 2 * qt + 2;

    auto load_kv = [&](int kt) {
        const uint32_t bb = sb + OFF_KV + (uint32_t)(kt & 1) * KVBUF;
        const int k0 = kt * KT;
        const __nv_bfloat16* srcs[4] = {Khi, Klo, Vhi, Vlo};
#pragma unroll
        for (int it = 0; it < 16; it++) {
            int idx = it * 256 + tid;
            int arr = idx >> 10, rem = idx & 1023;
            int row = rem >> 4, seg = rem & 15;
            const __nv_bfloat16* gp = srcs[arr]
                + (size_t)(b * SEQ + k0 + row) * KVDIM + g * HDIM + seg * 8;
            cp16(bb + arr * KVT + row * STRB + seg * 16, gp);
        }
        asm volatile("cp.async.commit_group;" ::: "memory");
    };

    load_kv(0);

    float oacc[16][4];
#pragma unroll
    for (int nt = 0; nt < 16; nt++)
#pragma unroll
        for (int j = 0; j < 4; j++) oacc[nt][j] = 0.f;
    float m0 = -INFINITY, m1 = -INFINITY, l0 = 0.f, l1 = 0.f;

    const int iwmin = q0 + w * 16;
    const int i0 = iwmin + rq;
    const int laneRow = (lid & 7) + ((lid >> 3) & 1) * 8;
    const int laneCol = (lid >> 4) * 16;

    for (int kt = 0; kt < nkt; kt++) {
        const int k0 = kt * KT;
        __syncthreads();
        if (kt + 1 < nkt) {
            load_kv(kt + 1);
            asm volatile("cp.async.wait_group 1;" ::: "memory");
        } else {
            asm volatile("cp.async.wait_group 0;" ::: "memory");
        }
        __syncthreads();

        if (k0 > iwmin + 15) continue;       // fully masked for this warp

        const uint32_t kvb = sb + OFF_KV + (uint32_t)(kt & 1) * KVBUF;
        const uint32_t KbH = kvb + laneRow * STRB + laneCol;
        const uint32_t KbL = KbH + KVT;
        const uint32_t QbH = sb + OFF_QHI + (w * 16 + laneRow) * STRB + laneCol;
        const uint32_t QbL = QbH + QTILE;

        // ---- S = Q K^T (3 split terms) ----
        float sacc[8][4];
#pragma unroll
        for (int nt = 0; nt < 8; nt++)
#pragma unroll
            for (int j = 0; j < 4; j++) sacc[nt][j] = 0.f;

#pragma unroll
        for (int ks = 0; ks < 8; ks++) {
            const uint32_t kb = ks * 32;
            uint32_t aHi[4], aLo[4], bHi[8][2], bLo[8][2];
            LDMX4(aHi[0], aHi[1], aHi[2], aHi[3], QbH + kb);
            LDMX4(aLo[0], aLo[1], aLo[2], aLo[3], QbL + kb);
#pragma unroll
            for (int j = 0; j < 4; j++) {
                uint32_t t0, t1, t2, t3;
                LDMX4(t0, t1, t2, t3, KbH + j * 16 * STRB + kb);
                bHi[2 * j][0] = t0; bHi[2 * j][1] = t2;      // FIXED ordering
                bHi[2 * j + 1][0] = t1; bHi[2 * j + 1][1] = t3;
                LDMX4(t0, t1, t2, t3, KbL + j * 16 * STRB + kb);
                bLo[2 * j][0] = t0; bLo[2 * j][1] = t2;
                bLo[2 * j + 1][0] = t1; bLo[2 * j + 1][1] = t3;
            }
#pragma unroll
            for (int nt = 0; nt < 8; nt++) {
                mma_bf16(sacc[nt], aHi, bHi[nt]);
                mma_bf16(sacc[nt], aHi, bLo[nt]);
                mma_bf16(sacc[nt], aLo, bHi[nt]);
            }
        }

        // ---- scale + causal mask ----
        const bool need_mask = (k0 + KT - 1) > iwmin;
#pragma unroll
        for (int nt = 0; nt < 8; nt++) {
#pragma unroll
            for (int j = 0; j < 4; j++) {
                float s = sacc[nt][j] * SM_SCALE;
                if (need_mask) {
                    int jj = k0 + nt * 8 + cq * 2 + (j & 1);
                    int ii = i0 + ((j >> 1) << 3);
                    if (jj > ii) s = -1e30f;
                }
                sacc[nt][j] = s;
            }
        }

        // ---- online softmax ----
        float mx0 = -INFINITY, mx1 = -INFINITY;
#pragma unroll
        for (int nt = 0; nt < 8; nt++) {
            mx0 = fmaxf(mx0, fmaxf(sacc[nt][0], sacc[nt][1]));
            mx1 = fmaxf(mx1, fmaxf(sacc[nt][2], sacc[nt][3]));
        }
        mx0 = fmaxf(mx0, __shfl_xor_sync(0xffffffffu, mx0, 1));
        mx0 = fmaxf(mx0, __shfl_xor_sync(0xffffffffu, mx0, 2));
        mx1 = fmaxf(mx1, __shfl_xor_sync(0xffffffffu, mx1, 1));
        mx1 = fmaxf(mx1, __shfl_xor_sync(0xffffffffu, mx1, 2));
        float mn0 = fmaxf(m0, mx0), mn1 = fmaxf(m1, mx1);
        float al0 = __expf(m0 - mn0), al1 = __expf(m1 - mn1);
        m0 = mn0; m1 = mn1;

        float ls0 = 0.f, ls1 = 0.f;
#pragma unroll
        for (int nt = 0; nt < 8; nt++) {
            float p0 = __expf(sacc[nt][0] - mn0);
            float p1 = __expf(sacc[nt][1] - mn0);
            float p2 = __expf(sacc[nt][2] - mn1);
            float p3 = __expf(sacc[nt][3] - mn1);
            ls0 += p0 + p1; ls1 += p2 + p3;
            sacc[nt][0] = p0; sacc[nt][1] = p1; sacc[nt][2] = p2; sacc[nt][3] = p3;
        }
        ls0 += __shfl_xor_sync(0xffffffffu, ls0, 1);
        ls0 += __shfl_xor_sync(0xffffffffu, ls0, 2);
        ls1 += __shfl_xor_sync(0xffffffffu, ls1, 1);
        ls1 += __shfl_xor_sync(0xffffffffu, ls1, 2);
        l0 = l0 * al0 + ls0;
        l1 = l1 * al1 + ls1;

#pragma unroll
        for (int nt = 0; nt < 16; nt++) {
            oacc[nt][0] *= al0; oacc[nt][1] *= al0;
            oacc[nt][2] *= al1; oacc[nt][3] *= al1;
        }

        // ---- O += P V (3 split terms) ----
        const uint32_t VbH = kvb + 2 * KVT;
#pragma unroll
        for (int ks = 0; ks < 4; ks++) {
            uint32_t aHi[4], aLo[4];
#pragma unroll
            for (int half = 0; half < 2; half++) {
                const float* p = sacc[2 * ks + half];
                float h0 = __bfloat162float(__float2bfloat16(p[0]));
                float h1 = __bfloat162float(__float2bfloat16(p[1]));
                float h2 = __bfloat162float(__float2bfloat16(p[2]));
                float h3 = __bfloat162float(__float2bfloat16(p[3]));
                aHi[2 * half + 0] = packbf(h0, h1);
                aHi[2 * half + 1] = packbf(h2, h3);
                aLo[2 * half + 0] = packbf(p[0] - h0, p[1] - h1);
                aLo[2 * half + 1] = packbf(p[2] - h2, p[3] - h3);
            }
#pragma unroll
            for (int ntp = 0; ntp < 8; ntp++) {
                const uint32_t va = VbH + (ks * 16 + (lid & 15)) * STRB
                                  + (ntp * 16 + ((lid >> 4) << 3)) * 2;
                uint32_t bh0, bh1, bh2, bh3, bl0, bl1, bl2, bl3;
                LDMX4T(bh0, bh1, bh2, bh3, va);
                LDMX4T(bl0, bl1, bl2, bl3, va + KVT);
                uint32_t bhA[2] = {bh0, bh1}, bhB[2] = {bh2, bh3};
                uint32_t blA[2] = {bl0, bl1}, blB[2] = {bl2, bl3};
                mma_bf16(oacc[2 * ntp + 0], aHi, bhA);
                mma_bf16(oacc[2 * ntp + 0], aHi, blA);
                mma_bf16(oacc[2 * ntp + 0], aLo, bhA);
                mma_bf16(oacc[2 * ntp + 1], aHi, bhB);
                mma_bf16(oacc[2 * ntp + 1], aHi, blB);
                mma_bf16(oacc[2 * ntp + 1], aLo, bhB);
            }
        }
    }

    // ---- normalize + store ----
    const float rl0 = 1.f / l0, rl1 = 1.f / l1;
    const size_t row0 = (size_t)(b * SEQ + q0 + w * 16 + rq);
#pragma unroll
    for (int nt = 0; nt < 16; nt++) {
        int col = h * HDIM + nt * 8 + cq * 2;
        float v00 = oacc[nt][0] * rl0, v01 = oacc[nt][1] * rl0;
        float v10 = oacc[nt][2] * rl1, v11 = oacc[nt][3] * rl1;
        __nv_bfloat16 h00 = __float2bfloat16(v00), h01 = __float2bfloat16(v01);
        __nv_bfloat16 h10 = __float2bfloat16(v10), h11 = __float2bfloat16(v11);
        *(__nv_bfloat162*)&Ohi[row0 * HID + col] = __nv_bfloat162(h00, h01);
        *(__nv_bfloat162*)&Ohi[(row0 + 8) * HID + col] = __nv_bfloat162(h10, h11);
        *(__nv_bfloat162*)&Olo[row0 * HID + col] =
            __nv_bfloat162(__float2bfloat16(v00 - __bfloat162float(h00)),
                           __float2bfloat16(v01 - __bfloat162float(h01)));
        *(__nv_bfloat162*)&Olo[(row0 + 8) * HID + col] =
            __nv_bfloat162(__float2bfloat16(v10 - __bfloat162float(h10)),
                           __float2bfloat16(v11 - __bfloat162float(h11)));
    }
}

// ---------------------------------------------------------------------------
// Launch
// ---------------------------------------------------------------------------
extern "C" void kernel_launch(void* const* d_in, const int* in_sizes, int n_in,
                              void* d_out, int out_size)
{
    const float* x  = (const float*)d_in[0];
    const float* Wq = (const float*)d_in[2];
    const float* bq = (const float*)d_in[3];
    const float* Wk = (const float*)d_in[4];
    const float* bk = (const float*)d_in[5];
    const float* Wv = (const float*)d_in[6];
    const float* bv = (const float*)d_in[7];
    const float* Wo = (const float*)d_in[8];
    const float* bo = (const float*)d_in[9];
    float* out = (float*)d_out;

    __nv_bfloat16 *Xhi, *Xlo, *Qhi, *Qlo, *Khi, *Klo, *Vhi, *Vlo, *AOhi, *AOlo;
    __nv_bfloat16 *WqThi, *WqTlo, *WkThi, *WkTlo, *WvThi, *WvTlo, *WoThi, *WoTlo;
    cudaGetSymbolAddress((void**)&Xhi, g_Xhi);
    cudaGetSymbolAddress((void**)&Xlo, g_Xlo);
    cudaGetSymbolAddress((void**)&Qhi, g_Qhi);
    cudaGetSymbolAddress((void**)&Qlo, g_Qlo);
    cudaGetSymbolAddress((void**)&Khi, g_Khi);
    cudaGetSymbolAddress((void**)&Klo, g_Klo);
    cudaGetSymbolAddress((void**)&Vhi, g_Vhi);
    cudaGetSymbolAddress((void**)&Vlo, g_Vlo);
    cudaGetSymbolAddress((void**)&AOhi, g_AOhi);
    cudaGetSymbolAddress((void**)&AOlo, g_AOlo);
    cudaGetSymbolAddress((void**)&WqThi, g_WqThi);
    cudaGetSymbolAddress((void**)&WqTlo, g_WqTlo);
    cudaGetSymbolAddress((void**)&WkThi, g_WkThi);
    cudaGetSymbolAddress((void**)&WkTlo, g_WkTlo);
    cudaGetSymbolAddress((void**)&WvThi, g_WvThi);
    cudaGetSymbolAddress((void**)&WvTlo, g_WvTlo);
    cudaGetSymbolAddress((void**)&WoThi, g_WoThi);
    cudaGetSymbolAddress((void**)&WoTlo, g_WoTlo);

    cudaFuncSetAttribute(mma_gemm_kernel<true>,
                         cudaFuncAttributeMaxDynamicSharedMemorySize, GEMM_SMEM);
    cudaFuncSetAttribute(mma_gemm_kernel<false>,
                         cudaFuncAttributeMaxDynamicSharedMemorySize, GEMM_SMEM);
    cudaFuncSetAttribute(mma_gemm_kv_kernel,
                         cudaFuncAttributeMaxDynamicSharedMemorySize, GEMM_SMEM);
    cudaFuncSetAttribute(flash_mma_kernel,
                         cudaFuncAttributeMaxDynamicSharedMemorySize, FLASH_SMEM);

    dim3 blk(256);

    // 1) prep
    split_kernel<<<(MROWS * HID / 4 + 255) / 256, 256>>>(x, Xhi, Xlo, MROWS * HID / 4);
    transpose_split_kernel<<<dim3(HID / 32, HID / 32), 256>>>(Wq, WqThi, WqTlo, HID, HID);
    transpose_split_kernel<<<dim3(KVDIM / 32, HID / 32), 256>>>(Wk, WkThi, WkTlo, HID, KVDIM);
    transpose_split_kernel<<<dim3(KVDIM / 32, HID / 32), 256>>>(Wv, WvThi, WvTlo, HID, KVDIM);
    transpose_split_kernel<<<dim3(HID / 32, HID / 32), 256>>>(Wo, WoThi, WoTlo, HID, HID);

    // 2) projections
    mma_gemm_kernel<true><<<dim3(HID / 128, MROWS / 128), blk, GEMM_SMEM>>>(
        Xhi, Xlo, WqThi, WqTlo, bq, nullptr, Qhi, Qlo, HID, HID);
    mma_gemm_kv_kernel<<<dim3(KVDIM / 128, MROWS / 128, 2), blk, GEMM_SMEM>>>(
        Xhi, Xlo, WkThi, WkTlo, bk, Khi, Klo,
        WvThi, WvTlo, bv, Vhi, Vlo, KVDIM, HID);

    // 3) attention
    flash_mma_kernel<<<dim3(SEQ / QT, NHEADS, BATCH), blk, FLASH_SMEM>>>(
        Qhi, Qlo, Khi, Klo, Vhi, Vlo, AOhi, AOlo);

    // 4) output projection
    mma_gemm_kernel<false><<<dim3(HID / 128, MROWS / 128), blk, GEMM_SMEM>>>(
        AOhi, AOlo, WoThi, WoTlo, bo, out, nullptr, nullptr, HID, HID);
}

// round 8
// speedup vs baseline: 1.0726x; 1.0726x over previous
#include <cuda_runtime.h>
#include <cuda_bf16.h>
#include <math.h>
#include <stdint.h>

// Problem constants
constexpr int BATCH = 2, SEQ = 2048, HID = 2048;
constexpr int NHEADS = 16, GRP = 4, HDIM = 128;
constexpr int MROWS = BATCH * SEQ;        // 4096
constexpr int KVDIM = GRP * HDIM;         // 512

// ---------------------------------------------------------------------------
// Device-global scratch
// ---------------------------------------------------------------------------
__device__ __nv_bfloat16 g_Xhi[MROWS * HID];
__device__ __nv_bfloat16 g_Xlo[MROWS * HID];
__device__ __nv_bfloat16 g_Qhi[MROWS * HID];
__device__ __nv_bfloat16 g_Qlo[MROWS * HID];
__device__ __nv_bfloat16 g_Khi[MROWS * KVDIM];
__device__ __nv_bfloat16 g_Klo[MROWS * KVDIM];
__device__ __nv_bfloat16 g_Vhi[MROWS * KVDIM];
__device__ __nv_bfloat16 g_Vlo[MROWS * KVDIM];
__device__ __nv_bfloat16 g_AOhi[MROWS * HID];
__device__ __nv_bfloat16 g_AOlo[MROWS * HID];
// Transposed weights, [N][K] K-major
__device__ __nv_bfloat16 g_WqThi[HID * HID];
__device__ __nv_bfloat16 g_WqTlo[HID * HID];
__device__ __nv_bfloat16 g_WkThi[KVDIM * HID];
__device__ __nv_bfloat16 g_WkTlo[KVDIM * HID];
__device__ __nv_bfloat16 g_WvThi[KVDIM * HID];
__device__ __nv_bfloat16 g_WvTlo[KVDIM * HID];
__device__ __nv_bfloat16 g_WoThi[HID * HID];
__device__ __nv_bfloat16 g_WoTlo[HID * HID];

// ---------------------------------------------------------------------------
// Helpers
// ---------------------------------------------------------------------------
__device__ __forceinline__ uint32_t smem_u32(const void* p) {
    uint32_t a;
    asm("{ .reg .u64 t; cvta.to.shared.u64 t, %1; cvt.u32.u64 %0, t; }"
        : "=r"(a) : "l"(p));
    return a;
}
__device__ __forceinline__ void cp16(uint32_t saddr, const void* gaddr) {
    asm volatile("cp.async.cg.shared.global [%0], [%1], 16;"
                 :: "r"(saddr), "l"(gaddr));
}
__device__ __forceinline__ void mma_bf16(float* c, const uint32_t* a, const uint32_t* b) {
    asm volatile("mma.sync.aligned.m16n8k16.row.col.f32.bf16.bf16.f32 "
                 "{%0,%1,%2,%3}, {%4,%5,%6,%7}, {%8,%9}, {%0,%1,%2,%3};"
                 : "+f"(c[0]), "+f"(c[1]), "+f"(c[2]), "+f"(c[3])
                 : "r"(a[0]), "r"(a[1]), "r"(a[2]), "r"(a[3]),
                   "r"(b[0]), "r"(b[1]));
}
#define LDMX4(r0, r1, r2, r3, addr) \
    asm volatile("ldmatrix.sync.aligned.m8n8.x4.shared.b16 {%0,%1,%2,%3}, [%4];" \
                 : "=r"(r0), "=r"(r1), "=r"(r2), "=r"(r3) : "r"(addr))
#define LDMX4T(r0, r1, r2, r3, addr) \
    asm volatile("ldmatrix.sync.aligned.m8n8.x4.trans.shared.b16 {%0,%1,%2,%3}, [%4];" \
                 : "=r"(r0), "=r"(r1), "=r"(r2), "=r"(r3) : "r"(addr))

__device__ __forceinline__ uint32_t packbf(float x, float y) {
    __nv_bfloat162 t = __floats2bfloat162_rn(x, y);
    return *(uint32_t*)&t;
}

// ---------------------------------------------------------------------------
// Split fp32 -> hi/lo bf16
// ---------------------------------------------------------------------------
__global__ __launch_bounds__(256)
void split_kernel(const float* __restrict__ x, __nv_bfloat16* __restrict__ hi,
                  __nv_bfloat16* __restrict__ lo, int n4)
{
    int i = blockIdx.x * blockDim.x + threadIdx.x;
    if (i >= n4) return;
    float4 v = ((const float4*)x)[i];
    __nv_bfloat16 h0 = __float2bfloat16(v.x), h1 = __float2bfloat16(v.y);
    __nv_bfloat16 h2 = __float2bfloat16(v.z), h3 = __float2bfloat16(v.w);
    ((__nv_bfloat162*)hi)[i * 2 + 0] = __nv_bfloat162(h0, h1);
    ((__nv_bfloat162*)hi)[i * 2 + 1] = __nv_bfloat162(h2, h3);
    ((__nv_bfloat162*)lo)[i * 2 + 0] =
        __nv_bfloat162(__float2bfloat16(v.x - __bfloat162float(h0)),
                       __float2bfloat16(v.y - __bfloat162float(h1)));
    ((__nv_bfloat162*)lo)[i * 2 + 1] =
        __nv_bfloat162(__float2bfloat16(v.z - __bfloat162float(h2)),
                       __float2bfloat16(v.w - __bfloat162float(h3)));
}

// ---------------------------------------------------------------------------
// Transpose W[K][N] -> T[N][K] with hi/lo bf16 split
// ---------------------------------------------------------------------------
__global__ __launch_bounds__(256)
void transpose_split_kernel(const float* __restrict__ W,
                            __nv_bfloat16* __restrict__ Thi,
                            __nv_bfloat16* __restrict__ Tlo, int K, int N)
{
    __shared__ float tile[32][33];
    int n0 = blockIdx.x * 32, k0 = blockIdx.y * 32;
    int tx = threadIdx.x & 31, ty = threadIdx.x >> 5;
    for (int j = ty; j < 32; j += 8)
        tile[j][tx] = W[(size_t)(k0 + j) * N + n0 + tx];
    __syncthreads();
    for (int j = ty; j < 32; j += 8) {
        float v = tile[tx][j];
        __nv_bfloat16 h = __float2bfloat16(v);
        size_t o = (size_t)(n0 + j) * K + k0 + tx;
        Thi[o] = h;
        Tlo[o] = __float2bfloat16(v - __bfloat162float(h));
    }
}

// ---------------------------------------------------------------------------
// HMMA GEMM body: C = (Ahi+Alo)[M,K] @ (Bhi+Blo)[N,K]^T + bias
// 128x128 CTA tile, 8 warps (2x4), term-wise ldmatrix (low reg pressure),
// cp.async 2-stage, 2 CTAs/SM.
// ---------------------------------------------------------------------------
constexpr int BK = 32;
constexpr int RSTRIDE = 40;                         // bf16 per smem row (80 B)
constexpr int TILE_BYTES2 = 128 * RSTRIDE * 2;      // 10240 B per tile
constexpr int GEMM_SMEM = 2 * 4 * TILE_BYTES2;      // 81920 B

template <bool SPLIT>
__device__ __forceinline__ void gemm_body(
    const __nv_bfloat16* __restrict__ Ahi, const __nv_bfloat16* __restrict__ Alo,
    const __nv_bfloat16* __restrict__ Bhi, const __nv_bfloat16* __restrict__ Blo,
    const float* __restrict__ bias, float* __restrict__ C,
    __nv_bfloat16* __restrict__ Chi, __nv_bfloat16* __restrict__ Clo,
    int N, int K, char* smptr)
{
    const uint32_t sbase = smem_u32(smptr);
    const int tid = threadIdx.x;
    const int wid = tid >> 5, lid = tid & 31;
    const int wm = wid >> 2, wn = wid & 3;
    const int m0 = blockIdx.y * 128, n0 = blockIdx.x * 128;

    const int tile = tid >> 6;
    const int tl = tid & 63;
    const __nv_bfloat16* tsrc =
        (tile == 0) ? Ahi + (size_t)m0 * K :
        (tile == 1) ? Alo + (size_t)m0 * K :
        (tile == 2) ? Bhi + (size_t)n0 * K :
                      Blo + (size_t)n0 * K;

    float acc[4][4][4];
#pragma unroll
    for (int mt = 0; mt < 4; mt++)
#pragma unroll
        for (int nt = 0; nt < 4; nt++)
#pragma unroll
            for (int j = 0; j < 4; j++) acc[mt][nt][j] = 0.f;

    const int nch = K / BK;

    auto issue = [&](int ch, int buf) {
        const __nv_bfloat16* src = tsrc + ch * BK;
        uint32_t base = sbase + (uint32_t)(buf * 4 + tile) * TILE_BYTES2;
#pragma unroll
        for (int it = 0; it < 8; it++) {
            int o = tl + it * 64;
            int row = o >> 2, seg = o & 3;
            cp16(base + row * 80 + seg * 16, src + (size_t)row * K + seg * 8);
        }
        asm volatile("cp.async.commit_group;" ::: "memory");
    };

    issue(0, 0);

    const int laneRow = (lid & 7) + ((lid >> 3) & 1) * 8;
    const int laneCol = (lid >> 4) * 16;

    for (int ch = 0; ch < nch; ch++) {
        const int buf = ch & 1;
        if (ch + 1 < nch) {
            issue(ch + 1, buf ^ 1);
            asm volatile("cp.async.wait_group 1;" ::: "memory");
        } else {
            asm volatile("cp.async.wait_group 0;" ::: "memory");
        }
        __syncthreads();

        const uint32_t Abase = sbase + (uint32_t)(buf * 4 + 0) * TILE_BYTES2
                             + (wm * 64 + laneRow) * 80 + laneCol;
        const uint32_t Bbase = sbase + (uint32_t)(buf * 4 + 2) * TILE_BYTES2
                             + (wn * 32 + laneRow) * 80 + laneCol;

#pragma unroll
        for (int ks = 0; ks < 2; ks++) {
            const uint32_t kb = ks * 32;
            // terms: t0=(AHi,BHi), t1=(AHi,BLo), t2=(ALo,BHi)
#pragma unroll
            for (int t = 0; t < 3; t++) {
                const uint32_t Ab = Abase + ((t == 2) ? TILE_BYTES2 : 0) + kb;
                const uint32_t Bb = Bbase + ((t == 1) ? TILE_BYTES2 : 0) + kb;
                uint32_t a[4][4], b[4][2];
#pragma unroll
                for (int mt = 0; mt < 4; mt++)
                    LDMX4(a[mt][0], a[mt][1], a[mt][2], a[mt][3],
                          Ab + mt * 16 * 80);
#pragma unroll
                for (int j = 0; j < 2; j++) {
                    uint32_t t0, t1, t2, t3;
                    LDMX4(t0, t1, t2, t3, Bb + j * 16 * 80);
                    b[2 * j][0] = t0; b[2 * j][1] = t2;
                    b[2 * j + 1][0] = t1; b[2 * j + 1][1] = t3;
                }
#pragma unroll
                for (int mt = 0; mt < 4; mt++)
#pragma unroll
                    for (int nt = 0; nt < 4; nt++)
                        mma_bf16(acc[mt][nt], a[mt], b[nt]);
            }
        }
        __syncthreads();
    }

    const int rbase = m0 + wm * 64 + (lid >> 2);
    const int cbase = n0 + wn * 32 + (lid & 3) * 2;
#pragma unroll
    for (int mt = 0; mt < 4; mt++) {
#pragma unroll
        for (int nt = 0; nt < 4; nt++) {
            int r = rbase + mt * 16;
            int c = cbase + nt * 8;
            float bx = __ldg(&bias[c]), by = __ldg(&bias[c + 1]);
            float v00 = acc[mt][nt][0] + bx, v01 = acc[mt][nt][1] + by;
            float v10 = acc[mt][nt][2] + bx, v11 = acc[mt][nt][3] + by;
            if (SPLIT) {
                __nv_bfloat16 h00 = __float2bfloat16(v00), h01 = __float2bfloat16(v01);
                __nv_bfloat16 h10 = __float2bfloat16(v10), h11 = __float2bfloat16(v11);
                *(__nv_bfloat162*)&Chi[(size_t)r * N + c] = __nv_bfloat162(h00, h01);
                *(__nv_bfloat162*)&Chi[(size_t)(r + 8) * N + c] = __nv_bfloat162(h10, h11);
                *(__nv_bfloat162*)&Clo[(size_t)r * N + c] =
                    __nv_bfloat162(__float2bfloat16(v00 - __bfloat162float(h00)),
                                   __float2bfloat16(v01 - __bfloat162float(h01)));
                *(__nv_bfloat162*)&Clo[(size_t)(r + 8) * N + c] =
                    __nv_bfloat162(__float2bfloat16(v10 - __bfloat162float(h10)),
                                   __float2bfloat16(v11 - __bfloat162float(h11)));
            } else {
                *(float2*)&C[(size_t)r * N + c] = make_float2(v00, v01);
                *(float2*)&C[(size_t)(r + 8) * N + c] = make_float2(v10, v11);
            }
        }
    }
}

template <bool SPLIT>
__global__ __launch_bounds__(256, 2)
void mma_gemm_kernel(const __nv_bfloat16* __restrict__ Ahi,
                     const __nv_bfloat16* __restrict__ Alo,
                     const __nv_bfloat16* __restrict__ Bhi,
                     const __nv_bfloat16* __restrict__ Blo,
                     const float* __restrict__ bias,
                     float* __restrict__ C,
                     __nv_bfloat16* __restrict__ Chi,
                     __nv_bfloat16* __restrict__ Clo,
                     int N, int K)
{
    extern __shared__ char smg[];
    gemm_body<SPLIT>(Ahi, Alo, Bhi, Blo, bias, C, Chi, Clo, N, K, smg);
}

// Fused K+V projection: blockIdx.z selects weight/output set.
__global__ __launch_bounds__(256, 2)
void mma_gemm_kv_kernel(const __nv_bfloat16* __restrict__ Ahi,
                        const __nv_bfloat16* __restrict__ Alo,
                        const __nv_bfloat16* __restrict__ BhiK,
                        const __nv_bfloat16* __restrict__ BloK,
                        const float* __restrict__ biasK,
                        __nv_bfloat16* __restrict__ KChi,
                        __nv_bfloat16* __restrict__ KClo,
                        const __nv_bfloat16* __restrict__ BhiV,
                        const __nv_bfloat16* __restrict__ BloV,
                        const float* __restrict__ biasV,
                        __nv_bfloat16* __restrict__ VChi,
                        __nv_bfloat16* __restrict__ VClo,
                        int N, int K)
{
    extern __shared__ char smg[];
    if (blockIdx.z == 0)
        gemm_body<true>(Ahi, Alo, BhiK, BloK, biasK, nullptr, KChi, KClo, N, K, smg);
    else
        gemm_body<true>(Ahi, Alo, BhiV, BloV, biasV, nullptr, VChi, VClo, N, K, smg);
}

// ---------------------------------------------------------------------------
// HMMA flash attention (causal GQA), double-buffered KV, ldmatrix fragments.
// CTA: 128 Q rows x one (head, batch). 8 warps x 16 Q rows.
// 3-term split for QK^T and PV (the 2-term PV variant failed at 1.25e-3).
// ---------------------------------------------------------------------------
constexpr int QT = 128, KT = 64;
constexpr int STRB = 272;                      // smem row stride bytes
constexpr int QTILE = QT * STRB;               // 34816
constexpr int KVT = KT * STRB;                 // 17408 per tile
constexpr int OFF_QHI = 0;
constexpr int OFF_QLO = QTILE;
constexpr int OFF_KV  = 2 * QTILE;             // 69632
constexpr int KVBUF   = 4 * KVT;               // 69632 (Khi,Klo,Vhi,Vlo)
constexpr int FLASH_SMEM = OFF_KV + 2 * KVBUF; // 208896
constexpr float SM_SCALE = 0.08838834764831845f;

__global__ __launch_bounds__(256, 1)
void flash_mma_kernel(const __nv_bfloat16* __restrict__ Qhi,
                      const __nv_bfloat16* __restrict__ Qlo,
                      const __nv_bfloat16* __restrict__ Khi,
                      const __nv_bfloat16* __restrict__ Klo,
                      const __nv_bfloat16* __restrict__ Vhi,
                      const __nv_bfloat16* __restrict__ Vlo,
                      __nv_bfloat16* __restrict__ Ohi,
                      __nv_bfloat16* __restrict__ Olo)
{
    extern __shared__ __nv_bfloat16 shb[];
    const uint32_t sb = smem_u32(shb);
    const int tid = threadIdx.x;
    const int w = tid >> 5, lid = tid & 31;
    const int rq = lid >> 2, cq = lid & 3;
    const int qt = blockIdx.x, h = blockIdx.y, b = blockIdx.z;
    const int g = h >> 2;
    const int q0 = qt * QT;

    // ---- load Q tile (hi+lo) ----
    {
        const __nv_bfloat16* srcs[2] = {Qhi, Qlo};
#pragma unroll
        for (int it = 0; it < 16; it++) {
            int idx = it * 256 + tid;
            int arr = idx >> 11, rem = idx & 2047;
            int row = rem >> 4, seg = rem & 15;
            const __nv_bfloat16* gp = srcs[arr]
                + (size_t)(b * SEQ + q0 + row) * HID + h * HDIM + seg * 8;
            cp16(sb + (arr ? OFF_QLO : OFF_QHI) + row * STRB + seg * 16, gp);
        }
        asm volatile("cp.async.commit_group;" ::: "memory");
    }

    const int nkt = 2 * qt + 2;

    auto load_kv = [&](int kt) {
        const uint32_t bb = sb + OFF_KV + (uint32_t)(kt & 1) * KVBUF;
        const int k0 = kt * KT;
        const __nv_bfloat16* srcs[4] = {Khi, Klo, Vhi, Vlo};
#pragma unroll
        for (int it = 0; it < 16; it++) {
            int idx = it * 256 + tid;
            int arr = idx >> 10, rem = idx & 1023;
            int row = rem >> 4, seg = rem & 15;
            const __nv_bfloat16* gp = srcs[arr]
                + (size_t)(b * SEQ + k0 + row) * KVDIM + g * HDIM + seg * 8;
            cp16(bb + arr * KVT + row * STRB + seg * 16, gp);
        }
        asm volatile("cp.async.commit_group;" ::: "memory");
    };

    load_kv(0);

    float oacc[16][4];
#pragma unroll
    for (int nt = 0; nt < 16; nt++)
#pragma unroll
        for (int j = 0; j < 4; j++) oacc[nt][j] = 0.f;
    float m0 = -INFINITY, m1 = -INFINITY, l0 = 0.f, l1 = 0.f;

    const int iwmin = q0 + w * 16;
    const int i0 = iwmin + rq;
    const int laneRow = (lid & 7) + ((lid >> 3) & 1) * 8;
    const int laneCol = (lid >> 4) * 16;

    for (int kt = 0; kt < nkt; kt++) {
        const int k0 = kt * KT;
        __syncthreads();
        if (kt + 1 < nkt) {
            load_kv(kt + 1);
            asm volatile("cp.async.wait_group 1;" ::: "memory");
        } else {
            asm volatile("cp.async.wait_group 0;" ::: "memory");
        }
        __syncthreads();

        if (k0 > iwmin + 15) continue;       // fully masked for this warp

        const uint32_t kvb = sb + OFF_KV + (uint32_t)(kt & 1) * KVBUF;
        const uint32_t KbH = kvb + laneRow * STRB + laneCol;
        const uint32_t KbL = KbH + KVT;
        const uint32_t QbH = sb + OFF_QHI + (w * 16 + laneRow) * STRB + laneCol;
        const uint32_t QbL = QbH + QTILE;

        // ---- S = Q K^T (3 split terms) ----
        float sacc[8][4];
#pragma unroll
        for (int nt = 0; nt < 8; nt++)
#pragma unroll
            for (int j = 0; j < 4; j++) sacc[nt][j] = 0.f;

#pragma unroll
        for (int ks = 0; ks < 8; ks++) {
            const uint32_t kb = ks * 32;
            uint32_t aHi[4], aLo[4], bHi[8][2], bLo[8][2];
            LDMX4(aHi[0], aHi[1], aHi[2], aHi[3], QbH + kb);
            LDMX4(aLo[0], aLo[1], aLo[2], aLo[3], QbL + kb);
#pragma unroll
            for (int j = 0; j < 4; j++) {
                uint32_t t0, t1, t2, t3;
                LDMX4(t0, t1, t2, t3, KbH + j * 16 * STRB + kb);
                bHi[2 * j][0] = t0; bHi[2 * j][1] = t2;
                bHi[2 * j + 1][0] = t1; bHi[2 * j + 1][1] = t3;
                LDMX4(t0, t1, t2, t3, KbL + j * 16 * STRB + kb);
                bLo[2 * j][0] = t0; bLo[2 * j][1] = t2;
                bLo[2 * j + 1][0] = t1; bLo[2 * j + 1][1] = t3;
            }
#pragma unroll
            for (int nt = 0; nt < 8; nt++) {
                mma_bf16(sacc[nt], aHi, bHi[nt]);
                mma_bf16(sacc[nt], aHi, bLo[nt]);
                mma_bf16(sacc[nt], aLo, bHi[nt]);
            }
        }

        // ---- scale + causal mask ----
        const bool need_mask = (k0 + KT - 1) > iwmin;
#pragma unroll
        for (int nt = 0; nt < 8; nt++) {
#pragma unroll
            for (int j = 0; j < 4; j++) {
                float s = sacc[nt][j] * SM_SCALE;
                if (need_mask) {
                    int jj = k0 + nt * 8 + cq * 2 + (j & 1);
                    int ii = i0 + ((j >> 1) << 3);
                    if (jj > ii) s = -1e30f;
                }
                sacc[nt][j] = s;
            }
        }

        // ---- online softmax ----
        float mx0 = -INFINITY, mx1 = -INFINITY;
#pragma unroll
        for (int nt = 0; nt < 8; nt++) {
            mx0 = fmaxf(mx0, fmaxf(sacc[nt][0], sacc[nt][1]));
            mx1 = fmaxf(mx1, fmaxf(sacc[nt][2], sacc[nt][3]));
        }
        mx0 = fmaxf(mx0, __shfl_xor_sync(0xffffffffu, mx0, 1));
        mx0 = fmaxf(mx0, __shfl_xor_sync(0xffffffffu, mx0, 2));
        mx1 = fmaxf(mx1, __shfl_xor_sync(0xffffffffu, mx1, 1));
        mx1 = fmaxf(mx1, __shfl_xor_sync(0xffffffffu, mx1, 2));
        float mn0 = fmaxf(m0, mx0), mn1 = fmaxf(m1, mx1);
        float al0 = __expf(m0 - mn0), al1 = __expf(m1 - mn1);
        m0 = mn0; m1 = mn1;

        float ls0 = 0.f, ls1 = 0.f;
#pragma unroll
        for (int nt = 0; nt < 8; nt++) {
            float p0 = __expf(sacc[nt][0] - mn0);
            float p1 = __expf(sacc[nt][1] - mn0);
            float p2 = __expf(sacc[nt][2] - mn1);
            float p3 = __expf(sacc[nt][3] - mn1);
            ls0 += p0 + p1; ls1 += p2 + p3;
            sacc[nt][0] = p0; sacc[nt][1] = p1; sacc[nt][2] = p2; sacc[nt][3] = p3;
        }
        ls0 += __shfl_xor_sync(0xffffffffu, ls0, 1);
        ls0 += __shfl_xor_sync(0xffffffffu, ls0, 2);
        ls1 += __shfl_xor_sync(0xffffffffu, ls1, 1);
        ls1 += __shfl_xor_sync(0xffffffffu, ls1, 2);
        l0 = l0 * al0 + ls0;
        l1 = l1 * al1 + ls1;

#pragma unroll
        for (int nt = 0; nt < 16; nt++) {
            oacc[nt][0] *= al0; oacc[nt][1] *= al0;
            oacc[nt][2] *= al1; oacc[nt][3] *= al1;
        }

        // ---- O += P V (3 split terms: Phi*Vhi + Phi*Vlo + Plo*Vhi) ----
        const uint32_t VbH = kvb + 2 * KVT;
#pragma unroll
        for (int ks = 0; ks < 4; ks++) {
            uint32_t aHi[4], aLo[4];
#pragma unroll
            for (int half = 0; half < 2; half++) {
                const float* p = sacc[2 * ks + half];
                float h0 = __bfloat162float(__float2bfloat16(p[0]));
                float h1 = __bfloat162float(__float2bfloat16(p[1]));
                float h2 = __bfloat162float(__float2bfloat16(p[2]));
                float h3 = __bfloat162float(__float2bfloat16(p[3]));
                aHi[2 * half + 0] = packbf(h0, h1);
                aHi[2 * half + 1] = packbf(h2, h3);
                aLo[2 * half + 0] = packbf(p[0] - h0, p[1] - h1);
                aLo[2 * half + 1] = packbf(p[2] - h2, p[3] - h3);
            }
#pragma unroll
            for (int ntp = 0; ntp < 8; ntp++) {
                const uint32_t va = VbH + (ks * 16 + (lid & 15)) * STRB
                                  + (ntp * 16 + ((lid >> 4) << 3)) * 2;
                uint32_t bh0, bh1, bh2, bh3, bl0, bl1, bl2, bl3;
                LDMX4T(bh0, bh1, bh2, bh3, va);
                LDMX4T(bl0, bl1, bl2, bl3, va + KVT);
                uint32_t bhA[2] = {bh0, bh1}, bhB[2] = {bh2, bh3};
                uint32_t blA[2] = {bl0, bl1}, blB[2] = {bl2, bl3};
                mma_bf16(oacc[2 * ntp + 0], aHi, bhA);
                mma_bf16(oacc[2 * ntp + 0], aHi, blA);
                mma_bf16(oacc[2 * ntp + 0], aLo, bhA);
                mma_bf16(oacc[2 * ntp + 1], aHi, bhB);
                mma_bf16(oacc[2 * ntp + 1], aHi, blB);
                mma_bf16(oacc[2 * ntp + 1], aLo, bhB);
            }
        }
    }

    // ---- normalize + store ----
    const float rl0 = 1.f / l0, rl1 = 1.f / l1;
    const size_t row0 = (size_t)(b * SEQ + q0 + w * 16 + rq);
#pragma unroll
    for (int nt = 0; nt < 16; nt++) {
        int col = h * HDIM + nt * 8 + cq * 2;
        float v00 = oacc[nt][0] * rl0, v01 = oacc[nt][1] * rl0;
        float v10 = oacc[nt][2] * rl1, v11 = oacc[nt][3] * rl1;
        __nv_bfloat16 h00 = __float2bfloat16(v00), h01 = __float2bfloat16(v01);
        __nv_bfloat16 h10 = __float2bfloat16(v10), h11 = __float2bfloat16(v11);
        *(__nv_bfloat162*)&Ohi[row0 * HID + col] = __nv_bfloat162(h00, h01);
        *(__nv_bfloat162*)&Ohi[(row0 + 8) * HID + col] = __nv_bfloat162(h10, h11);
        *(__nv_bfloat162*)&Olo[row0 * HID + col] =
            __nv_bfloat162(__float2bfloat16(v00 - __bfloat162float(h00)),
                           __float2bfloat16(v01 - __bfloat162float(h01)));
        *(__nv_bfloat162*)&Olo[(row0 + 8) * HID + col] =
            __nv_bfloat162(__float2bfloat16(v10 - __bfloat162float(h10)),
                           __float2bfloat16(v11 - __bfloat162float(h11)));
    }
}

// ---------------------------------------------------------------------------
// Launch
// ---------------------------------------------------------------------------
extern "C" void kernel_launch(void* const* d_in, const int* in_sizes, int n_in,
                              void* d_out, int out_size)
{
    const float* x  = (const float*)d_in[0];
    const float* Wq = (const float*)d_in[2];
    const float* bq = (const float*)d_in[3];
    const float* Wk = (const float*)d_in[4];
    const float* bk = (const float*)d_in[5];
    const float* Wv = (const float*)d_in[6];
    const float* bv = (const float*)d_in[7];
    const float* Wo = (const float*)d_in[8];
    const float* bo = (const float*)d_in[9];
    float* out = (float*)d_out;

    __nv_bfloat16 *Xhi, *Xlo, *Qhi, *Qlo, *Khi, *Klo, *Vhi, *Vlo, *AOhi, *AOlo;
    __nv_bfloat16 *WqThi, *WqTlo, *WkThi, *WkTlo, *WvThi, *WvTlo, *WoThi, *WoTlo;
    cudaGetSymbolAddress((void**)&Xhi, g_Xhi);
    cudaGetSymbolAddress((void**)&Xlo, g_Xlo);
    cudaGetSymbolAddress((void**)&Qhi, g_Qhi);
    cudaGetSymbolAddress((void**)&Qlo, g_Qlo);
    cudaGetSymbolAddress((void**)&Khi, g_Khi);
    cudaGetSymbolAddress((void**)&Klo, g_Klo);
    cudaGetSymbolAddress((void**)&Vhi, g_Vhi);
    cudaGetSymbolAddress((void**)&Vlo, g_Vlo);
    cudaGetSymbolAddress((void**)&AOhi, g_AOhi);
    cudaGetSymbolAddress((void**)&AOlo, g_AOlo);
    cudaGetSymbolAddress((void**)&WqThi, g_WqThi);
    cudaGetSymbolAddress((void**)&WqTlo, g_WqTlo);
    cudaGetSymbolAddress((void**)&WkThi, g_WkThi);
    cudaGetSymbolAddress((void**)&WkTlo, g_WkTlo);
    cudaGetSymbolAddress((void**)&WvThi, g_WvThi);
    cudaGetSymbolAddress((void**)&WvTlo, g_WvTlo);
    cudaGetSymbolAddress((void**)&WoThi, g_WoThi);
    cudaGetSymbolAddress((void**)&WoTlo, g_WoTlo);

    cudaFuncSetAttribute(mma_gemm_kernel<true>,
                         cudaFuncAttributeMaxDynamicSharedMemorySize, GEMM_SMEM);
    cudaFuncSetAttribute(mma_gemm_kernel<false>,
                         cudaFuncAttributeMaxDynamicSharedMemorySize, GEMM_SMEM);
    cudaFuncSetAttribute(mma_gemm_kv_kernel,
                         cudaFuncAttributeMaxDynamicSharedMemorySize, GEMM_SMEM);
    cudaFuncSetAttribute(flash_mma_kernel,
                         cudaFuncAttributeMaxDynamicSharedMemorySize, FLASH_SMEM);

    dim3 blk(256);

    // 1) prep
    split_kernel<<<(MROWS * HID / 4 + 255) / 256, 256>>>(x, Xhi, Xlo, MROWS * HID / 4);
    transpose_split_kernel<<<dim3(HID / 32, HID / 32), 256>>>(Wq, WqThi, WqTlo, HID, HID);
    transpose_split_kernel<<<dim3(KVDIM / 32, HID / 32), 256>>>(Wk, WkThi, WkTlo, HID, KVDIM);
    transpose_split_kernel<<<dim3(KVDIM / 32, HID / 32), 256>>>(Wv, WvThi, WvTlo, HID, KVDIM);
    transpose_split_kernel<<<dim3(HID / 32, HID / 32), 256>>>(Wo, WoThi, WoTlo, HID, HID);

    // 2) projections
    mma_gemm_kernel<true><<<dim3(HID / 128, MROWS / 128), blk, GEMM_SMEM>>>(
        Xhi, Xlo, WqThi, WqTlo, bq, nullptr, Qhi, Qlo, HID, HID);
    mma_gemm_kv_kernel<<<dim3(KVDIM / 128, MROWS / 128, 2), blk, GEMM_SMEM>>>(
        Xhi, Xlo, WkThi, WkTlo, bk, Khi, Klo,
        WvThi, WvTlo, bv, Vhi, Vlo, KVDIM, HID);

    // 3) attention
    flash_mma_kernel<<<dim3(SEQ / QT, NHEADS, BATCH), blk, FLASH_SMEM>>>(
        Qhi, Qlo, Khi, Klo, Vhi, Vlo, AOhi, AOlo);

    // 4) output projection
    mma_gemm_kernel<false><<<dim3(HID / 128, MROWS / 128), blk, GEMM_SMEM>>>(
        AOhi, AOlo, WoThi, WoTlo, bo, out, nullptr, nullptr, HID, HID);
}

// round 9
// speedup vs baseline: 1.1039x; 1.0292x over previous
#include <cuda_runtime.h>
#include <cuda_bf16.h>
#include <math.h>
#include <stdint.h>

// Problem constants
constexpr int BATCH = 2, SEQ = 2048, HID = 2048;
constexpr int NHEADS = 16, GRP = 4, HDIM = 128;
constexpr int MROWS = BATCH * SEQ;        // 4096
constexpr int KVDIM = GRP * HDIM;         // 512

// ---------------------------------------------------------------------------
// Device-global scratch
// ---------------------------------------------------------------------------
__device__ __nv_bfloat16 g_Xhi[MROWS * HID];
__device__ __nv_bfloat16 g_Xlo[MROWS * HID];
__device__ __nv_bfloat16 g_Qhi[MROWS * HID];
__device__ __nv_bfloat16 g_Qlo[MROWS * HID];
__device__ __nv_bfloat16 g_Khi[MROWS * KVDIM];
__device__ __nv_bfloat16 g_Klo[MROWS * KVDIM];
__device__ __nv_bfloat16 g_Vhi[MROWS * KVDIM];
__device__ __nv_bfloat16 g_Vlo[MROWS * KVDIM];
__device__ __nv_bfloat16 g_AOhi[MROWS * HID];
__device__ __nv_bfloat16 g_AOlo[MROWS * HID];
// Transposed weights, [N][K] K-major
__device__ __nv_bfloat16 g_WqThi[HID * HID];
__device__ __nv_bfloat16 g_WqTlo[HID * HID];
__device__ __nv_bfloat16 g_WkThi[KVDIM * HID];
__device__ __nv_bfloat16 g_WkTlo[KVDIM * HID];
__device__ __nv_bfloat16 g_WvThi[KVDIM * HID];
__device__ __nv_bfloat16 g_WvTlo[KVDIM * HID];
__device__ __nv_bfloat16 g_WoThi[HID * HID];
__device__ __nv_bfloat16 g_WoTlo[HID * HID];

// ---------------------------------------------------------------------------
// Helpers
// ---------------------------------------------------------------------------
__device__ __forceinline__ uint32_t smem_u32(const void* p) {
    uint32_t a;
    asm("{ .reg .u64 t; cvta.to.shared.u64 t, %1; cvt.u32.u64 %0, t; }"
        : "=r"(a) : "l"(p));
    return a;
}
__device__ __forceinline__ void cp16(uint32_t saddr, const void* gaddr) {
    asm volatile("cp.async.cg.shared.global [%0], [%1], 16;"
                 :: "r"(saddr), "l"(gaddr));
}
__device__ __forceinline__ void mma_bf16(float* c, const uint32_t* a, const uint32_t* b) {
    asm volatile("mma.sync.aligned.m16n8k16.row.col.f32.bf16.bf16.f32 "
                 "{%0,%1,%2,%3}, {%4,%5,%6,%7}, {%8,%9}, {%0,%1,%2,%3};"
                 : "+f"(c[0]), "+f"(c[1]), "+f"(c[2]), "+f"(c[3])
                 : "r"(a[0]), "r"(a[1]), "r"(a[2]), "r"(a[3]),
                   "r"(b[0]), "r"(b[1]));
}
#define LDMX4(r0, r1, r2, r3, addr) \
    asm volatile("ldmatrix.sync.aligned.m8n8.x4.shared.b16 {%0,%1,%2,%3}, [%4];" \
                 : "=r"(r0), "=r"(r1), "=r"(r2), "=r"(r3) : "r"(addr))
#define LDMX4T(r0, r1, r2, r3, addr) \
    asm volatile("ldmatrix.sync.aligned.m8n8.x4.trans.shared.b16 {%0,%1,%2,%3}, [%4];" \
                 : "=r"(r0), "=r"(r1), "=r"(r2), "=r"(r3) : "r"(addr))

__device__ __forceinline__ uint32_t packbf(float x, float y) {
    __nv_bfloat162 t = __floats2bfloat162_rn(x, y);
    return *(uint32_t*)&t;
}

// ---------------------------------------------------------------------------
// Split fp32 -> hi/lo bf16
// ---------------------------------------------------------------------------
__global__ __launch_bounds__(256)
void split_kernel(const float* __restrict__ x, __nv_bfloat16* __restrict__ hi,
                  __nv_bfloat16* __restrict__ lo, int n4)
{
    int i = blockIdx.x * blockDim.x + threadIdx.x;
    if (i >= n4) return;
    float4 v = ((const float4*)x)[i];
    __nv_bfloat16 h0 = __float2bfloat16(v.x), h1 = __float2bfloat16(v.y);
    __nv_bfloat16 h2 = __float2bfloat16(v.z), h3 = __float2bfloat16(v.w);
    ((__nv_bfloat162*)hi)[i * 2 + 0] = __nv_bfloat162(h0, h1);
    ((__nv_bfloat162*)hi)[i * 2 + 1] = __nv_bfloat162(h2, h3);
    ((__nv_bfloat162*)lo)[i * 2 + 0] =
        __nv_bfloat162(__float2bfloat16(v.x - __bfloat162float(h0)),
                       __float2bfloat16(v.y - __bfloat162float(h1)));
    ((__nv_bfloat162*)lo)[i * 2 + 1] =
        __nv_bfloat162(__float2bfloat16(v.z - __bfloat162float(h2)),
                       __float2bfloat16(v.w - __bfloat162float(h3)));
}

// ---------------------------------------------------------------------------
// Transpose W[K][N] -> T[N][K] with hi/lo bf16 split
// ---------------------------------------------------------------------------
__global__ __launch_bounds__(256)
void transpose_split_kernel(const float* __restrict__ W,
                            __nv_bfloat16* __restrict__ Thi,
                            __nv_bfloat16* __restrict__ Tlo, int K, int N)
{
    __shared__ float tile[32][33];
    int n0 = blockIdx.x * 32, k0 = blockIdx.y * 32;
    int tx = threadIdx.x & 31, ty = threadIdx.x >> 5;
    for (int j = ty; j < 32; j += 8)
        tile[j][tx] = W[(size_t)(k0 + j) * N + n0 + tx];
    __syncthreads();
    for (int j = ty; j < 32; j += 8) {
        float v = tile[tx][j];
        __nv_bfloat16 h = __float2bfloat16(v);
        size_t o = (size_t)(n0 + j) * K + k0 + tx;
        Thi[o] = h;
        Tlo[o] = __float2bfloat16(v - __bfloat162float(h));
    }
}

// ---------------------------------------------------------------------------
// HMMA GEMM body: C = (Ahi+Alo)[M,K] @ (Bhi+Blo)[N,K]^T + bias
// 128x128 CTA tile, 8 warps (2x4), term-wise ldmatrix, cp.async 2-stage,
// 2 CTAs/SM.
// ---------------------------------------------------------------------------
constexpr int BK = 32;
constexpr int RSTRIDE = 40;                         // bf16 per smem row (80 B)
constexpr int TILE_BYTES2 = 128 * RSTRIDE * 2;      // 10240 B per tile
constexpr int GEMM_SMEM = 2 * 4 * TILE_BYTES2;      // 81920 B

template <bool SPLIT>
__device__ __forceinline__ void gemm_body(
    const __nv_bfloat16* __restrict__ Ahi, const __nv_bfloat16* __restrict__ Alo,
    const __nv_bfloat16* __restrict__ Bhi, const __nv_bfloat16* __restrict__ Blo,
    const float* __restrict__ bias, float* __restrict__ C,
    __nv_bfloat16* __restrict__ Chi, __nv_bfloat16* __restrict__ Clo,
    int bn, int N, int K, char* smptr)
{
    const uint32_t sbase = smem_u32(smptr);
    const int tid = threadIdx.x;
    const int wid = tid >> 5, lid = tid & 31;
    const int wm = wid >> 2, wn = wid & 3;
    const int m0 = blockIdx.y * 128, n0 = bn * 128;

    const int tile = tid >> 6;
    const int tl = tid & 63;
    const __nv_bfloat16* tsrc =
        (tile == 0) ? Ahi + (size_t)m0 * K :
        (tile == 1) ? Alo + (size_t)m0 * K :
        (tile == 2) ? Bhi + (size_t)n0 * K :
                      Blo + (size_t)n0 * K;

    float acc[4][4][4];
#pragma unroll
    for (int mt = 0; mt < 4; mt++)
#pragma unroll
        for (int nt = 0; nt < 4; nt++)
#pragma unroll
            for (int j = 0; j < 4; j++) acc[mt][nt][j] = 0.f;

    const int nch = K / BK;

    auto issue = [&](int ch, int buf) {
        const __nv_bfloat16* src = tsrc + ch * BK;
        uint32_t base = sbase + (uint32_t)(buf * 4 + tile) * TILE_BYTES2;
#pragma unroll
        for (int it = 0; it < 8; it++) {
            int o = tl + it * 64;
            int row = o >> 2, seg = o & 3;
            cp16(base + row * 80 + seg * 16, src + (size_t)row * K + seg * 8);
        }
        asm volatile("cp.async.commit_group;" ::: "memory");
    };

    issue(0, 0);

    const int laneRow = (lid & 7) + ((lid >> 3) & 1) * 8;
    const int laneCol = (lid >> 4) * 16;

    for (int ch = 0; ch < nch; ch++) {
        const int buf = ch & 1;
        if (ch + 1 < nch) {
            issue(ch + 1, buf ^ 1);
            asm volatile("cp.async.wait_group 1;" ::: "memory");
        } else {
            asm volatile("cp.async.wait_group 0;" ::: "memory");
        }
        __syncthreads();

        const uint32_t Abase = sbase + (uint32_t)(buf * 4 + 0) * TILE_BYTES2
                             + (wm * 64 + laneRow) * 80 + laneCol;
        const uint32_t Bbase = sbase + (uint32_t)(buf * 4 + 2) * TILE_BYTES2
                             + (wn * 32 + laneRow) * 80 + laneCol;

#pragma unroll
        for (int ks = 0; ks < 2; ks++) {
            const uint32_t kb = ks * 32;
            // terms: t0=(AHi,BHi), t1=(AHi,BLo), t2=(ALo,BHi)
#pragma unroll
            for (int t = 0; t < 3; t++) {
                const uint32_t Ab = Abase + ((t == 2) ? TILE_BYTES2 : 0) + kb;
                const uint32_t Bb = Bbase + ((t == 1) ? TILE_BYTES2 : 0) + kb;
                uint32_t a[4][4], b[4][2];
#pragma unroll
                for (int mt = 0; mt < 4; mt++)
                    LDMX4(a[mt][0], a[mt][1], a[mt][2], a[mt][3],
                          Ab + mt * 16 * 80);
#pragma unroll
                for (int j = 0; j < 2; j++) {
                    uint32_t t0, t1, t2, t3;
                    LDMX4(t0, t1, t2, t3, Bb + j * 16 * 80);
                    b[2 * j][0] = t0; b[2 * j][1] = t2;
                    b[2 * j + 1][0] = t1; b[2 * j + 1][1] = t3;
                }
#pragma unroll
                for (int mt = 0; mt < 4; mt++)
#pragma unroll
                    for (int nt = 0; nt < 4; nt++)
                        mma_bf16(acc[mt][nt], a[mt], b[nt]);
            }
        }
        __syncthreads();
    }

    const int rbase = m0 + wm * 64 + (lid >> 2);
    const int cbase = n0 + wn * 32 + (lid & 3) * 2;
#pragma unroll
    for (int mt = 0; mt < 4; mt++) {
#pragma unroll
        for (int nt = 0; nt < 4; nt++) {
            int r = rbase + mt * 16;
            int c = cbase + nt * 8;
            float bx = __ldg(&bias[c]), by = __ldg(&bias[c + 1]);
            float v00 = acc[mt][nt][0] + bx, v01 = acc[mt][nt][1] + by;
            float v10 = acc[mt][nt][2] + bx, v11 = acc[mt][nt][3] + by;
            if (SPLIT) {
                __nv_bfloat16 h00 = __float2bfloat16(v00), h01 = __float2bfloat16(v01);
                __nv_bfloat16 h10 = __float2bfloat16(v10), h11 = __float2bfloat16(v11);
                *(__nv_bfloat162*)&Chi[(size_t)r * N + c] = __nv_bfloat162(h00, h01);
                *(__nv_bfloat162*)&Chi[(size_t)(r + 8) * N + c] = __nv_bfloat162(h10, h11);
                *(__nv_bfloat162*)&Clo[(size_t)r * N + c] =
                    __nv_bfloat162(__float2bfloat16(v00 - __bfloat162float(h00)),
                                   __float2bfloat16(v01 - __bfloat162float(h01)));
                *(__nv_bfloat162*)&Clo[(size_t)(r + 8) * N + c] =
                    __nv_bfloat162(__float2bfloat16(v10 - __bfloat162float(h10)),
                                   __float2bfloat16(v11 - __bfloat162float(h11)));
            } else {
                *(float2*)&C[(size_t)r * N + c] = make_float2(v00, v01);
                *(float2*)&C[(size_t)(r + 8) * N + c] = make_float2(v10, v11);
            }
        }
    }
}

// Fused Q+K+V projection. bx 0..15 -> Q n-block, 16..19 -> K, 20..23 -> V.
__global__ __launch_bounds__(256, 2)
void mma_gemm_qkv_kernel(const __nv_bfloat16* __restrict__ Ahi,
                         const __nv_bfloat16* __restrict__ Alo,
                         const __nv_bfloat16* __restrict__ BhiQ,
                         const __nv_bfloat16* __restrict__ BloQ,
                         const float* __restrict__ biasQ,
                         __nv_bfloat16* __restrict__ QChi,
                         __nv_bfloat16* __restrict__ QClo,
                         const __nv_bfloat16* __restrict__ BhiK,
                         const __nv_bfloat16* __restrict__ BloK,
                         const float* __restrict__ biasK,
                         __nv_bfloat16* __restrict__ KChi,
                         __nv_bfloat16* __restrict__ KClo,
                         const __nv_bfloat16* __restrict__ BhiV,
                         const __nv_bfloat16* __restrict__ BloV,
                         const float* __restrict__ biasV,
                         __nv_bfloat16* __restrict__ VChi,
                         __nv_bfloat16* __restrict__ VClo)
{
    extern __shared__ char smg[];
    const int bx = blockIdx.x;
    if (bx < 16)
        gemm_body<true>(Ahi, Alo, BhiQ, BloQ, biasQ, nullptr, QChi, QClo,
                        bx, HID, HID, smg);
    else if (bx < 20)
        gemm_body<true>(Ahi, Alo, BhiK, BloK, biasK, nullptr, KChi, KClo,
                        bx - 16, KVDIM, HID, smg);
    else
        gemm_body<true>(Ahi, Alo, BhiV, BloV, biasV, nullptr, VChi, VClo,
                        bx - 20, KVDIM, HID, smg);
}

// Output projection (fp32 C)
__global__ __launch_bounds__(256, 2)
void mma_gemm_o_kernel(const __nv_bfloat16* __restrict__ Ahi,
                       const __nv_bfloat16* __restrict__ Alo,
                       const __nv_bfloat16* __restrict__ Bhi,
                       const __nv_bfloat16* __restrict__ Blo,
                       const float* __restrict__ bias,
                       float* __restrict__ C)
{
    extern __shared__ char smg[];
    gemm_body<false>(Ahi, Alo, Bhi, Blo, bias, C, nullptr, nullptr,
                     blockIdx.x, HID, HID, smg);
}

// ---------------------------------------------------------------------------
// HMMA flash attention (causal GQA).
// CTA: 64 Q rows, 4 warps (16 rows each), 128 threads, single KV buffer,
// 2 CTAs/SM (smem 104448 x2 = 208896). 3-term split for QK^T and PV.
// ---------------------------------------------------------------------------
constexpr int QT = 64, KT = 64;
constexpr int STRB = 272;                      // smem row stride bytes
constexpr int QTILE = QT * STRB;               // 17408
constexpr int KVT = KT * STRB;                 // 17408 per array
constexpr int OFF_QHI = 0;
constexpr int OFF_QLO = QTILE;                 // 17408
constexpr int OFF_KV  = 2 * QTILE;             // 34816
constexpr int FLASH_SMEM = OFF_KV + 4 * KVT;   // 104448
constexpr float SM_SCALE = 0.08838834764831845f;

__global__ __launch_bounds__(128, 2)
void flash_mma_kernel(const __nv_bfloat16* __restrict__ Qhi,
                      const __nv_bfloat16* __restrict__ Qlo,
                      const __nv_bfloat16* __restrict__ Khi,
                      const __nv_bfloat16* __restrict__ Klo,
                      const __nv_bfloat16* __restrict__ Vhi,
                      const __nv_bfloat16* __restrict__ Vlo,
                      __nv_bfloat16* __restrict__ Ohi,
                      __nv_bfloat16* __restrict__ Olo)
{
    extern __shared__ __nv_bfloat16 shb[];
    const uint32_t sb = smem_u32(shb);
    const int tid = threadIdx.x;
    const int w = tid >> 5, lid = tid & 31;
    const int rq = lid >> 2, cq = lid & 3;
    const int qt = blockIdx.x, h = blockIdx.y, b = blockIdx.z;
    const int g = h >> 2;
    const int q0 = qt * QT;

    // ---- load Q tile (hi+lo): 2 arrays x 64 rows x 16 segs = 2048 ops ----
    {
        const __nv_bfloat16* srcs[2] = {Qhi, Qlo};
#pragma unroll
        for (int it = 0; it < 16; it++) {
            int idx = it * 128 + tid;
            int arr = idx >> 10, rem = idx & 1023;
            int row = rem >> 4, seg = rem & 15;
            const __nv_bfloat16* gp = srcs[arr]
                + (size_t)(b * SEQ + q0 + row) * HID + h * HDIM + seg * 8;
            cp16(sb + (arr ? OFF_QLO : OFF_QHI) + row * STRB + seg * 16, gp);
        }
        asm volatile("cp.async.commit_group;" ::: "memory");
    }

    const int nkt = qt + 1;

    float oacc[16][4];
#pragma unroll
    for (int nt = 0; nt < 16; nt++)
#pragma unroll
        for (int j = 0; j < 4; j++) oacc[nt][j] = 0.f;
    float m0 = -INFINITY, m1 = -INFINITY, l0 = 0.f, l1 = 0.f;

    const int iwmin = q0 + w * 16;
    const int i0 = iwmin + rq;
    const int laneRow = (lid & 7) + ((lid >> 3) & 1) * 8;
    const int laneCol = (lid >> 4) * 16;

    for (int kt = 0; kt < nkt; kt++) {
        const int k0 = kt * KT;
        __syncthreads();                       // previous tile reads done
        // ---- load K/V tiles: 4 arrays x 64 rows x 16 segs = 4096 ops ----
        {
            const __nv_bfloat16* srcs[4] = {Khi, Klo, Vhi, Vlo};
#pragma unroll
            for (int it = 0; it < 32; it++) {
                int idx = it * 128 + tid;
                int arr = idx >> 10, rem = idx & 1023;
                int row = rem >> 4, seg = rem & 15;
                const __nv_bfloat16* gp = srcs[arr]
                    + (size_t)(b * SEQ + k0 + row) * KVDIM + g * HDIM + seg * 8;
                cp16(sb + OFF_KV + arr * KVT + row * STRB + seg * 16, gp);
            }
            asm volatile("cp.async.commit_group;" ::: "memory");
            asm volatile("cp.async.wait_group 0;" ::: "memory");
        }
        __syncthreads();

        const uint32_t KbH = sb + OFF_KV + laneRow * STRB + laneCol;
        const uint32_t KbL = KbH + KVT;
        const uint32_t QbH = sb + OFF_QHI + (w * 16 + laneRow) * STRB + laneCol;
        const uint32_t QbL = QbH + QTILE;

        // ---- S = Q K^T (3 split terms), 16x64 per warp ----
        float sacc[8][4];
#pragma unroll
        for (int nt = 0; nt < 8; nt++)
#pragma unroll
            for (int j = 0; j < 4; j++) sacc[nt][j] = 0.f;

#pragma unroll
        for (int ks = 0; ks < 8; ks++) {
            const uint32_t kb = ks * 32;
            uint32_t aHi[4], aLo[4], bHi[8][2], bLo[8][2];
            LDMX4(aHi[0], aHi[1], aHi[2], aHi[3], QbH + kb);
            LDMX4(aLo[0], aLo[1], aLo[2], aLo[3], QbL + kb);
#pragma unroll
            for (int j = 0; j < 4; j++) {
                uint32_t t0, t1, t2, t3;
                LDMX4(t0, t1, t2, t3, KbH + j * 16 * STRB + kb);
                bHi[2 * j][0] = t0; bHi[2 * j][1] = t2;
                bHi[2 * j + 1][0] = t1; bHi[2 * j + 1][1] = t3;
                LDMX4(t0, t1, t2, t3, KbL + j * 16 * STRB + kb);
                bLo[2 * j][0] = t0; bLo[2 * j][1] = t2;
                bLo[2 * j + 1][0] = t1; bLo[2 * j + 1][1] = t3;
            }
#pragma unroll
            for (int nt = 0; nt < 8; nt++) {
                mma_bf16(sacc[nt], aHi, bHi[nt]);
                mma_bf16(sacc[nt], aHi, bLo[nt]);
                mma_bf16(sacc[nt], aLo, bHi[nt]);
            }
        }

        // ---- scale + causal mask (only the last tile needs masking) ----
        const bool need_mask = (k0 + KT - 1) > iwmin;
#pragma unroll
        for (int nt = 0; nt < 8; nt++) {
#pragma unroll
            for (int j = 0; j < 4; j++) {
                float s = sacc[nt][j] * SM_SCALE;
                if (need_mask) {
                    int jj = k0 + nt * 8 + cq * 2 + (j & 1);
                    int ii = i0 + ((j >> 1) << 3);
                    if (jj > ii) s = -1e30f;
                }
                sacc[nt][j] = s;
            }
        }

        // ---- online softmax ----
        float mx0 = -INFINITY, mx1 = -INFINITY;
#pragma unroll
        for (int nt = 0; nt < 8; nt++) {
            mx0 = fmaxf(mx0, fmaxf(sacc[nt][0], sacc[nt][1]));
            mx1 = fmaxf(mx1, fmaxf(sacc[nt][2], sacc[nt][3]));
        }
        mx0 = fmaxf(mx0, __shfl_xor_sync(0xffffffffu, mx0, 1));
        mx0 = fmaxf(mx0, __shfl_xor_sync(0xffffffffu, mx0, 2));
        mx1 = fmaxf(mx1, __shfl_xor_sync(0xffffffffu, mx1, 1));
        mx1 = fmaxf(mx1, __shfl_xor_sync(0xffffffffu, mx1, 2));
        float mn0 = fmaxf(m0, mx0), mn1 = fmaxf(m1, mx1);
        float al0 = __expf(m0 - mn0), al1 = __expf(m1 - mn1);
        m0 = mn0; m1 = mn1;

        float ls0 = 0.f, ls1 = 0.f;
#pragma unroll
        for (int nt = 0; nt < 8; nt++) {
            float p0 = __expf(sacc[nt][0] - mn0);
            float p1 = __expf(sacc[nt][1] - mn0);
            float p2 = __expf(sacc[nt][2] - mn1);
            float p3 = __expf(sacc[nt][3] - mn1);
            ls0 += p0 + p1; ls1 += p2 + p3;
            sacc[nt][0] = p0; sacc[nt][1] = p1; sacc[nt][2] = p2; sacc[nt][3] = p3;
        }
        ls0 += __shfl_xor_sync(0xffffffffu, ls0, 1);
        ls0 += __shfl_xor_sync(0xffffffffu, ls0, 2);
        ls1 += __shfl_xor_sync(0xffffffffu, ls1, 1);
        ls1 += __shfl_xor_sync(0xffffffffu, ls1, 2);
        l0 = l0 * al0 + ls0;
        l1 = l1 * al1 + ls1;

#pragma unroll
        for (int nt = 0; nt < 16; nt++) {
            oacc[nt][0] *= al0; oacc[nt][1] *= al0;
            oacc[nt][2] *= al1; oacc[nt][3] *= al1;
        }

        // ---- O += P V (3 split terms: Phi*Vhi + Phi*Vlo + Plo*Vhi) ----
        const uint32_t VbH = sb + OFF_KV + 2 * KVT;
#pragma unroll
        for (int ks = 0; ks < 4; ks++) {
            uint32_t aHi[4], aLo[4];
#pragma unroll
            for (int half = 0; half < 2; half++) {
                const float* p = sacc[2 * ks + half];
                float h0 = __bfloat162float(__float2bfloat16(p[0]));
                float h1 = __bfloat162float(__float2bfloat16(p[1]));
                float h2 = __bfloat162float(__float2bfloat16(p[2]));
                float h3 = __bfloat162float(__float2bfloat16(p[3]));
                aHi[2 * half + 0] = packbf(h0, h1);
                aHi[2 * half + 1] = packbf(h2, h3);
                aLo[2 * half + 0] = packbf(p[0] - h0, p[1] - h1);
                aLo[2 * half + 1] = packbf(p[2] - h2, p[3] - h3);
            }
#pragma unroll
            for (int ntp = 0; ntp < 8; ntp++) {
                const uint32_t va = VbH + (ks * 16 + (lid & 15)) * STRB
                                  + (ntp * 16 + ((lid >> 4) << 3)) * 2;
                uint32_t bh0, bh1, bh2, bh3, bl0, bl1, bl2, bl3;
                LDMX4T(bh0, bh1, bh2, bh3, va);
                LDMX4T(bl0, bl1, bl2, bl3, va + KVT);
                uint32_t bhA[2] = {bh0, bh1}, bhB[2] = {bh2, bh3};
                uint32_t blA[2] = {bl0, bl1}, blB[2] = {bl2, bl3};
                mma_bf16(oacc[2 * ntp + 0], aHi, bhA);
                mma_bf16(oacc[2 * ntp + 0], aHi, blA);
                mma_bf16(oacc[2 * ntp + 0], aLo, bhA);
                mma_bf16(oacc[2 * ntp + 1], aHi, bhB);
                mma_bf16(oacc[2 * ntp + 1], aHi, blB);
                mma_bf16(oacc[2 * ntp + 1], aLo, bhB);
            }
        }
    }

    // ---- normalize + store ----
    const float rl0 = 1.f / l0, rl1 = 1.f / l1;
    const size_t row0 = (size_t)(b * SEQ + q0 + w * 16 + rq);
#pragma unroll
    for (int nt = 0; nt < 16; nt++) {
        int col = h * HDIM + nt * 8 + cq * 2;
        float v00 = oacc[nt][0] * rl0, v01 = oacc[nt][1] * rl0;
        float v10 = oacc[nt][2] * rl1, v11 = oacc[nt][3] * rl1;
        __nv_bfloat16 h00 = __float2bfloat16(v00), h01 = __float2bfloat16(v01);
        __nv_bfloat16 h10 = __float2bfloat16(v10), h11 = __float2bfloat16(v11);
        *(__nv_bfloat162*)&Ohi[row0 * HID + col] = __nv_bfloat162(h00, h01);
        *(__nv_bfloat162*)&Ohi[(row0 + 8) * HID + col] = __nv_bfloat162(h10, h11);
        *(__nv_bfloat162*)&Olo[row0 * HID + col] =
            __nv_bfloat162(__float2bfloat16(v00 - __bfloat162float(h00)),
                           __float2bfloat16(v01 - __bfloat162float(h01)));
        *(__nv_bfloat162*)&Olo[(row0 + 8) * HID + col] =
            __nv_bfloat162(__float2bfloat16(v10 - __bfloat162float(h10)),
                           __float2bfloat16(v11 - __bfloat162float(h11)));
    }
}

// ---------------------------------------------------------------------------
// Launch
// ---------------------------------------------------------------------------
extern "C" void kernel_launch(void* const* d_in, const int* in_sizes, int n_in,
                              void* d_out, int out_size)
{
    const float* x  = (const float*)d_in[0];
    const float* Wq = (const float*)d_in[2];
    const float* bq = (const float*)d_in[3];
    const float* Wk = (const float*)d_in[4];
    const float* bk = (const float*)d_in[5];
    const float* Wv = (const float*)d_in[6];
    const float* bv = (const float*)d_in[7];
    const float* Wo = (const float*)d_in[8];
    const float* bo = (const float*)d_in[9];
    float* out = (float*)d_out;

    __nv_bfloat16 *Xhi, *Xlo, *Qhi, *Qlo, *Khi, *Klo, *Vhi, *Vlo, *AOhi, *AOlo;
    __nv_bfloat16 *WqThi, *WqTlo, *WkThi, *WkTlo, *WvThi, *WvTlo, *WoThi, *WoTlo;
    cudaGetSymbolAddress((void**)&Xhi, g_Xhi);
    cudaGetSymbolAddress((void**)&Xlo, g_Xlo);
    cudaGetSymbolAddress((void**)&Qhi, g_Qhi);
    cudaGetSymbolAddress((void**)&Qlo, g_Qlo);
    cudaGetSymbolAddress((void**)&Khi, g_Khi);
    cudaGetSymbolAddress((void**)&Klo, g_Klo);
    cudaGetSymbolAddress((void**)&Vhi, g_Vhi);
    cudaGetSymbolAddress((void**)&Vlo, g_Vlo);
    cudaGetSymbolAddress((void**)&AOhi, g_AOhi);
    cudaGetSymbolAddress((void**)&AOlo, g_AOlo);
    cudaGetSymbolAddress((void**)&WqThi, g_WqThi);
    cudaGetSymbolAddress((void**)&WqTlo, g_WqTlo);
    cudaGetSymbolAddress((void**)&WkThi, g_WkThi);
    cudaGetSymbolAddress((void**)&WkTlo, g_WkTlo);
    cudaGetSymbolAddress((void**)&WvThi, g_WvThi);
    cudaGetSymbolAddress((void**)&WvTlo, g_WvTlo);
    cudaGetSymbolAddress((void**)&WoThi, g_WoThi);
    cudaGetSymbolAddress((void**)&WoTlo, g_WoTlo);

    cudaFuncSetAttribute(mma_gemm_qkv_kernel,
                         cudaFuncAttributeMaxDynamicSharedMemorySize, GEMM_SMEM);
    cudaFuncSetAttribute(mma_gemm_o_kernel,
                         cudaFuncAttributeMaxDynamicSharedMemorySize, GEMM_SMEM);
    cudaFuncSetAttribute(flash_mma_kernel,
                         cudaFuncAttributeMaxDynamicSharedMemorySize, FLASH_SMEM);

    // 1) prep
    split_kernel<<<(MROWS * HID / 4 + 255) / 256, 256>>>(x, Xhi, Xlo, MROWS * HID / 4);
    transpose_split_kernel<<<dim3(HID / 32, HID / 32), 256>>>(Wq, WqThi, WqTlo, HID, HID);
    transpose_split_kernel<<<dim3(KVDIM / 32, HID / 32), 256>>>(Wk, WkThi, WkTlo, HID, KVDIM);
    transpose_split_kernel<<<dim3(KVDIM / 32, HID / 32), 256>>>(Wv, WvThi, WvTlo, HID, KVDIM);
    transpose_split_kernel<<<dim3(HID / 32, HID / 32), 256>>>(Wo, WoThi, WoTlo, HID, HID);

    // 2) fused Q+K+V projection (24 n-blocks x 32 m-blocks)
    mma_gemm_qkv_kernel<<<dim3(24, MROWS / 128), 256, GEMM_SMEM>>>(
        Xhi, Xlo,
        WqThi, WqTlo, bq, Qhi, Qlo,
        WkThi, WkTlo, bk, Khi, Klo,
        WvThi, WvTlo, bv, Vhi, Vlo);

    // 3) attention (64-row CTAs, 2 CTAs/SM)
    flash_mma_kernel<<<dim3(SEQ / QT, NHEADS, BATCH), 128, FLASH_SMEM>>>(
        Qhi, Qlo, Khi, Klo, Vhi, Vlo, AOhi, AOlo);

    // 4) output projection
    mma_gemm_o_kernel<<<dim3(HID / 128, MROWS / 128), 256, GEMM_SMEM>>>(
        AOhi, AOlo, WoThi, WoTlo, bo, out);
}

// round 10
// speedup vs baseline: 1.1042x; 1.0002x over previous
#include <cuda_runtime.h>
#include <cuda_bf16.h>
#include <math.h>
#include <stdint.h>

// Problem constants
constexpr int BATCH = 2, SEQ = 2048, HID = 2048;
constexpr int NHEADS = 16, GRP = 4, HDIM = 128;
constexpr int MROWS = BATCH * SEQ;        // 4096
constexpr int KVDIM = GRP * HDIM;         // 512

// ---------------------------------------------------------------------------
// Device-global scratch
// ---------------------------------------------------------------------------
__device__ __nv_bfloat16 g_Xhi[MROWS * HID];
__device__ __nv_bfloat16 g_Xlo[MROWS * HID];
__device__ __nv_bfloat16 g_Qhi[MROWS * HID];
__device__ __nv_bfloat16 g_Qlo[MROWS * HID];
__device__ __nv_bfloat16 g_Khi[MROWS * KVDIM];
__device__ __nv_bfloat16 g_Klo[MROWS * KVDIM];
__device__ __nv_bfloat16 g_Vhi[MROWS * KVDIM];
__device__ __nv_bfloat16 g_Vlo[MROWS * KVDIM];
__device__ __nv_bfloat16 g_AOhi[MROWS * HID];
__device__ __nv_bfloat16 g_AOlo[MROWS * HID];
// Transposed weights, [N][K] K-major
__device__ __nv_bfloat16 g_WqThi[HID * HID];
__device__ __nv_bfloat16 g_WqTlo[HID * HID];
__device__ __nv_bfloat16 g_WkThi[KVDIM * HID];
__device__ __nv_bfloat16 g_WkTlo[KVDIM * HID];
__device__ __nv_bfloat16 g_WvThi[KVDIM * HID];
__device__ __nv_bfloat16 g_WvTlo[KVDIM * HID];
__device__ __nv_bfloat16 g_WoThi[HID * HID];
__device__ __nv_bfloat16 g_WoTlo[HID * HID];

// ---------------------------------------------------------------------------
// Helpers
// ---------------------------------------------------------------------------
__device__ __forceinline__ uint32_t smem_u32(const void* p) {
    uint32_t a;
    asm("{ .reg .u64 t; cvta.to.shared.u64 t, %1; cvt.u32.u64 %0, t; }"
        : "=r"(a) : "l"(p));
    return a;
}
__device__ __forceinline__ void cp16(uint32_t saddr, const void* gaddr) {
    asm volatile("cp.async.cg.shared.global [%0], [%1], 16;"
                 :: "r"(saddr), "l"(gaddr));
}
__device__ __forceinline__ void mma_bf16(float* c, const uint32_t* a, const uint32_t* b) {
    asm volatile("mma.sync.aligned.m16n8k16.row.col.f32.bf16.bf16.f32 "
                 "{%0,%1,%2,%3}, {%4,%5,%6,%7}, {%8,%9}, {%0,%1,%2,%3};"
                 : "+f"(c[0]), "+f"(c[1]), "+f"(c[2]), "+f"(c[3])
                 : "r"(a[0]), "r"(a[1]), "r"(a[2]), "r"(a[3]),
                   "r"(b[0]), "r"(b[1]));
}
#define LDMX4(r0, r1, r2, r3, addr) \
    asm volatile("ldmatrix.sync.aligned.m8n8.x4.shared.b16 {%0,%1,%2,%3}, [%4];" \
                 : "=r"(r0), "=r"(r1), "=r"(r2), "=r"(r3) : "r"(addr))
#define LDMX4T(r0, r1, r2, r3, addr) \
    asm volatile("ldmatrix.sync.aligned.m8n8.x4.trans.shared.b16 {%0,%1,%2,%3}, [%4];" \
                 : "=r"(r0), "=r"(r1), "=r"(r2), "=r"(r3) : "r"(addr))

__device__ __forceinline__ uint32_t packbf(float x, float y) {
    __nv_bfloat162 t = __floats2bfloat162_rn(x, y);
    return *(uint32_t*)&t;
}

// ---------------------------------------------------------------------------
// Split fp32 -> hi/lo bf16
// ---------------------------------------------------------------------------
__global__ __launch_bounds__(256)
void split_kernel(const float* __restrict__ x, __nv_bfloat16* __restrict__ hi,
                  __nv_bfloat16* __restrict__ lo, int n4)
{
    int i = blockIdx.x * blockDim.x + threadIdx.x;
    if (i >= n4) return;
    float4 v = ((const float4*)x)[i];
    __nv_bfloat16 h0 = __float2bfloat16(v.x), h1 = __float2bfloat16(v.y);
    __nv_bfloat16 h2 = __float2bfloat16(v.z), h3 = __float2bfloat16(v.w);
    ((__nv_bfloat162*)hi)[i * 2 + 0] = __nv_bfloat162(h0, h1);
    ((__nv_bfloat162*)hi)[i * 2 + 1] = __nv_bfloat162(h2, h3);
    ((__nv_bfloat162*)lo)[i * 2 + 0] =
        __nv_bfloat162(__float2bfloat16(v.x - __bfloat162float(h0)),
                       __float2bfloat16(v.y - __bfloat162float(h1)));
    ((__nv_bfloat162*)lo)[i * 2 + 1] =
        __nv_bfloat162(__float2bfloat16(v.z - __bfloat162float(h2)),
                       __float2bfloat16(v.w - __bfloat162float(h3)));
}

// ---------------------------------------------------------------------------
// Transpose W[K][N] -> T[N][K] with hi/lo bf16 split
// ---------------------------------------------------------------------------
__global__ __launch_bounds__(256)
void transpose_split_kernel(const float* __restrict__ W,
                            __nv_bfloat16* __restrict__ Thi,
                            __nv_bfloat16* __restrict__ Tlo, int K, int N)
{
    __shared__ float tile[32][33];
    int n0 = blockIdx.x * 32, k0 = blockIdx.y * 32;
    int tx = threadIdx.x & 31, ty = threadIdx.x >> 5;
    for (int j = ty; j < 32; j += 8)
        tile[j][tx] = W[(size_t)(k0 + j) * N + n0 + tx];
    __syncthreads();
    for (int j = ty; j < 32; j += 8) {
        float v = tile[tx][j];
        __nv_bfloat16 h = __float2bfloat16(v);
        size_t o = (size_t)(n0 + j) * K + k0 + tx;
        Thi[o] = h;
        Tlo[o] = __float2bfloat16(v - __bfloat162float(h));
    }
}

// ---------------------------------------------------------------------------
// HMMA GEMM body: C = (Ahi+Alo)[M,K] @ (Bhi+Blo)[N,K]^T + bias
// 128x128 CTA tile, 8 warps (2x4), term-wise ldmatrix, cp.async 2-stage,
// 2 CTAs/SM.
// ---------------------------------------------------------------------------
constexpr int BK = 32;
constexpr int RSTRIDE = 40;                         // bf16 per smem row (80 B)
constexpr int TILE_BYTES2 = 128 * RSTRIDE * 2;      // 10240 B per tile
constexpr int GEMM_SMEM = 2 * 4 * TILE_BYTES2;      // 81920 B

template <bool SPLIT>
__device__ __forceinline__ void gemm_body(
    const __nv_bfloat16* __restrict__ Ahi, const __nv_bfloat16* __restrict__ Alo,
    const __nv_bfloat16* __restrict__ Bhi, const __nv_bfloat16* __restrict__ Blo,
    const float* __restrict__ bias, float* __restrict__ C,
    __nv_bfloat16* __restrict__ Chi, __nv_bfloat16* __restrict__ Clo,
    int bn, int N, int K, char* smptr)
{
    const uint32_t sbase = smem_u32(smptr);
    const int tid = threadIdx.x;
    const int wid = tid >> 5, lid = tid & 31;
    const int wm = wid >> 2, wn = wid & 3;
    const int m0 = blockIdx.y * 128, n0 = bn * 128;

    const int tile = tid >> 6;
    const int tl = tid & 63;
    const __nv_bfloat16* tsrc =
        (tile == 0) ? Ahi + (size_t)m0 * K :
        (tile == 1) ? Alo + (size_t)m0 * K :
        (tile == 2) ? Bhi + (size_t)n0 * K :
                      Blo + (size_t)n0 * K;

    float acc[4][4][4];
#pragma unroll
    for (int mt = 0; mt < 4; mt++)
#pragma unroll
        for (int nt = 0; nt < 4; nt++)
#pragma unroll
            for (int j = 0; j < 4; j++) acc[mt][nt][j] = 0.f;

    const int nch = K / BK;

    auto issue = [&](int ch, int buf) {
        const __nv_bfloat16* src = tsrc + ch * BK;
        uint32_t base = sbase + (uint32_t)(buf * 4 + tile) * TILE_BYTES2;
#pragma unroll
        for (int it = 0; it < 8; it++) {
            int o = tl + it * 64;
            int row = o >> 2, seg = o & 3;
            cp16(base + row * 80 + seg * 16, src + (size_t)row * K + seg * 8);
        }
        asm volatile("cp.async.commit_group;" ::: "memory");
    };

    issue(0, 0);

    const int laneRow = (lid & 7) + ((lid >> 3) & 1) * 8;
    const int laneCol = (lid >> 4) * 16;

    for (int ch = 0; ch < nch; ch++) {
        const int buf = ch & 1;
        if (ch + 1 < nch) {
            issue(ch + 1, buf ^ 1);
            asm volatile("cp.async.wait_group 1;" ::: "memory");
        } else {
            asm volatile("cp.async.wait_group 0;" ::: "memory");
        }
        __syncthreads();

        const uint32_t Abase = sbase + (uint32_t)(buf * 4 + 0) * TILE_BYTES2
                             + (wm * 64 + laneRow) * 80 + laneCol;
        const uint32_t Bbase = sbase + (uint32_t)(buf * 4 + 2) * TILE_BYTES2
                             + (wn * 32 + laneRow) * 80 + laneCol;

#pragma unroll
        for (int ks = 0; ks < 2; ks++) {
            const uint32_t kb = ks * 32;
            // terms: t0=(AHi,BHi), t1=(AHi,BLo), t2=(ALo,BHi)
#pragma unroll
            for (int t = 0; t < 3; t++) {
                const uint32_t Ab = Abase + ((t == 2) ? TILE_BYTES2 : 0) + kb;
                const uint32_t Bb = Bbase + ((t == 1) ? TILE_BYTES2 : 0) + kb;
                uint32_t a[4][4], b[4][2];
#pragma unroll
                for (int mt = 0; mt < 4; mt++)
                    LDMX4(a[mt][0], a[mt][1], a[mt][2], a[mt][3],
                          Ab + mt * 16 * 80);
#pragma unroll
                for (int j = 0; j < 2; j++) {
                    uint32_t t0, t1, t2, t3;
                    LDMX4(t0, t1, t2, t3, Bb + j * 16 * 80);
                    b[2 * j][0] = t0; b[2 * j][1] = t2;
                    b[2 * j + 1][0] = t1; b[2 * j + 1][1] = t3;
                }
#pragma unroll
                for (int mt = 0; mt < 4; mt++)
#pragma unroll
                    for (int nt = 0; nt < 4; nt++)
                        mma_bf16(acc[mt][nt], a[mt], b[nt]);
            }
        }
        __syncthreads();
    }

    const int rbase = m0 + wm * 64 + (lid >> 2);
    const int cbase = n0 + wn * 32 + (lid & 3) * 2;
#pragma unroll
    for (int mt = 0; mt < 4; mt++) {
#pragma unroll
        for (int nt = 0; nt < 4; nt++) {
            int r = rbase + mt * 16;
            int c = cbase + nt * 8;
            float bx = __ldg(&bias[c]), by = __ldg(&bias[c + 1]);
            float v00 = acc[mt][nt][0] + bx, v01 = acc[mt][nt][1] + by;
            float v10 = acc[mt][nt][2] + bx, v11 = acc[mt][nt][3] + by;
            if (SPLIT) {
                __nv_bfloat16 h00 = __float2bfloat16(v00), h01 = __float2bfloat16(v01);
                __nv_bfloat16 h10 = __float2bfloat16(v10), h11 = __float2bfloat16(v11);
                *(__nv_bfloat162*)&Chi[(size_t)r * N + c] = __nv_bfloat162(h00, h01);
                *(__nv_bfloat162*)&Chi[(size_t)(r + 8) * N + c] = __nv_bfloat162(h10, h11);
                *(__nv_bfloat162*)&Clo[(size_t)r * N + c] =
                    __nv_bfloat162(__float2bfloat16(v00 - __bfloat162float(h00)),
                                   __float2bfloat16(v01 - __bfloat162float(h01)));
                *(__nv_bfloat162*)&Clo[(size_t)(r + 8) * N + c] =
                    __nv_bfloat162(__float2bfloat16(v10 - __bfloat162float(h10)),
                                   __float2bfloat16(v11 - __bfloat162float(h11)));
            } else {
                *(float2*)&C[(size_t)r * N + c] = make_float2(v00, v01);
                *(float2*)&C[(size_t)(r + 8) * N + c] = make_float2(v10, v11);
            }
        }
    }
}

// Fused Q+K+V projection. bx 0..15 -> Q n-block, 16..19 -> K, 20..23 -> V.
__global__ __launch_bounds__(256, 2)
void mma_gemm_qkv_kernel(const __nv_bfloat16* __restrict__ Ahi,
                         const __nv_bfloat16* __restrict__ Alo,
                         const __nv_bfloat16* __restrict__ BhiQ,
                         const __nv_bfloat16* __restrict__ BloQ,
                         const float* __restrict__ biasQ,
                         __nv_bfloat16* __restrict__ QChi,
                         __nv_bfloat16* __restrict__ QClo,
                         const __nv_bfloat16* __restrict__ BhiK,
                         const __nv_bfloat16* __restrict__ BloK,
                         const float* __restrict__ biasK,
                         __nv_bfloat16* __restrict__ KChi,
                         __nv_bfloat16* __restrict__ KClo,
                         const __nv_bfloat16* __restrict__ BhiV,
                         const __nv_bfloat16* __restrict__ BloV,
                         const float* __restrict__ biasV,
                         __nv_bfloat16* __restrict__ VChi,
                         __nv_bfloat16* __restrict__ VClo)
{
    extern __shared__ char smg[];
    const int bx = blockIdx.x;
    if (bx < 16)
        gemm_body<true>(Ahi, Alo, BhiQ, BloQ, biasQ, nullptr, QChi, QClo,
                        bx, HID, HID, smg);
    else if (bx < 20)
        gemm_body<true>(Ahi, Alo, BhiK, BloK, biasK, nullptr, KChi, KClo,
                        bx - 16, KVDIM, HID, smg);
    else
        gemm_body<true>(Ahi, Alo, BhiV, BloV, biasV, nullptr, VChi, VClo,
                        bx - 20, KVDIM, HID, smg);
}

// Output projection (fp32 C)
__global__ __launch_bounds__(256, 2)
void mma_gemm_o_kernel(const __nv_bfloat16* __restrict__ Ahi,
                       const __nv_bfloat16* __restrict__ Alo,
                       const __nv_bfloat16* __restrict__ Bhi,
                       const __nv_bfloat16* __restrict__ Blo,
                       const float* __restrict__ bias,
                       float* __restrict__ C)
{
    extern __shared__ char smg[];
    gemm_body<false>(Ahi, Alo, Bhi, Blo, bias, C, nullptr, nullptr,
                     blockIdx.x, HID, HID, smg);
}

// ---------------------------------------------------------------------------
// HMMA flash attention (causal GQA).
// CTA: 64 Q rows, 4 warps (16 rows each), 128 threads, single KV buffer,
// 2 CTAs/SM. 3-term split for QK^T and PV.
// MMAs scheduled term-major so each accumulator's reuse distance is >= 8
// (S) / 16 (PV) independent MMAs — hides HMMA latency at 2 warps/SMSP.
// ---------------------------------------------------------------------------
constexpr int QT = 64, KT = 64;
constexpr int STRB = 272;                      // smem row stride bytes
constexpr int QTILE = QT * STRB;               // 17408
constexpr int KVT = KT * STRB;                 // 17408 per array
constexpr int OFF_QHI = 0;
constexpr int OFF_QLO = QTILE;                 // 17408
constexpr int OFF_KV  = 2 * QTILE;             // 34816
constexpr int FLASH_SMEM = OFF_KV + 4 * KVT;   // 104448
constexpr float SM_SCALE = 0.08838834764831845f;

__global__ __launch_bounds__(128, 2)
void flash_mma_kernel(const __nv_bfloat16* __restrict__ Qhi,
                      const __nv_bfloat16* __restrict__ Qlo,
                      const __nv_bfloat16* __restrict__ Khi,
                      const __nv_bfloat16* __restrict__ Klo,
                      const __nv_bfloat16* __restrict__ Vhi,
                      const __nv_bfloat16* __restrict__ Vlo,
                      __nv_bfloat16* __restrict__ Ohi,
                      __nv_bfloat16* __restrict__ Olo)
{
    extern __shared__ __nv_bfloat16 shb[];
    const uint32_t sb = smem_u32(shb);
    const int tid = threadIdx.x;
    const int w = tid >> 5, lid = tid & 31;
    const int rq = lid >> 2, cq = lid & 3;
    const int qt = blockIdx.x, h = blockIdx.y, b = blockIdx.z;
    const int g = h >> 2;
    const int q0 = qt * QT;

    // ---- load Q tile (hi+lo) ----
    {
        const __nv_bfloat16* srcs[2] = {Qhi, Qlo};
#pragma unroll
        for (int it = 0; it < 16; it++) {
            int idx = it * 128 + tid;
            int arr = idx >> 10, rem = idx & 1023;
            int row = rem >> 4, seg = rem & 15;
            const __nv_bfloat16* gp = srcs[arr]
                + (size_t)(b * SEQ + q0 + row) * HID + h * HDIM + seg * 8;
            cp16(sb + (arr ? OFF_QLO : OFF_QHI) + row * STRB + seg * 16, gp);
        }
        asm volatile("cp.async.commit_group;" ::: "memory");
    }

    const int nkt = qt + 1;

    float oacc[16][4];
#pragma unroll
    for (int nt = 0; nt < 16; nt++)
#pragma unroll
        for (int j = 0; j < 4; j++) oacc[nt][j] = 0.f;
    float m0 = -INFINITY, m1 = -INFINITY, l0 = 0.f, l1 = 0.f;

    const int iwmin = q0 + w * 16;
    const int i0 = iwmin + rq;
    const int laneRow = (lid & 7) + ((lid >> 3) & 1) * 8;
    const int laneCol = (lid >> 4) * 16;

    for (int kt = 0; kt < nkt; kt++) {
        const int k0 = kt * KT;
        __syncthreads();
        // ---- load K/V tiles ----
        {
            const __nv_bfloat16* srcs[4] = {Khi, Klo, Vhi, Vlo};
#pragma unroll
            for (int it = 0; it < 32; it++) {
                int idx = it * 128 + tid;
                int arr = idx >> 10, rem = idx & 1023;
                int row = rem >> 4, seg = rem & 15;
                const __nv_bfloat16* gp = srcs[arr]
                    + (size_t)(b * SEQ + k0 + row) * KVDIM + g * HDIM + seg * 8;
                cp16(sb + OFF_KV + arr * KVT + row * STRB + seg * 16, gp);
            }
            asm volatile("cp.async.commit_group;" ::: "memory");
            asm volatile("cp.async.wait_group 0;" ::: "memory");
        }
        __syncthreads();

        const uint32_t KbH = sb + OFF_KV + laneRow * STRB + laneCol;
        const uint32_t KbL = KbH + KVT;
        const uint32_t QbH = sb + OFF_QHI + (w * 16 + laneRow) * STRB + laneCol;
        const uint32_t QbL = QbH + QTILE;

        // ---- S = Q K^T (3 split terms), term-major sweeps ----
        float sacc[8][4];
#pragma unroll
        for (int nt = 0; nt < 8; nt++)
#pragma unroll
            for (int j = 0; j < 4; j++) sacc[nt][j] = 0.f;

#pragma unroll
        for (int ks = 0; ks < 8; ks++) {
            const uint32_t kb = ks * 32;
            uint32_t aHi[4], aLo[4], bHi[8][2], bLo[8][2];
            LDMX4(aHi[0], aHi[1], aHi[2], aHi[3], QbH + kb);
            LDMX4(aLo[0], aLo[1], aLo[2], aLo[3], QbL + kb);
#pragma unroll
            for (int j = 0; j < 4; j++) {
                uint32_t t0, t1, t2, t3;
                LDMX4(t0, t1, t2, t3, KbH + j * 16 * STRB + kb);
                bHi[2 * j][0] = t0; bHi[2 * j][1] = t2;
                bHi[2 * j + 1][0] = t1; bHi[2 * j + 1][1] = t3;
                LDMX4(t0, t1, t2, t3, KbL + j * 16 * STRB + kb);
                bLo[2 * j][0] = t0; bLo[2 * j][1] = t2;
                bLo[2 * j + 1][0] = t1; bLo[2 * j + 1][1] = t3;
            }
            // term-major: reuse distance per accumulator = 8
#pragma unroll
            for (int nt = 0; nt < 8; nt++)
                mma_bf16(sacc[nt], aHi, bHi[nt]);
#pragma unroll
            for (int nt = 0; nt < 8; nt++)
                mma_bf16(sacc[nt], aHi, bLo[nt]);
#pragma unroll
            for (int nt = 0; nt < 8; nt++)
                mma_bf16(sacc[nt], aLo, bHi[nt]);
        }

        // ---- scale + causal mask ----
        const bool need_mask = (k0 + KT - 1) > iwmin;
#pragma unroll
        for (int nt = 0; nt < 8; nt++) {
#pragma unroll
            for (int j = 0; j < 4; j++) {
                float s = sacc[nt][j] * SM_SCALE;
                if (need_mask) {
                    int jj = k0 + nt * 8 + cq * 2 + (j & 1);
                    int ii = i0 + ((j >> 1) << 3);
                    if (jj > ii) s = -1e30f;
                }
                sacc[nt][j] = s;
            }
        }

        // ---- online softmax ----
        float mx0 = -INFINITY, mx1 = -INFINITY;
#pragma unroll
        for (int nt = 0; nt < 8; nt++) {
            mx0 = fmaxf(mx0, fmaxf(sacc[nt][0], sacc[nt][1]));
            mx1 = fmaxf(mx1, fmaxf(sacc[nt][2], sacc[nt][3]));
        }
        mx0 = fmaxf(mx0, __shfl_xor_sync(0xffffffffu, mx0, 1));
        mx0 = fmaxf(mx0, __shfl_xor_sync(0xffffffffu, mx0, 2));
        mx1 = fmaxf(mx1, __shfl_xor_sync(0xffffffffu, mx1, 1));
        mx1 = fmaxf(mx1, __shfl_xor_sync(0xffffffffu, mx1, 2));
        float mn0 = fmaxf(m0, mx0), mn1 = fmaxf(m1, mx1);
        float al0 = __expf(m0 - mn0), al1 = __expf(m1 - mn1);
        m0 = mn0; m1 = mn1;

        float ls0 = 0.f, ls1 = 0.f;
#pragma unroll
        for (int nt = 0; nt < 8; nt++) {
            float p0 = __expf(sacc[nt][0] - mn0);
            float p1 = __expf(sacc[nt][1] - mn0);
            float p2 = __expf(sacc[nt][2] - mn1);
            float p3 = __expf(sacc[nt][3] - mn1);
            ls0 += p0 + p1; ls1 += p2 + p3;
            sacc[nt][0] = p0; sacc[nt][1] = p1; sacc[nt][2] = p2; sacc[nt][3] = p3;
        }
        ls0 += __shfl_xor_sync(0xffffffffu, ls0, 1);
        ls0 += __shfl_xor_sync(0xffffffffu, ls0, 2);
        ls1 += __shfl_xor_sync(0xffffffffu, ls1, 1);
        ls1 += __shfl_xor_sync(0xffffffffu, ls1, 2);
        l0 = l0 * al0 + ls0;
        l1 = l1 * al1 + ls1;

#pragma unroll
        for (int nt = 0; nt < 16; nt++) {
            oacc[nt][0] *= al0; oacc[nt][1] *= al0;
            oacc[nt][2] *= al1; oacc[nt][3] *= al1;
        }

        // ---- O += P V (3 split terms), V fragments hoisted, term-major ----
        const uint32_t VbH = sb + OFF_KV + 2 * KVT;
#pragma unroll
        for (int ks = 0; ks < 4; ks++) {
            uint32_t aHi[4], aLo[4];
#pragma unroll
            for (int half = 0; half < 2; half++) {
                const float* p = sacc[2 * ks + half];
                float h0 = __bfloat162float(__float2bfloat16(p[0]));
                float h1 = __bfloat162float(__float2bfloat16(p[1]));
                float h2 = __bfloat162float(__float2bfloat16(p[2]));
                float h3 = __bfloat162float(__float2bfloat16(p[3]));
                aHi[2 * half + 0] = packbf(h0, h1);
                aHi[2 * half + 1] = packbf(h2, h3);
                aLo[2 * half + 0] = packbf(p[0] - h0, p[1] - h1);
                aLo[2 * half + 1] = packbf(p[2] - h2, p[3] - h3);
            }
            uint32_t bh[8][4], bl[8][4];
#pragma unroll
            for (int ntp = 0; ntp < 8; ntp++) {
                const uint32_t va = VbH + (ks * 16 + (lid & 15)) * STRB
                                  + (ntp * 16 + ((lid >> 4) << 3)) * 2;
                LDMX4T(bh[ntp][0], bh[ntp][1], bh[ntp][2], bh[ntp][3], va);
                LDMX4T(bl[ntp][0], bl[ntp][1], bl[ntp][2], bl[ntp][3], va + KVT);
            }
            // term-major: reuse distance per accumulator = 16
#pragma unroll
            for (int ntp = 0; ntp < 8; ntp++) {
                mma_bf16(oacc[2 * ntp + 0], aHi, &bh[ntp][0]);
                mma_bf16(oacc[2 * ntp + 1], aHi, &bh[ntp][2]);
            }
#pragma unroll
            for (int ntp = 0; ntp < 8; ntp++) {
                mma_bf16(oacc[2 * ntp + 0], aHi, &bl[ntp][0]);
                mma_bf16(oacc[2 * ntp + 1], aHi, &bl[ntp][2]);
            }
#pragma unroll
            for (int ntp = 0; ntp < 8; ntp++) {
                mma_bf16(oacc[2 * ntp + 0], aLo, &bh[ntp][0]);
                mma_bf16(oacc[2 * ntp + 1], aLo, &bh[ntp][2]);
            }
        }
    }

    // ---- normalize + store ----
    const float rl0 = 1.f / l0, rl1 = 1.f / l1;
    const size_t row0 = (size_t)(b * SEQ + q0 + w * 16 + rq);
#pragma unroll
    for (int nt = 0; nt < 16; nt++) {
        int col = h * HDIM + nt * 8 + cq * 2;
        float v00 = oacc[nt][0] * rl0, v01 = oacc[nt][1] * rl0;
        float v10 = oacc[nt][2] * rl1, v11 = oacc[nt][3] * rl1;
        __nv_bfloat16 h00 = __float2bfloat16(v00), h01 = __float2bfloat16(v01);
        __nv_bfloat16 h10 = __float2bfloat16(v10), h11 = __float2bfloat16(v11);
        *(__nv_bfloat162*)&Ohi[row0 * HID + col] = __nv_bfloat162(h00, h01);
        *(__nv_bfloat162*)&Ohi[(row0 + 8) * HID + col] = __nv_bfloat162(h10, h11);
        *(__nv_bfloat162*)&Olo[row0 * HID + col] =
            __nv_bfloat162(__float2bfloat16(v00 - __bfloat162float(h00)),
                           __float2bfloat16(v01 - __bfloat162float(h01)));
        *(__nv_bfloat162*)&Olo[(row0 + 8) * HID + col] =
            __nv_bfloat162(__float2bfloat16(v10 - __bfloat162float(h10)),
                           __float2bfloat16(v11 - __bfloat162float(h11)));
    }
}

// ---------------------------------------------------------------------------
// Launch
// ---------------------------------------------------------------------------
extern "C" void kernel_launch(void* const* d_in, const int* in_sizes, int n_in,
                              void* d_out, int out_size)
{
    const float* x  = (const float*)d_in[0];
    const float* Wq = (const float*)d_in[2];
    const float* bq = (const float*)d_in[3];
    const float* Wk = (const float*)d_in[4];
    const float* bk = (const float*)d_in[5];
    const float* Wv = (const float*)d_in[6];
    const float* bv = (const float*)d_in[7];
    const float* Wo = (const float*)d_in[8];
    const float* bo = (const float*)d_in[9];
    float* out = (float*)d_out;

    __nv_bfloat16 *Xhi, *Xlo, *Qhi, *Qlo, *Khi, *Klo, *Vhi, *Vlo, *AOhi, *AOlo;
    __nv_bfloat16 *WqThi, *WqTlo, *WkThi, *WkTlo, *WvThi, *WvTlo, *WoThi, *WoTlo;
    cudaGetSymbolAddress((void**)&Xhi, g_Xhi);
    cudaGetSymbolAddress((void**)&Xlo, g_Xlo);
    cudaGetSymbolAddress((void**)&Qhi, g_Qhi);
    cudaGetSymbolAddress((void**)&Qlo, g_Qlo);
    cudaGetSymbolAddress((void**)&Khi, g_Khi);
    cudaGetSymbolAddress((void**)&Klo, g_Klo);
    cudaGetSymbolAddress((void**)&Vhi, g_Vhi);
    cudaGetSymbolAddress((void**)&Vlo, g_Vlo);
    cudaGetSymbolAddress((void**)&AOhi, g_AOhi);
    cudaGetSymbolAddress((void**)&AOlo, g_AOlo);
    cudaGetSymbolAddress((void**)&WqThi, g_WqThi);
    cudaGetSymbolAddress((void**)&WqTlo, g_WqTlo);
    cudaGetSymbolAddress((void**)&WkThi, g_WkThi);
    cudaGetSymbolAddress((void**)&WkTlo, g_WkTlo);
    cudaGetSymbolAddress((void**)&WvThi, g_WvThi);
    cudaGetSymbolAddress((void**)&WvTlo, g_WvTlo);
    cudaGetSymbolAddress((void**)&WoThi, g_WoThi);
    cudaGetSymbolAddress((void**)&WoTlo, g_WoTlo);

    cudaFuncSetAttribute(mma_gemm_qkv_kernel,
                         cudaFuncAttributeMaxDynamicSharedMemorySize, GEMM_SMEM);
    cudaFuncSetAttribute(mma_gemm_o_kernel,
                         cudaFuncAttributeMaxDynamicSharedMemorySize, GEMM_SMEM);
    cudaFuncSetAttribute(flash_mma_kernel,
                         cudaFuncAttributeMaxDynamicSharedMemorySize, FLASH_SMEM);

    // 1) prep
    split_kernel<<<(MROWS * HID / 4 + 255) / 256, 256>>>(x, Xhi, Xlo, MROWS * HID / 4);
    transpose_split_kernel<<<dim3(HID / 32, HID / 32), 256>>>(Wq, WqThi, WqTlo, HID, HID);
    transpose_split_kernel<<<dim3(KVDIM / 32, HID / 32), 256>>>(Wk, WkThi, WkTlo, HID, KVDIM);
    transpose_split_kernel<<<dim3(KVDIM / 32, HID / 32), 256>>>(Wv, WvThi, WvTlo, HID, KVDIM);
    transpose_split_kernel<<<dim3(HID / 32, HID / 32), 256>>>(Wo, WoThi, WoTlo, HID, HID);

    // 2) fused Q+K+V projection (24 n-blocks x 32 m-blocks)
    mma_gemm_qkv_kernel<<<dim3(24, MROWS / 128), 256, GEMM_SMEM>>>(
        Xhi, Xlo,
        WqThi, WqTlo, bq, Qhi, Qlo,
        WkThi, WkTlo, bk, Khi, Klo,
        WvThi, WvTlo, bv, Vhi, Vlo);

    // 3) attention (64-row CTAs, 2 CTAs/SM)
    flash_mma_kernel<<<dim3(SEQ / QT, NHEADS, BATCH), 128, FLASH_SMEM>>>(
        Qhi, Qlo, Khi, Klo, Vhi, Vlo, AOhi, AOlo);

    // 4) output projection
    mma_gemm_o_kernel<<<dim3(HID / 128, MROWS / 128), 256, GEMM_SMEM>>>(
        AOhi, AOlo, WoThi, WoTlo, bo, out);
}

// round 11
// speedup vs baseline: 1.5246x; 1.3807x over previous
#include <cuda_runtime.h>
#include <cuda_fp16.h>
#include <math.h>
#include <stdint.h>

// Problem constants
constexpr int BATCH = 2, SEQ = 2048, HID = 2048;
constexpr int NHEADS = 16, GRP = 4, HDIM = 128;
constexpr int MROWS = BATCH * SEQ;        // 4096
constexpr int KVDIM = GRP * HDIM;         // 512

// ---------------------------------------------------------------------------
// Device-global scratch (fp16 hi/lo)
// ---------------------------------------------------------------------------
__device__ __half g_Xhi[MROWS * HID];
__device__ __half g_Xlo[MROWS * HID];
__device__ __half g_Qhi[MROWS * HID];
__device__ __half g_Qlo[MROWS * HID];
__device__ __half g_Khi[MROWS * KVDIM];
__device__ __half g_Klo[MROWS * KVDIM];      // written, not consumed (kept for simplicity)
__device__ __half g_Vhi[MROWS * KVDIM];
__device__ __half g_Vlo[MROWS * KVDIM];
__device__ __half g_AOhi[MROWS * HID];
__device__ __half g_AOlo[MROWS * HID];
// Transposed weights, [N][K] K-major
__device__ __half g_WqThi[HID * HID];
__device__ __half g_WkThi[KVDIM * HID];
__device__ __half g_WvThi[KVDIM * HID];
__device__ __half g_WoThi[HID * HID];

// ---------------------------------------------------------------------------
// Helpers
// ---------------------------------------------------------------------------
__device__ __forceinline__ uint32_t smem_u32(const void* p) {
    uint32_t a;
    asm("{ .reg .u64 t; cvta.to.shared.u64 t, %1; cvt.u32.u64 %0, t; }"
        : "=r"(a) : "l"(p));
    return a;
}
__device__ __forceinline__ void cp16(uint32_t saddr, const void* gaddr) {
    asm volatile("cp.async.cg.shared.global [%0], [%1], 16;"
                 :: "r"(saddr), "l"(gaddr));
}
__device__ __forceinline__ void mma_f16(float* c, const uint32_t* a, const uint32_t* b) {
    asm volatile("mma.sync.aligned.m16n8k16.row.col.f32.f16.f16.f32 "
                 "{%0,%1,%2,%3}, {%4,%5,%6,%7}, {%8,%9}, {%0,%1,%2,%3};"
                 : "+f"(c[0]), "+f"(c[1]), "+f"(c[2]), "+f"(c[3])
                 : "r"(a[0]), "r"(a[1]), "r"(a[2]), "r"(a[3]),
                   "r"(b[0]), "r"(b[1]));
}
#define LDMX4(r0, r1, r2, r3, addr) \
    asm volatile("ldmatrix.sync.aligned.m8n8.x4.shared.b16 {%0,%1,%2,%3}, [%4];" \
                 : "=r"(r0), "=r"(r1), "=r"(r2), "=r"(r3) : "r"(addr))
#define LDMX4T(r0, r1, r2, r3, addr) \
    asm volatile("ldmatrix.sync.aligned.m8n8.x4.trans.shared.b16 {%0,%1,%2,%3}, [%4];" \
                 : "=r"(r0), "=r"(r1), "=r"(r2), "=r"(r3) : "r"(addr))

__device__ __forceinline__ uint32_t packh(float x, float y) {
    __half2 t = __floats2half2_rn(x, y);
    return *(uint32_t*)&t;
}

// ---------------------------------------------------------------------------
// Split fp32 -> hi/lo fp16
// ---------------------------------------------------------------------------
__global__ __launch_bounds__(256)
void split_kernel(const float* __restrict__ x, __half* __restrict__ hi,
                  __half* __restrict__ lo, int n4)
{
    int i = blockIdx.x * blockDim.x + threadIdx.x;
    if (i >= n4) return;
    float4 v = ((const float4*)x)[i];
    __half h0 = __float2half_rn(v.x), h1 = __float2half_rn(v.y);
    __half h2 = __float2half_rn(v.z), h3 = __float2half_rn(v.w);
    ((__half2*)hi)[i * 2 + 0] = __half2(h0, h1);
    ((__half2*)hi)[i * 2 + 1] = __half2(h2, h3);
    ((__half2*)lo)[i * 2 + 0] =
        __half2(__float2half_rn(v.x - __half2float(h0)),
                __float2half_rn(v.y - __half2float(h1)));
    ((__half2*)lo)[i * 2 + 1] =
        __half2(__float2half_rn(v.z - __half2float(h2)),
                __float2half_rn(v.w - __half2float(h3)));
}

// ---------------------------------------------------------------------------
// Transpose W[K][N] -> T[N][K], fp16 hi only (2-term scheme needs no W-lo)
// ---------------------------------------------------------------------------
__global__ __launch_bounds__(256)
void transpose_h_kernel(const float* __restrict__ W,
                        __half* __restrict__ Thi, int K, int N)
{
    __shared__ float tile[32][33];
    int n0 = blockIdx.x * 32, k0 = blockIdx.y * 32;
    int tx = threadIdx.x & 31, ty = threadIdx.x >> 5;
    for (int j = ty; j < 32; j += 8)
        tile[j][tx] = W[(size_t)(k0 + j) * N + n0 + tx];
    __syncthreads();
    for (int j = ty; j < 32; j += 8)
        Thi[(size_t)(n0 + j) * K + k0 + tx] = __float2half_rn(tile[tx][j]);
}

// ---------------------------------------------------------------------------
// HMMA GEMM body: C = (Ahi+Alo)[M,K] @ Bhi[N,K]^T + bias   (2-term fp16)
// 128x128 CTA tile, 8 warps (2x4), cp.async 2-stage, 3 tiles/buffer.
// ---------------------------------------------------------------------------
constexpr int BK = 32;
constexpr int RSTRIDE = 40;                         // fp16 per smem row (80 B)
constexpr int TILE_BYTES2 = 128 * RSTRIDE * 2;      // 10240 B per tile
constexpr int GEMM_SMEM = 2 * 3 * TILE_BYTES2;      // 61440 B

template <bool SPLIT>
__device__ __forceinline__ void gemm_body(
    const __half* __restrict__ Ahi, const __half* __restrict__ Alo,
    const __half* __restrict__ Bhi,
    const float* __restrict__ bias, float* __restrict__ C,
    __half* __restrict__ Chi, __half* __restrict__ Clo,
    int bn, int N, int K, char* smptr)
{
    const uint32_t sbase = smem_u32(smptr);
    const int tid = threadIdx.x;
    const int wid = tid >> 5, lid = tid & 31;
    const int wm = wid >> 2, wn = wid & 3;
    const int m0 = blockIdx.y * 128, n0 = bn * 128;

    // loader mapping: threads 0-63 -> Ahi (8 segs), 64-127 -> Alo (8 segs),
    // 128-255 -> Bhi (4 segs)
    const int tile = (tid < 64) ? 0 : (tid < 128) ? 1 : 2;
    const int tl = (tid < 128) ? (tid & 63) : (tid - 128);
    const __half* tsrc =
        (tile == 0) ? Ahi + (size_t)m0 * K :
        (tile == 1) ? Alo + (size_t)m0 * K :
                      Bhi + (size_t)n0 * K;

    float acc[4][4][4];
#pragma unroll
    for (int mt = 0; mt < 4; mt++)
#pragma unroll
        for (int nt = 0; nt < 4; nt++)
#pragma unroll
            for (int j = 0; j < 4; j++) acc[mt][nt][j] = 0.f;

    const int nch = K / BK;

    auto issue = [&](int ch, int buf) {
        const __half* src = tsrc + ch * BK;
        uint32_t base = sbase + (uint32_t)(buf * 3 + tile) * TILE_BYTES2;
        if (tid < 128) {
#pragma unroll
            for (int it = 0; it < 8; it++) {
                int o = tl + it * 64;
                cp16(base + (o >> 2) * 80 + (o & 3) * 16,
                     src + (size_t)(o >> 2) * K + (o & 3) * 8);
            }
        } else {
#pragma unroll
            for (int it = 0; it < 4; it++) {
                int o = tl + it * 128;
                cp16(base + (o >> 2) * 80 + (o & 3) * 16,
                     src + (size_t)(o >> 2) * K + (o & 3) * 8);
            }
        }
        asm volatile("cp.async.commit_group;" ::: "memory");
    };

    issue(0, 0);

    const int laneRow = (lid & 7) + ((lid >> 3) & 1) * 8;
    const int laneCol = (lid >> 4) * 16;

    for (int ch = 0; ch < nch; ch++) {
        const int buf = ch & 1;
        if (ch + 1 < nch) {
            issue(ch + 1, buf ^ 1);
            asm volatile("cp.async.wait_group 1;" ::: "memory");
        } else {
            asm volatile("cp.async.wait_group 0;" ::: "memory");
        }
        __syncthreads();

        const uint32_t AbH = sbase + (uint32_t)(buf * 3 + 0) * TILE_BYTES2
                           + (wm * 64 + laneRow) * 80 + laneCol;
        const uint32_t AbL = AbH + TILE_BYTES2;
        const uint32_t BbH = sbase + (uint32_t)(buf * 3 + 2) * TILE_BYTES2
                           + (wn * 32 + laneRow) * 80 + laneCol;

#pragma unroll
        for (int ks = 0; ks < 2; ks++) {
            const uint32_t kb = ks * 32;
            uint32_t aHi[4][4], aLo[4][4], b[4][2];
#pragma unroll
            for (int mt = 0; mt < 4; mt++) {
                LDMX4(aHi[mt][0], aHi[mt][1], aHi[mt][2], aHi[mt][3],
                      AbH + mt * 16 * 80 + kb);
                LDMX4(aLo[mt][0], aLo[mt][1], aLo[mt][2], aLo[mt][3],
                      AbL + mt * 16 * 80 + kb);
            }
#pragma unroll
            for (int j = 0; j < 2; j++) {
                uint32_t t0, t1, t2, t3;
                LDMX4(t0, t1, t2, t3, BbH + j * 16 * 80 + kb);
                b[2 * j][0] = t0; b[2 * j][1] = t2;
                b[2 * j + 1][0] = t1; b[2 * j + 1][1] = t3;
            }
#pragma unroll
            for (int mt = 0; mt < 4; mt++)
#pragma unroll
                for (int nt = 0; nt < 4; nt++)
                    mma_f16(acc[mt][nt], aHi[mt], b[nt]);
#pragma unroll
            for (int mt = 0; mt < 4; mt++)
#pragma unroll
                for (int nt = 0; nt < 4; nt++)
                    mma_f16(acc[mt][nt], aLo[mt], b[nt]);
        }
        __syncthreads();
    }

    const int rbase = m0 + wm * 64 + (lid >> 2);
    const int cbase = n0 + wn * 32 + (lid & 3) * 2;
#pragma unroll
    for (int mt = 0; mt < 4; mt++) {
#pragma unroll
        for (int nt = 0; nt < 4; nt++) {
            int r = rbase + mt * 16;
            int c = cbase + nt * 8;
            float bx = __ldg(&bias[c]), by = __ldg(&bias[c + 1]);
            float v00 = acc[mt][nt][0] + bx, v01 = acc[mt][nt][1] + by;
            float v10 = acc[mt][nt][2] + bx, v11 = acc[mt][nt][3] + by;
            if (SPLIT) {
                __half h00 = __float2half_rn(v00), h01 = __float2half_rn(v01);
                __half h10 = __float2half_rn(v10), h11 = __float2half_rn(v11);
                *(__half2*)&Chi[(size_t)r * N + c] = __half2(h00, h01);
                *(__half2*)&Chi[(size_t)(r + 8) * N + c] = __half2(h10, h11);
                *(__half2*)&Clo[(size_t)r * N + c] =
                    __half2(__float2half_rn(v00 - __half2float(h00)),
                            __float2half_rn(v01 - __half2float(h01)));
                *(__half2*)&Clo[(size_t)(r + 8) * N + c] =
                    __half2(__float2half_rn(v10 - __half2float(h10)),
                            __float2half_rn(v11 - __half2float(h11)));
            } else {
                *(float2*)&C[(size_t)r * N + c] = make_float2(v00, v01);
                *(float2*)&C[(size_t)(r + 8) * N + c] = make_float2(v10, v11);
            }
        }
    }
}

// Fused Q+K+V projection. bx 0..15 -> Q n-block, 16..19 -> K, 20..23 -> V.
__global__ __launch_bounds__(256, 2)
void mma_gemm_qkv_kernel(const __half* __restrict__ Ahi,
                         const __half* __restrict__ Alo,
                         const __half* __restrict__ BhiQ,
                         const float* __restrict__ biasQ,
                         __half* __restrict__ QChi, __half* __restrict__ QClo,
                         const __half* __restrict__ BhiK,
                         const float* __restrict__ biasK,
                         __half* __restrict__ KChi, __half* __restrict__ KClo,
                         const __half* __restrict__ BhiV,
                         const float* __restrict__ biasV,
                         __half* __restrict__ VChi, __half* __restrict__ VClo)
{
    extern __shared__ char smg[];
    const int bx = blockIdx.x;
    if (bx < 16)
        gemm_body<true>(Ahi, Alo, BhiQ, biasQ, nullptr, QChi, QClo,
                        bx, HID, HID, smg);
    else if (bx < 20)
        gemm_body<true>(Ahi, Alo, BhiK, biasK, nullptr, KChi, KClo,
                        bx - 16, KVDIM, HID, smg);
    else
        gemm_body<true>(Ahi, Alo, BhiV, biasV, nullptr, VChi, VClo,
                        bx - 20, KVDIM, HID, smg);
}

// Output projection (fp32 C)
__global__ __launch_bounds__(256, 2)
void mma_gemm_o_kernel(const __half* __restrict__ Ahi,
                       const __half* __restrict__ Alo,
                       const __half* __restrict__ Bhi,
                       const float* __restrict__ bias,
                       float* __restrict__ C)
{
    extern __shared__ char smg[];
    gemm_body<false>(Ahi, Alo, Bhi, bias, C, nullptr, nullptr,
                     blockIdx.x, HID, HID, smg);
}

// ---------------------------------------------------------------------------
// HMMA flash attention (causal GQA), fp16.
// CTA: 64 Q rows, 4 warps, 128 threads, single KV buffer, 2 CTAs/SM.
// S = (Qhi+Qlo)·Khi (2 terms, no Klo needed). PV = 3-term split (sensitive).
// ---------------------------------------------------------------------------
constexpr int QT = 64, KT = 64;
constexpr int STRB = 272;                      // smem row stride bytes
constexpr int QTILE = QT * STRB;               // 17408
constexpr int KVT = KT * STRB;                 // 17408 per array
constexpr int OFF_QHI = 0;
constexpr int OFF_QLO = QTILE;                 // 17408
constexpr int OFF_KV  = 2 * QTILE;             // 34816: Khi, Vhi, Vlo
constexpr int FLASH_SMEM = OFF_KV + 3 * KVT;   // 87040
constexpr float SM_SCALE = 0.08838834764831845f;

__global__ __launch_bounds__(128, 2)
void flash_mma_kernel(const __half* __restrict__ Qhi,
                      const __half* __restrict__ Qlo,
                      const __half* __restrict__ Khi,
                      const __half* __restrict__ Vhi,
                      const __half* __restrict__ Vlo,
                      __half* __restrict__ Ohi,
                      __half* __restrict__ Olo)
{
    extern __shared__ __half shb[];
    const uint32_t sb = smem_u32(shb);
    const int tid = threadIdx.x;
    const int w = tid >> 5, lid = tid & 31;
    const int rq = lid >> 2, cq = lid & 3;
    const int qt = blockIdx.x, h = blockIdx.y, b = blockIdx.z;
    const int g = h >> 2;
    const int q0 = qt * QT;

    // ---- load Q tile (hi+lo) ----
    {
        const __half* srcs[2] = {Qhi, Qlo};
#pragma unroll
        for (int it = 0; it < 16; it++) {
            int idx = it * 128 + tid;
            int arr = idx >> 10, rem = idx & 1023;
            int row = rem >> 4, seg = rem & 15;
            const __half* gp = srcs[arr]
                + (size_t)(b * SEQ + q0 + row) * HID + h * HDIM + seg * 8;
            cp16(sb + (arr ? OFF_QLO : OFF_QHI) + row * STRB + seg * 16, gp);
        }
        asm volatile("cp.async.commit_group;" ::: "memory");
    }

    const int nkt = qt + 1;

    float oacc[16][4];
#pragma unroll
    for (int nt = 0; nt < 16; nt++)
#pragma unroll
        for (int j = 0; j < 4; j++) oacc[nt][j] = 0.f;
    float m0 = -INFINITY, m1 = -INFINITY, l0 = 0.f, l1 = 0.f;

    const int iwmin = q0 + w * 16;
    const int i0 = iwmin + rq;
    const int laneRow = (lid & 7) + ((lid >> 3) & 1) * 8;
    const int laneCol = (lid >> 4) * 16;

    for (int kt = 0; kt < nkt; kt++) {
        const int k0 = kt * KT;
        __syncthreads();
        // ---- load K/V tiles (Khi, Vhi, Vlo): 3 x 1024 segs ----
        {
            const __half* srcs[3] = {Khi, Vhi, Vlo};
#pragma unroll
            for (int it = 0; it < 24; it++) {
                int idx = it * 128 + tid;
                int arr = idx >> 10, rem = idx & 1023;
                int row = rem >> 4, seg = rem & 15;
                const __half* gp = srcs[arr]
                    + (size_t)(b * SEQ + k0 + row) * KVDIM + g * HDIM + seg * 8;
                cp16(sb + OFF_KV + arr * KVT + row * STRB + seg * 16, gp);
            }
            asm volatile("cp.async.commit_group;" ::: "memory");
            asm volatile("cp.async.wait_group 0;" ::: "memory");
        }
        __syncthreads();

        const uint32_t KbH = sb + OFF_KV + laneRow * STRB + laneCol;
        const uint32_t QbH = sb + OFF_QHI + (w * 16 + laneRow) * STRB + laneCol;
        const uint32_t QbL = QbH + QTILE;

        // ---- S = (Qhi+Qlo) Khi^T  (2 terms) ----
        float sacc[8][4];
#pragma unroll
        for (int nt = 0; nt < 8; nt++)
#pragma unroll
            for (int j = 0; j < 4; j++) sacc[nt][j] = 0.f;

#pragma unroll
        for (int ks = 0; ks < 8; ks++) {
            const uint32_t kb = ks * 32;
            uint32_t aHi[4], aLo[4], bHi[8][2];
            LDMX4(aHi[0], aHi[1], aHi[2], aHi[3], QbH + kb);
            LDMX4(aLo[0], aLo[1], aLo[2], aLo[3], QbL + kb);
#pragma unroll
            for (int j = 0; j < 4; j++) {
                uint32_t t0, t1, t2, t3;
                LDMX4(t0, t1, t2, t3, KbH + j * 16 * STRB + kb);
                bHi[2 * j][0] = t0; bHi[2 * j][1] = t2;
                bHi[2 * j + 1][0] = t1; bHi[2 * j + 1][1] = t3;
            }
#pragma unroll
            for (int nt = 0; nt < 8; nt++)
                mma_f16(sacc[nt], aHi, bHi[nt]);
#pragma unroll
            for (int nt = 0; nt < 8; nt++)
                mma_f16(sacc[nt], aLo, bHi[nt]);
        }

        // ---- scale + causal mask ----
        const bool need_mask = (k0 + KT - 1) > iwmin;
#pragma unroll
        for (int nt = 0; nt < 8; nt++) {
#pragma unroll
            for (int j = 0; j < 4; j++) {
                float s = sacc[nt][j] * SM_SCALE;
                if (need_mask) {
                    int jj = k0 + nt * 8 + cq * 2 + (j & 1);
                    int ii = i0 + ((j >> 1) << 3);
                    if (jj > ii) s = -1e30f;
                }
                sacc[nt][j] = s;
            }
        }

        // ---- online softmax ----
        float mx0 = -INFINITY, mx1 = -INFINITY;
#pragma unroll
        for (int nt = 0; nt < 8; nt++) {
            mx0 = fmaxf(mx0, fmaxf(sacc[nt][0], sacc[nt][1]));
            mx1 = fmaxf(mx1, fmaxf(sacc[nt][2], sacc[nt][3]));
        }
        mx0 = fmaxf(mx0, __shfl_xor_sync(0xffffffffu, mx0, 1));
        mx0 = fmaxf(mx0, __shfl_xor_sync(0xffffffffu, mx0, 2));
        mx1 = fmaxf(mx1, __shfl_xor_sync(0xffffffffu, mx1, 1));
        mx1 = fmaxf(mx1, __shfl_xor_sync(0xffffffffu, mx1, 2));
        float mn0 = fmaxf(m0, mx0), mn1 = fmaxf(m1, mx1);
        float al0 = __expf(m0 - mn0), al1 = __expf(m1 - mn1);
        m0 = mn0; m1 = mn1;

        float ls0 = 0.f, ls1 = 0.f;
#pragma unroll
        for (int nt = 0; nt < 8; nt++) {
            float p0 = __expf(sacc[nt][0] - mn0);
            float p1 = __expf(sacc[nt][1] - mn0);
            float p2 = __expf(sacc[nt][2] - mn1);
            float p3 = __expf(sacc[nt][3] - mn1);
            ls0 += p0 + p1; ls1 += p2 + p3;
            sacc[nt][0] = p0; sacc[nt][1] = p1; sacc[nt][2] = p2; sacc[nt][3] = p3;
        }
        ls0 += __shfl_xor_sync(0xffffffffu, ls0, 1);
        ls0 += __shfl_xor_sync(0xffffffffu, ls0, 2);
        ls1 += __shfl_xor_sync(0xffffffffu, ls1, 1);
        ls1 += __shfl_xor_sync(0xffffffffu, ls1, 2);
        l0 = l0 * al0 + ls0;
        l1 = l1 * al1 + ls1;

#pragma unroll
        for (int nt = 0; nt < 16; nt++) {
            oacc[nt][0] *= al0; oacc[nt][1] *= al0;
            oacc[nt][2] *= al1; oacc[nt][3] *= al1;
        }

        // ---- O += P V (3 split terms: Phi*Vhi + Phi*Vlo + Plo*Vhi) ----
        const uint32_t VbH = sb + OFF_KV + KVT;     // Vhi
#pragma unroll
        for (int ks = 0; ks < 4; ks++) {
            uint32_t aHi[4], aLo[4];
#pragma unroll
            for (int half = 0; half < 2; half++) {
                const float* p = sacc[2 * ks + half];
                float h0 = __half2float(__float2half_rn(p[0]));
                float h1 = __half2float(__float2half_rn(p[1]));
                float h2 = __half2float(__float2half_rn(p[2]));
                float h3 = __half2float(__float2half_rn(p[3]));
                aHi[2 * half + 0] = packh(h0, h1);
                aHi[2 * half + 1] = packh(h2, h3);
                aLo[2 * half + 0] = packh(p[0] - h0, p[1] - h1);
                aLo[2 * half + 1] = packh(p[2] - h2, p[3] - h3);
            }
            uint32_t bh[8][4], bl[8][4];
#pragma unroll
            for (int ntp = 0; ntp < 8; ntp++) {
                const uint32_t va = VbH + (ks * 16 + (lid & 15)) * STRB
                                  + (ntp * 16 + ((lid >> 4) << 3)) * 2;
                LDMX4T(bh[ntp][0], bh[ntp][1], bh[ntp][2], bh[ntp][3], va);
                LDMX4T(bl[ntp][0], bl[ntp][1], bl[ntp][2], bl[ntp][3], va + KVT);
            }
#pragma unroll
            for (int ntp = 0; ntp < 8; ntp++) {
                mma_f16(oacc[2 * ntp + 0], aHi, &bh[ntp][0]);
                mma_f16(oacc[2 * ntp + 1], aHi, &bh[ntp][2]);
            }
#pragma unroll
            for (int ntp = 0; ntp < 8; ntp++) {
                mma_f16(oacc[2 * ntp + 0], aHi, &bl[ntp][0]);
                mma_f16(oacc[2 * ntp + 1], aHi, &bl[ntp][2]);
            }
#pragma unroll
            for (int ntp = 0; ntp < 8; ntp++) {
                mma_f16(oacc[2 * ntp + 0], aLo, &bh[ntp][0]);
                mma_f16(oacc[2 * ntp + 1], aLo, &bh[ntp][2]);
            }
        }
    }

    // ---- normalize + store ----
    const float rl0 = 1.f / l0, rl1 = 1.f / l1;
    const size_t row0 = (size_t)(b * SEQ + q0 + w * 16 + rq);
#pragma unroll
    for (int nt = 0; nt < 16; nt++) {
        int col = h * HDIM + nt * 8 + cq * 2;
        float v00 = oacc[nt][0] * rl0, v01 = oacc[nt][1] * rl0;
        float v10 = oacc[nt][2] * rl1, v11 = oacc[nt][3] * rl1;
        __half h00 = __float2half_rn(v00), h01 = __float2half_rn(v01);
        __half h10 = __float2half_rn(v10), h11 = __float2half_rn(v11);
        *(__half2*)&Ohi[row0 * HID + col] = __half2(h00, h01);
        *(__half2*)&Ohi[(row0 + 8) * HID + col] = __half2(h10, h11);
        *(__half2*)&Olo[row0 * HID + col] =
            __half2(__float2half_rn(v00 - __half2float(h00)),
                    __float2half_rn(v01 - __half2float(h01)));
        *(__half2*)&Olo[(row0 + 8) * HID + col] =
            __half2(__float2half_rn(v10 - __half2float(h10)),
                    __float2half_rn(v11 - __half2float(h11)));
    }
}

// ---------------------------------------------------------------------------
// Launch
// ---------------------------------------------------------------------------
extern "C" void kernel_launch(void* const* d_in, const int* in_sizes, int n_in,
                              void* d_out, int out_size)
{
    const float* x  = (const float*)d_in[0];
    const float* Wq = (const float*)d_in[2];
    const float* bq = (const float*)d_in[3];
    const float* Wk = (const float*)d_in[4];
    const float* bk = (const float*)d_in[5];
    const float* Wv = (const float*)d_in[6];
    const float* bv = (const float*)d_in[7];
    const float* Wo = (const float*)d_in[8];
    const float* bo = (const float*)d_in[9];
    float* out = (float*)d_out;

    __half *Xhi, *Xlo, *Qhi, *Qlo, *Khi, *Klo, *Vhi, *Vlo, *AOhi, *AOlo;
    __half *WqThi, *WkThi, *WvThi, *WoThi;
    cudaGetSymbolAddress((void**)&Xhi, g_Xhi);
    cudaGetSymbolAddress((void**)&Xlo, g_Xlo);
    cudaGetSymbolAddress((void**)&Qhi, g_Qhi);
    cudaGetSymbolAddress((void**)&Qlo, g_Qlo);
    cudaGetSymbolAddress((void**)&Khi, g_Khi);
    cudaGetSymbolAddress((void**)&Klo, g_Klo);
    cudaGetSymbolAddress((void**)&Vhi, g_Vhi);
    cudaGetSymbolAddress((void**)&Vlo, g_Vlo);
    cudaGetSymbolAddress((void**)&AOhi, g_AOhi);
    cudaGetSymbolAddress((void**)&AOlo, g_AOlo);
    cudaGetSymbolAddress((void**)&WqThi, g_WqThi);
    cudaGetSymbolAddress((void**)&WkThi, g_WkThi);
    cudaGetSymbolAddress((void**)&WvThi, g_WvThi);
    cudaGetSymbolAddress((void**)&WoThi, g_WoThi);

    cudaFuncSetAttribute(mma_gemm_qkv_kernel,
                         cudaFuncAttributeMaxDynamicSharedMemorySize, GEMM_SMEM);
    cudaFuncSetAttribute(mma_gemm_o_kernel,
                         cudaFuncAttributeMaxDynamicSharedMemorySize, GEMM_SMEM);
    cudaFuncSetAttribute(flash_mma_kernel,
                         cudaFuncAttributeMaxDynamicSharedMemorySize, FLASH_SMEM);

    // 1) prep
    split_kernel<<<(MROWS * HID / 4 + 255) / 256, 256>>>(x, Xhi, Xlo, MROWS * HID / 4);
    transpose_h_kernel<<<dim3(HID / 32, HID / 32), 256>>>(Wq, WqThi, HID, HID);
    transpose_h_kernel<<<dim3(KVDIM / 32, HID / 32), 256>>>(Wk, WkThi, HID, KVDIM);
    transpose_h_kernel<<<dim3(KVDIM / 32, HID / 32), 256>>>(Wv, WvThi, HID, KVDIM);
    transpose_h_kernel<<<dim3(HID / 32, HID / 32), 256>>>(Wo, WoThi, HID, HID);

    // 2) fused Q+K+V projection (24 n-blocks x 32 m-blocks)
    mma_gemm_qkv_kernel<<<dim3(24, MROWS / 128), 256, GEMM_SMEM>>>(
        Xhi, Xlo,
        WqThi, bq, Qhi, Qlo,
        WkThi, bk, Khi, Klo,
        WvThi, bv, Vhi, Vlo);

    // 3) attention (64-row CTAs, 2 CTAs/SM)
    flash_mma_kernel<<<dim3(SEQ / QT, NHEADS, BATCH), 128, FLASH_SMEM>>>(
        Qhi, Qlo, Khi, Vhi, Vlo, AOhi, AOlo);

    // 4) output projection
    mma_gemm_o_kernel<<<dim3(HID / 128, MROWS / 128), 256, GEMM_SMEM>>>(
        AOhi, AOlo, WoThi, bo, out);
}

// round 12
// speedup vs baseline: 2.5736x; 1.6881x over previous
#include <cuda_runtime.h>
#include <cuda_fp16.h>
#include <math.h>
#include <stdint.h>

// Problem constants
constexpr int BATCH = 2, SEQ = 2048, HID = 2048;
constexpr int NHEADS = 16, GRP = 4, HDIM = 128;
constexpr int MROWS = BATCH * SEQ;        // 4096
constexpr int KVDIM = GRP * HDIM;         // 512

// ---------------------------------------------------------------------------
// Device-global scratch (pure fp16)
// ---------------------------------------------------------------------------
__device__ __half g_X[MROWS * HID];
__device__ __half g_Q[MROWS * HID];
__device__ __half g_K[MROWS * KVDIM];
__device__ __half g_V[MROWS * KVDIM];
__device__ __half g_AO[MROWS * HID];
// Transposed weights, [N][K] K-major
__device__ __half g_WqT[HID * HID];
__device__ __half g_WkT[KVDIM * HID];
__device__ __half g_WvT[KVDIM * HID];
__device__ __half g_WoT[HID * HID];

// ---------------------------------------------------------------------------
// Helpers
// ---------------------------------------------------------------------------
__device__ __forceinline__ uint32_t smem_u32(const void* p) {
    uint32_t a;
    asm("{ .reg .u64 t; cvta.to.shared.u64 t, %1; cvt.u32.u64 %0, t; }"
        : "=r"(a) : "l"(p));
    return a;
}
__device__ __forceinline__ void cp16(uint32_t saddr, const void* gaddr) {
    asm volatile("cp.async.cg.shared.global [%0], [%1], 16;"
                 :: "r"(saddr), "l"(gaddr));
}
__device__ __forceinline__ void mma_f16(float* c, const uint32_t* a, const uint32_t* b) {
    asm volatile("mma.sync.aligned.m16n8k16.row.col.f32.f16.f16.f32 "
                 "{%0,%1,%2,%3}, {%4,%5,%6,%7}, {%8,%9}, {%0,%1,%2,%3};"
                 : "+f"(c[0]), "+f"(c[1]), "+f"(c[2]), "+f"(c[3])
                 : "r"(a[0]), "r"(a[1]), "r"(a[2]), "r"(a[3]),
                   "r"(b[0]), "r"(b[1]));
}
#define LDMX4(r0, r1, r2, r3, addr) \
    asm volatile("ldmatrix.sync.aligned.m8n8.x4.shared.b16 {%0,%1,%2,%3}, [%4];" \
                 : "=r"(r0), "=r"(r1), "=r"(r2), "=r"(r3) : "r"(addr))
#define LDMX4T(r0, r1, r2, r3, addr) \
    asm volatile("ldmatrix.sync.aligned.m8n8.x4.trans.shared.b16 {%0,%1,%2,%3}, [%4];" \
                 : "=r"(r0), "=r"(r1), "=r"(r2), "=r"(r3) : "r"(addr))

__device__ __forceinline__ uint32_t packh(float x, float y) {
    __half2 t = __floats2half2_rn(x, y);
    return *(uint32_t*)&t;
}

// ---------------------------------------------------------------------------
// Convert fp32 -> fp16
// ---------------------------------------------------------------------------
__global__ __launch_bounds__(256)
void convert_kernel(const float* __restrict__ x, __half* __restrict__ o, int n4)
{
    int i = blockIdx.x * blockDim.x + threadIdx.x;
    if (i >= n4) return;
    float4 v = ((const float4*)x)[i];
    ((__half2*)o)[i * 2 + 0] = __floats2half2_rn(v.x, v.y);
    ((__half2*)o)[i * 2 + 1] = __floats2half2_rn(v.z, v.w);
}

// ---------------------------------------------------------------------------
// Transpose W[K][N] -> T[N][K], fp16
// ---------------------------------------------------------------------------
__global__ __launch_bounds__(256)
void transpose_h_kernel(const float* __restrict__ W,
                        __half* __restrict__ T, int K, int N)
{
    __shared__ float tile[32][33];
    int n0 = blockIdx.x * 32, k0 = blockIdx.y * 32;
    int tx = threadIdx.x & 31, ty = threadIdx.x >> 5;
    for (int j = ty; j < 32; j += 8)
        tile[j][tx] = W[(size_t)(k0 + j) * N + n0 + tx];
    __syncthreads();
    for (int j = ty; j < 32; j += 8)
        T[(size_t)(n0 + j) * K + k0 + tx] = __float2half_rn(tile[tx][j]);
}

// ---------------------------------------------------------------------------
// HMMA GEMM body: C = A[M,K] @ B[N,K]^T + bias   (pure fp16, fp32 accum)
// 128x128 CTA tile, 8 warps (2x4), cp.async 2-stage, 2 tiles/buffer.
// ---------------------------------------------------------------------------
constexpr int BK = 32;
constexpr int RSTRIDE = 40;                         // fp16 per smem row (80 B)
constexpr int TILE_BYTES2 = 128 * RSTRIDE * 2;      // 10240 B per tile
constexpr int GEMM_SMEM = 2 * 2 * TILE_BYTES2;      // 40960 B

template <bool HALF_OUT>
__device__ __forceinline__ void gemm_body(
    const __half* __restrict__ A, const __half* __restrict__ B,
    const float* __restrict__ bias, float* __restrict__ C,
    __half* __restrict__ Ch,
    int bn, int N, int K, char* smptr)
{
    const uint32_t sbase = smem_u32(smptr);
    const int tid = threadIdx.x;
    const int wid = tid >> 5, lid = tid & 31;
    const int wm = wid >> 2, wn = wid & 3;
    const int m0 = blockIdx.y * 128, n0 = bn * 128;

    const int tile = tid >> 7;            // 0 = A, 1 = B
    const int tl = tid & 127;
    const __half* tsrc = (tile == 0) ? A + (size_t)m0 * K
                                     : B + (size_t)n0 * K;

    float acc[4][4][4];
#pragma unroll
    for (int mt = 0; mt < 4; mt++)
#pragma unroll
        for (int nt = 0; nt < 4; nt++)
#pragma unroll
            for (int j = 0; j < 4; j++) acc[mt][nt][j] = 0.f;

    const int nch = K / BK;

    auto issue = [&](int ch, int buf) {
        const __half* src = tsrc + ch * BK;
        uint32_t base = sbase + (uint32_t)(buf * 2 + tile) * TILE_BYTES2;
#pragma unroll
        for (int it = 0; it < 4; it++) {
            int o = tl + it * 128;        // 0..511
            cp16(base + (o >> 2) * 80 + (o & 3) * 16,
                 src + (size_t)(o >> 2) * K + (o & 3) * 8);
        }
        asm volatile("cp.async.commit_group;" ::: "memory");
    };

    issue(0, 0);

    const int laneRow = (lid & 7) + ((lid >> 3) & 1) * 8;
    const int laneCol = (lid >> 4) * 16;

    for (int ch = 0; ch < nch; ch++) {
        const int buf = ch & 1;
        if (ch + 1 < nch) {
            issue(ch + 1, buf ^ 1);
            asm volatile("cp.async.wait_group 1;" ::: "memory");
        } else {
            asm volatile("cp.async.wait_group 0;" ::: "memory");
        }
        __syncthreads();

        const uint32_t Ab = sbase + (uint32_t)(buf * 2 + 0) * TILE_BYTES2
                          + (wm * 64 + laneRow) * 80 + laneCol;
        const uint32_t Bb = sbase + (uint32_t)(buf * 2 + 1) * TILE_BYTES2
                          + (wn * 32 + laneRow) * 80 + laneCol;

#pragma unroll
        for (int ks = 0; ks < 2; ks++) {
            const uint32_t kb = ks * 32;
            uint32_t a[4][4], b[4][2];
#pragma unroll
            for (int mt = 0; mt < 4; mt++)
                LDMX4(a[mt][0], a[mt][1], a[mt][2], a[mt][3],
                      Ab + mt * 16 * 80 + kb);
#pragma unroll
            for (int j = 0; j < 2; j++) {
                uint32_t t0, t1, t2, t3;
                LDMX4(t0, t1, t2, t3, Bb + j * 16 * 80 + kb);
                b[2 * j][0] = t0; b[2 * j][1] = t2;
                b[2 * j + 1][0] = t1; b[2 * j + 1][1] = t3;
            }
#pragma unroll
            for (int mt = 0; mt < 4; mt++)
#pragma unroll
                for (int nt = 0; nt < 4; nt++)
                    mma_f16(acc[mt][nt], a[mt], b[nt]);
        }
        __syncthreads();
    }

    const int rbase = m0 + wm * 64 + (lid >> 2);
    const int cbase = n0 + wn * 32 + (lid & 3) * 2;
#pragma unroll
    for (int mt = 0; mt < 4; mt++) {
#pragma unroll
        for (int nt = 0; nt < 4; nt++) {
            int r = rbase + mt * 16;
            int c = cbase + nt * 8;
            float bx = __ldg(&bias[c]), by = __ldg(&bias[c + 1]);
            float v00 = acc[mt][nt][0] + bx, v01 = acc[mt][nt][1] + by;
            float v10 = acc[mt][nt][2] + bx, v11 = acc[mt][nt][3] + by;
            if (HALF_OUT) {
                *(__half2*)&Ch[(size_t)r * N + c] = __floats2half2_rn(v00, v01);
                *(__half2*)&Ch[(size_t)(r + 8) * N + c] = __floats2half2_rn(v10, v11);
            } else {
                *(float2*)&C[(size_t)r * N + c] = make_float2(v00, v01);
                *(float2*)&C[(size_t)(r + 8) * N + c] = make_float2(v10, v11);
            }
        }
    }
}

// Fused Q+K+V projection. bx 0..15 -> Q n-block, 16..19 -> K, 20..23 -> V.
__global__ __launch_bounds__(256, 2)
void mma_gemm_qkv_kernel(const __half* __restrict__ X,
                         const __half* __restrict__ BQ,
                         const float* __restrict__ biasQ,
                         __half* __restrict__ QC,
                         const __half* __restrict__ BK_,
                         const float* __restrict__ biasK,
                         __half* __restrict__ KC,
                         const __half* __restrict__ BV,
                         const float* __restrict__ biasV,
                         __half* __restrict__ VC)
{
    extern __shared__ char smg[];
    const int bx = blockIdx.x;
    if (bx < 16)
        gemm_body<true>(X, BQ, biasQ, nullptr, QC, bx, HID, HID, smg);
    else if (bx < 20)
        gemm_body<true>(X, BK_, biasK, nullptr, KC, bx - 16, KVDIM, HID, smg);
    else
        gemm_body<true>(X, BV, biasV, nullptr, VC, bx - 20, KVDIM, HID, smg);
}

// Output projection (fp32 C)
__global__ __launch_bounds__(256, 2)
void mma_gemm_o_kernel(const __half* __restrict__ A,
                       const __half* __restrict__ B,
                       const float* __restrict__ bias,
                       float* __restrict__ C)
{
    extern __shared__ char smg[];
    gemm_body<false>(A, B, bias, C, nullptr, blockIdx.x, HID, HID, smg);
}

// ---------------------------------------------------------------------------
// HMMA flash attention (causal GQA), pure fp16.
// CTA: 64 Q rows, 4 warps, 128 threads, single KV buffer, 2+ CTAs/SM.
// ---------------------------------------------------------------------------
constexpr int QT = 64, KT = 64;
constexpr int STRB = 272;                      // smem row stride bytes
constexpr int QTILE = QT * STRB;               // 17408
constexpr int KVT = KT * STRB;                 // 17408 per array
constexpr int OFF_Q = 0;
constexpr int OFF_K = QTILE;                   // 17408
constexpr int OFF_V = QTILE + KVT;             // 34816
constexpr int FLASH_SMEM = OFF_V + KVT;        // 52224
constexpr float SM_SCALE = 0.08838834764831845f;

__global__ __launch_bounds__(128, 2)
void flash_mma_kernel(const __half* __restrict__ Q,
                      const __half* __restrict__ K,
                      const __half* __restrict__ V,
                      __half* __restrict__ O)
{
    extern __shared__ __half shb[];
    const uint32_t sb = smem_u32(shb);
    const int tid = threadIdx.x;
    const int w = tid >> 5, lid = tid & 31;
    const int rq = lid >> 2, cq = lid & 3;
    const int qt = blockIdx.x, h = blockIdx.y, b = blockIdx.z;
    const int g = h >> 2;
    const int q0 = qt * QT;

    // ---- load Q tile: 64 rows x 16 segs = 1024 segs ----
#pragma unroll
    for (int it = 0; it < 8; it++) {
        int idx = it * 128 + tid;
        int row = idx >> 4, seg = idx & 15;
        cp16(sb + OFF_Q + row * STRB + seg * 16,
             Q + (size_t)(b * SEQ + q0 + row) * HID + h * HDIM + seg * 8);
    }
    asm volatile("cp.async.commit_group;" ::: "memory");

    const int nkt = qt + 1;

    float oacc[16][4];
#pragma unroll
    for (int nt = 0; nt < 16; nt++)
#pragma unroll
        for (int j = 0; j < 4; j++) oacc[nt][j] = 0.f;
    float m0 = -INFINITY, m1 = -INFINITY, l0 = 0.f, l1 = 0.f;

    const int iwmin = q0 + w * 16;
    const int i0 = iwmin + rq;
    const int laneRow = (lid & 7) + ((lid >> 3) & 1) * 8;
    const int laneCol = (lid >> 4) * 16;

    for (int kt = 0; kt < nkt; kt++) {
        const int k0 = kt * KT;
        __syncthreads();
        // ---- load K,V tiles: 2 x 1024 segs ----
        {
            const __half* srcs[2] = {K, V};
#pragma unroll
            for (int it = 0; it < 16; it++) {
                int idx = it * 128 + tid;
                int arr = idx >> 10, rem = idx & 1023;
                int row = rem >> 4, seg = rem & 15;
                cp16(sb + OFF_K + arr * KVT + row * STRB + seg * 16,
                     srcs[arr] + (size_t)(b * SEQ + k0 + row) * KVDIM
                               + g * HDIM + seg * 8);
            }
            asm volatile("cp.async.commit_group;" ::: "memory");
            asm volatile("cp.async.wait_group 0;" ::: "memory");
        }
        __syncthreads();

        const uint32_t Kb = sb + OFF_K + laneRow * STRB + laneCol;
        const uint32_t Qb = sb + OFF_Q + (w * 16 + laneRow) * STRB + laneCol;

        // ---- S = Q K^T ----
        float sacc[8][4];
#pragma unroll
        for (int nt = 0; nt < 8; nt++)
#pragma unroll
            for (int j = 0; j < 4; j++) sacc[nt][j] = 0.f;

#pragma unroll
        for (int ks = 0; ks < 8; ks++) {
            const uint32_t kb = ks * 32;
            uint32_t a[4], bK[8][2];
            LDMX4(a[0], a[1], a[2], a[3], Qb + kb);
#pragma unroll
            for (int j = 0; j < 4; j++) {
                uint32_t t0, t1, t2, t3;
                LDMX4(t0, t1, t2, t3, Kb + j * 16 * STRB + kb);
                bK[2 * j][0] = t0; bK[2 * j][1] = t2;
                bK[2 * j + 1][0] = t1; bK[2 * j + 1][1] = t3;
            }
#pragma unroll
            for (int nt = 0; nt < 8; nt++)
                mma_f16(sacc[nt], a, bK[nt]);
        }

        // ---- scale + causal mask ----
        const bool need_mask = (k0 + KT - 1) > iwmin;
#pragma unroll
        for (int nt = 0; nt < 8; nt++) {
#pragma unroll
            for (int j = 0; j < 4; j++) {
                float s = sacc[nt][j] * SM_SCALE;
                if (need_mask) {
                    int jj = k0 + nt * 8 + cq * 2 + (j & 1);
                    int ii = i0 + ((j >> 1) << 3);
                    if (jj > ii) s = -1e30f;
                }
                sacc[nt][j] = s;
            }
        }

        // ---- online softmax ----
        float mx0 = -INFINITY, mx1 = -INFINITY;
#pragma unroll
        for (int nt = 0; nt < 8; nt++) {
            mx0 = fmaxf(mx0, fmaxf(sacc[nt][0], sacc[nt][1]));
            mx1 = fmaxf(mx1, fmaxf(sacc[nt][2], sacc[nt][3]));
        }
        mx0 = fmaxf(mx0, __shfl_xor_sync(0xffffffffu, mx0, 1));
        mx0 = fmaxf(mx0, __shfl_xor_sync(0xffffffffu, mx0, 2));
        mx1 = fmaxf(mx1, __shfl_xor_sync(0xffffffffu, mx1, 1));
        mx1 = fmaxf(mx1, __shfl_xor_sync(0xffffffffu, mx1, 2));
        float mn0 = fmaxf(m0, mx0), mn1 = fmaxf(m1, mx1);
        float al0 = __expf(m0 - mn0), al1 = __expf(m1 - mn1);
        m0 = mn0; m1 = mn1;

        float ls0 = 0.f, ls1 = 0.f;
#pragma unroll
        for (int nt = 0; nt < 8; nt++) {
            float p0 = __expf(sacc[nt][0] - mn0);
            float p1 = __expf(sacc[nt][1] - mn0);
            float p2 = __expf(sacc[nt][2] - mn1);
            float p3 = __expf(sacc[nt][3] - mn1);
            ls0 += p0 + p1; ls1 += p2 + p3;
            sacc[nt][0] = p0; sacc[nt][1] = p1; sacc[nt][2] = p2; sacc[nt][3] = p3;
        }
        ls0 += __shfl_xor_sync(0xffffffffu, ls0, 1);
        ls0 += __shfl_xor_sync(0xffffffffu, ls0, 2);
        ls1 += __shfl_xor_sync(0xffffffffu, ls1, 1);
        ls1 += __shfl_xor_sync(0xffffffffu, ls1, 2);
        l0 = l0 * al0 + ls0;
        l1 = l1 * al1 + ls1;

#pragma unroll
        for (int nt = 0; nt < 16; nt++) {
            oacc[nt][0] *= al0; oacc[nt][1] *= al0;
            oacc[nt][2] *= al1; oacc[nt][3] *= al1;
        }

        // ---- O += P V (fp16 P, fp16 V) ----
        const uint32_t Vb = sb + OFF_V;
#pragma unroll
        for (int ks = 0; ks < 4; ks++) {
            uint32_t aP[4];
#pragma unroll
            for (int half = 0; half < 2; half++) {
                const float* p = sacc[2 * ks + half];
                aP[2 * half + 0] = packh(p[0], p[1]);
                aP[2 * half + 1] = packh(p[2], p[3]);
            }
            uint32_t bv[8][4];
#pragma unroll
            for (int ntp = 0; ntp < 8; ntp++) {
                const uint32_t va = Vb + (ks * 16 + (lid & 15)) * STRB
                                  + (ntp * 16 + ((lid >> 4) << 3)) * 2;
                LDMX4T(bv[ntp][0], bv[ntp][1], bv[ntp][2], bv[ntp][3], va);
            }
#pragma unroll
            for (int ntp = 0; ntp < 8; ntp++) {
                mma_f16(oacc[2 * ntp + 0], aP, &bv[ntp][0]);
                mma_f16(oacc[2 * ntp + 1], aP, &bv[ntp][2]);
            }
        }
    }

    // ---- normalize + store ----
    const float rl0 = 1.f / l0, rl1 = 1.f / l1;
    const size_t row0 = (size_t)(b * SEQ + q0 + w * 16 + rq);
#pragma unroll
    for (int nt = 0; nt < 16; nt++) {
        int col = h * HDIM + nt * 8 + cq * 2;
        *(__half2*)&O[row0 * HID + col] =
            __floats2half2_rn(oacc[nt][0] * rl0, oacc[nt][1] * rl0);
        *(__half2*)&O[(row0 + 8) * HID + col] =
            __floats2half2_rn(oacc[nt][2] * rl1, oacc[nt][3] * rl1);
    }
}

// ---------------------------------------------------------------------------
// Launch
// ---------------------------------------------------------------------------
extern "C" void kernel_launch(void* const* d_in, const int* in_sizes, int n_in,
                              void* d_out, int out_size)
{
    const float* x  = (const float*)d_in[0];
    const float* Wq = (const float*)d_in[2];
    const float* bq = (const float*)d_in[3];
    const float* Wk = (const float*)d_in[4];
    const float* bk = (const float*)d_in[5];
    const float* Wv = (const float*)d_in[6];
    const float* bv = (const float*)d_in[7];
    const float* Wo = (const float*)d_in[8];
    const float* bo = (const float*)d_in[9];
    float* out = (float*)d_out;

    __half *X, *Q, *K, *V, *AO, *WqT, *WkT, *WvT, *WoT;
    cudaGetSymbolAddress((void**)&X, g_X);
    cudaGetSymbolAddress((void**)&Q, g_Q);
    cudaGetSymbolAddress((void**)&K, g_K);
    cudaGetSymbolAddress((void**)&V, g_V);
    cudaGetSymbolAddress((void**)&AO, g_AO);
    cudaGetSymbolAddress((void**)&WqT, g_WqT);
    cudaGetSymbolAddress((void**)&WkT, g_WkT);
    cudaGetSymbolAddress((void**)&WvT, g_WvT);
    cudaGetSymbolAddress((void**)&WoT, g_WoT);

    cudaFuncSetAttribute(mma_gemm_qkv_kernel,
                         cudaFuncAttributeMaxDynamicSharedMemorySize, GEMM_SMEM);
    cudaFuncSetAttribute(mma_gemm_o_kernel,
                         cudaFuncAttributeMaxDynamicSharedMemorySize, GEMM_SMEM);
    cudaFuncSetAttribute(flash_mma_kernel,
                         cudaFuncAttributeMaxDynamicSharedMemorySize, FLASH_SMEM);

    // 1) prep
    convert_kernel<<<(MROWS * HID / 4 + 255) / 256, 256>>>(x, X, MROWS * HID / 4);
    transpose_h_kernel<<<dim3(HID / 32, HID / 32), 256>>>(Wq, WqT, HID, HID);
    transpose_h_kernel<<<dim3(KVDIM / 32, HID / 32), 256>>>(Wk, WkT, HID, KVDIM);
    transpose_h_kernel<<<dim3(KVDIM / 32, HID / 32), 256>>>(Wv, WvT, HID, KVDIM);
    transpose_h_kernel<<<dim3(HID / 32, HID / 32), 256>>>(Wo, WoT, HID, HID);

    // 2) fused Q+K+V projection (24 n-blocks x 32 m-blocks)
    mma_gemm_qkv_kernel<<<dim3(24, MROWS / 128), 256, GEMM_SMEM>>>(
        X, WqT, bq, Q, WkT, bk, K, WvT, bv, V);

    // 3) attention
    flash_mma_kernel<<<dim3(SEQ / QT, NHEADS, BATCH), 128, FLASH_SMEM>>>(
        Q, K, V, AO);

    // 4) output projection
    mma_gemm_o_kernel<<<dim3(HID / 128, MROWS / 128), 256, GEMM_SMEM>>>(
        AO, WoT, bo, out);
}

// round 13
// speedup vs baseline: 2.5955x; 1.0085x over previous
#include <cuda_runtime.h>
#include <cuda_fp16.h>
#include <math.h>
#include <stdint.h>

// Problem constants
constexpr int BATCH = 2, SEQ = 2048, HID = 2048;
constexpr int NHEADS = 16, GRP = 4, HDIM = 128;
constexpr int MROWS = BATCH * SEQ;        // 4096
constexpr int KVDIM = GRP * HDIM;         // 512

// ---------------------------------------------------------------------------
// Device-global scratch (pure fp16)
// ---------------------------------------------------------------------------
__device__ __half g_X[MROWS * HID];
__device__ __half g_Q[MROWS * HID];
__device__ __half g_K[MROWS * KVDIM];
__device__ __half g_V[MROWS * KVDIM];
__device__ __half g_AO[MROWS * HID];
// Transposed weights, [N][K] K-major
__device__ __half g_WqT[HID * HID];
__device__ __half g_WkT[KVDIM * HID];
__device__ __half g_WvT[KVDIM * HID];
__device__ __half g_WoT[HID * HID];

// ---------------------------------------------------------------------------
// Helpers
// ---------------------------------------------------------------------------
__device__ __forceinline__ uint32_t smem_u32(const void* p) {
    uint32_t a;
    asm("{ .reg .u64 t; cvta.to.shared.u64 t, %1; cvt.u32.u64 %0, t; }"
        : "=r"(a) : "l"(p));
    return a;
}
__device__ __forceinline__ void cp16(uint32_t saddr, const void* gaddr) {
    asm volatile("cp.async.cg.shared.global [%0], [%1], 16;"
                 :: "r"(saddr), "l"(gaddr));
}
__device__ __forceinline__ void mma_f16(float* c, const uint32_t* a, const uint32_t* b) {
    asm volatile("mma.sync.aligned.m16n8k16.row.col.f32.f16.f16.f32 "
                 "{%0,%1,%2,%3}, {%4,%5,%6,%7}, {%8,%9}, {%0,%1,%2,%3};"
                 : "+f"(c[0]), "+f"(c[1]), "+f"(c[2]), "+f"(c[3])
                 : "r"(a[0]), "r"(a[1]), "r"(a[2]), "r"(a[3]),
                   "r"(b[0]), "r"(b[1]));
}
#define LDMX4(r0, r1, r2, r3, addr) \
    asm volatile("ldmatrix.sync.aligned.m8n8.x4.shared.b16 {%0,%1,%2,%3}, [%4];" \
                 : "=r"(r0), "=r"(r1), "=r"(r2), "=r"(r3) : "r"(addr))
#define LDMX4T(r0, r1, r2, r3, addr) \
    asm volatile("ldmatrix.sync.aligned.m8n8.x4.trans.shared.b16 {%0,%1,%2,%3}, [%4];" \
                 : "=r"(r0), "=r"(r1), "=r"(r2), "=r"(r3) : "r"(addr))

__device__ __forceinline__ uint32_t packh(float x, float y) {
    __half2 t = __floats2half2_rn(x, y);
    return *(uint32_t*)&t;
}

// ---------------------------------------------------------------------------
// Convert fp32 -> fp16
// ---------------------------------------------------------------------------
__global__ __launch_bounds__(256)
void convert_kernel(const float* __restrict__ x, __half* __restrict__ o, int n4)
{
    int i = blockIdx.x * blockDim.x + threadIdx.x;
    if (i >= n4) return;
    float4 v = ((const float4*)x)[i];
    ((__half2*)o)[i * 2 + 0] = __floats2half2_rn(v.x, v.y);
    ((__half2*)o)[i * 2 + 1] = __floats2half2_rn(v.z, v.w);
}

// ---------------------------------------------------------------------------
// Fused transpose of all 4 weights: blockIdx.z selects target.
// z=0: Wq [2048->2048], z=1: Wk [2048->512], z=2: Wv, z=3: Wo
// ---------------------------------------------------------------------------
__global__ __launch_bounds__(256)
void transpose_all_kernel(const float* __restrict__ Wq, __half* __restrict__ TQ,
                          const float* __restrict__ Wk, __half* __restrict__ TK,
                          const float* __restrict__ Wv, __half* __restrict__ TV,
                          const float* __restrict__ Wo, __half* __restrict__ TO)
{
    const int z = blockIdx.z;
    const int N = (z == 1 || z == 2) ? KVDIM : HID;
    if (blockIdx.x * 32 >= N) return;
    const float* W = (z == 0) ? Wq : (z == 1) ? Wk : (z == 2) ? Wv : Wo;
    __half* T = (z == 0) ? TQ : (z == 1) ? TK : (z == 2) ? TV : TO;
    const int K = HID;

    __shared__ float tile[32][33];
    int n0 = blockIdx.x * 32, k0 = blockIdx.y * 32;
    int tx = threadIdx.x & 31, ty = threadIdx.x >> 5;
    for (int j = ty; j < 32; j += 8)
        tile[j][tx] = W[(size_t)(k0 + j) * N + n0 + tx];
    __syncthreads();
    for (int j = ty; j < 32; j += 8)
        T[(size_t)(n0 + j) * K + k0 + tx] = __float2half_rn(tile[tx][j]);
}

// ---------------------------------------------------------------------------
// HMMA GEMM body: C = A[M,K] @ B[N,K]^T + bias   (pure fp16, fp32 accum)
// ---------------------------------------------------------------------------
constexpr int BK = 32;
constexpr int RSTRIDE = 40;                         // fp16 per smem row (80 B)
constexpr int TILE_BYTES2 = 128 * RSTRIDE * 2;      // 10240 B per tile
constexpr int GEMM_SMEM = 2 * 2 * TILE_BYTES2;      // 40960 B

template <bool HALF_OUT>
__device__ __forceinline__ void gemm_body(
    const __half* __restrict__ A, const __half* __restrict__ B,
    const float* __restrict__ bias, float* __restrict__ C,
    __half* __restrict__ Ch,
    int bn, int N, int K, char* smptr)
{
    const uint32_t sbase = smem_u32(smptr);
    const int tid = threadIdx.x;
    const int wid = tid >> 5, lid = tid & 31;
    const int wm = wid >> 2, wn = wid & 3;
    const int m0 = blockIdx.y * 128, n0 = bn * 128;

    const int tile = tid >> 7;            // 0 = A, 1 = B
    const int tl = tid & 127;
    const __half* tsrc = (tile == 0) ? A + (size_t)m0 * K
                                     : B + (size_t)n0 * K;

    float acc[4][4][4];
#pragma unroll
    for (int mt = 0; mt < 4; mt++)
#pragma unroll
        for (int nt = 0; nt < 4; nt++)
#pragma unroll
            for (int j = 0; j < 4; j++) acc[mt][nt][j] = 0.f;

    const int nch = K / BK;

    auto issue = [&](int ch, int buf) {
        const __half* src = tsrc + ch * BK;
        uint32_t base = sbase + (uint32_t)(buf * 2 + tile) * TILE_BYTES2;
#pragma unroll
        for (int it = 0; it < 4; it++) {
            int o = tl + it * 128;        // 0..511
            cp16(base + (o >> 2) * 80 + (o & 3) * 16,
                 src + (size_t)(o >> 2) * K + (o & 3) * 8);
        }
        asm volatile("cp.async.commit_group;" ::: "memory");
    };

    issue(0, 0);

    const int laneRow = (lid & 7) + ((lid >> 3) & 1) * 8;
    const int laneCol = (lid >> 4) * 16;

    for (int ch = 0; ch < nch; ch++) {
        const int buf = ch & 1;
        if (ch + 1 < nch) {
            issue(ch + 1, buf ^ 1);
            asm volatile("cp.async.wait_group 1;" ::: "memory");
        } else {
            asm volatile("cp.async.wait_group 0;" ::: "memory");
        }
        __syncthreads();

        const uint32_t Ab = sbase + (uint32_t)(buf * 2 + 0) * TILE_BYTES2
                          + (wm * 64 + laneRow) * 80 + laneCol;
        const uint32_t Bb = sbase + (uint32_t)(buf * 2 + 1) * TILE_BYTES2
                          + (wn * 32 + laneRow) * 80 + laneCol;

#pragma unroll
        for (int ks = 0; ks < 2; ks++) {
            const uint32_t kb = ks * 32;
            uint32_t a[4][4], b[4][2];
#pragma unroll
            for (int mt = 0; mt < 4; mt++)
                LDMX4(a[mt][0], a[mt][1], a[mt][2], a[mt][3],
                      Ab + mt * 16 * 80 + kb);
#pragma unroll
            for (int j = 0; j < 2; j++) {
                uint32_t t0, t1, t2, t3;
                LDMX4(t0, t1, t2, t3, Bb + j * 16 * 80 + kb);
                b[2 * j][0] = t0; b[2 * j][1] = t2;
                b[2 * j + 1][0] = t1; b[2 * j + 1][1] = t3;
            }
#pragma unroll
            for (int mt = 0; mt < 4; mt++)
#pragma unroll
                for (int nt = 0; nt < 4; nt++)
                    mma_f16(acc[mt][nt], a[mt], b[nt]);
        }
        __syncthreads();
    }

    const int rbase = m0 + wm * 64 + (lid >> 2);
    const int cbase = n0 + wn * 32 + (lid & 3) * 2;
#pragma unroll
    for (int mt = 0; mt < 4; mt++) {
#pragma unroll
        for (int nt = 0; nt < 4; nt++) {
            int r = rbase + mt * 16;
            int c = cbase + nt * 8;
            float bx = __ldg(&bias[c]), by = __ldg(&bias[c + 1]);
            float v00 = acc[mt][nt][0] + bx, v01 = acc[mt][nt][1] + by;
            float v10 = acc[mt][nt][2] + bx, v11 = acc[mt][nt][3] + by;
            if (HALF_OUT) {
                *(__half2*)&Ch[(size_t)r * N + c] = __floats2half2_rn(v00, v01);
                *(__half2*)&Ch[(size_t)(r + 8) * N + c] = __floats2half2_rn(v10, v11);
            } else {
                *(float2*)&C[(size_t)r * N + c] = make_float2(v00, v01);
                *(float2*)&C[(size_t)(r + 8) * N + c] = make_float2(v10, v11);
            }
        }
    }
}

// Fused Q+K+V projection. bx 0..15 -> Q n-block, 16..19 -> K, 20..23 -> V.
__global__ __launch_bounds__(256, 2)
void mma_gemm_qkv_kernel(const __half* __restrict__ X,
                         const __half* __restrict__ BQ,
                         const float* __restrict__ biasQ,
                         __half* __restrict__ QC,
                         const __half* __restrict__ BK_,
                         const float* __restrict__ biasK,
                         __half* __restrict__ KC,
                         const __half* __restrict__ BV,
                         const float* __restrict__ biasV,
                         __half* __restrict__ VC)
{
    extern __shared__ char smg[];
    const int bx = blockIdx.x;
    if (bx < 16)
        gemm_body<true>(X, BQ, biasQ, nullptr, QC, bx, HID, HID, smg);
    else if (bx < 20)
        gemm_body<true>(X, BK_, biasK, nullptr, KC, bx - 16, KVDIM, HID, smg);
    else
        gemm_body<true>(X, BV, biasV, nullptr, VC, bx - 20, KVDIM, HID, smg);
}

// Output projection (fp32 C)
__global__ __launch_bounds__(256, 2)
void mma_gemm_o_kernel(const __half* __restrict__ A,
                       const __half* __restrict__ B,
                       const float* __restrict__ bias,
                       float* __restrict__ C)
{
    extern __shared__ char smg[];
    gemm_body<false>(A, B, bias, C, nullptr, blockIdx.x, HID, HID, smg);
}

// ---------------------------------------------------------------------------
// HMMA flash attention (causal GQA), pure fp16, double-buffered KV.
// CTA: 64 Q rows, 4 warps, 128 threads, 2 CTAs/SM (87 KB smem each).
// qt reversed: longest CTAs launch first (causal load balancing).
// ---------------------------------------------------------------------------
constexpr int QT = 64, KT = 64;
constexpr int STRB = 272;                      // smem row stride bytes
constexpr int QTILE = QT * STRB;               // 17408
constexpr int KVT = KT * STRB;                 // 17408 per array
constexpr int OFF_Q = 0;
constexpr int OFF_KV = QTILE;                  // 2 buffers x (K,V)
constexpr int KVBUF = 2 * KVT;                 // 34816
constexpr int FLASH_SMEM = OFF_KV + 2 * KVBUF; // 87040
constexpr float SM_SCALE = 0.08838834764831845f;

__global__ __launch_bounds__(128, 2)
void flash_mma_kernel(const __half* __restrict__ Q,
                      const __half* __restrict__ K,
                      const __half* __restrict__ V,
                      __half* __restrict__ O)
{
    extern __shared__ __half shb[];
    const uint32_t sb = smem_u32(shb);
    const int tid = threadIdx.x;
    const int w = tid >> 5, lid = tid & 31;
    const int rq = lid >> 2, cq = lid & 3;
    const int qt = gridDim.x - 1 - blockIdx.x;     // reversed: big work first
    const int h = blockIdx.y, b = blockIdx.z;
    const int g = h >> 2;
    const int q0 = qt * QT;

    // ---- load Q tile ----
#pragma unroll
    for (int it = 0; it < 8; it++) {
        int idx = it * 128 + tid;
        int row = idx >> 4, seg = idx & 15;
        cp16(sb + OFF_Q + row * STRB + seg * 16,
             Q + (size_t)(b * SEQ + q0 + row) * HID + h * HDIM + seg * 8);
    }
    asm volatile("cp.async.commit_group;" ::: "memory");

    const int nkt = qt + 1;

    auto load_kv = [&](int kt) {
        const uint32_t bb = sb + OFF_KV + (uint32_t)(kt & 1) * KVBUF;
        const int k0 = kt * KT;
        const __half* srcs[2] = {K, V};
#pragma unroll
        for (int it = 0; it < 16; it++) {
            int idx = it * 128 + tid;
            int arr = idx >> 10, rem = idx & 1023;
            int row = rem >> 4, seg = rem & 15;
            cp16(bb + arr * KVT + row * STRB + seg * 16,
                 srcs[arr] + (size_t)(b * SEQ + k0 + row) * KVDIM
                           + g * HDIM + seg * 8);
        }
        asm volatile("cp.async.commit_group;" ::: "memory");
    };

    load_kv(0);

    float oacc[16][4];
#pragma unroll
    for (int nt = 0; nt < 16; nt++)
#pragma unroll
        for (int j = 0; j < 4; j++) oacc[nt][j] = 0.f;
    float m0 = -INFINITY, m1 = -INFINITY, l0 = 0.f, l1 = 0.f;

    const int iwmin = q0 + w * 16;
    const int i0 = iwmin + rq;
    const int laneRow = (lid & 7) + ((lid >> 3) & 1) * 8;
    const int laneCol = (lid >> 4) * 16;

    for (int kt = 0; kt < nkt; kt++) {
        const int k0 = kt * KT;
        __syncthreads();                   // prior readers of buf[(kt+1)&1] done
        if (kt + 1 < nkt) {
            load_kv(kt + 1);
            asm volatile("cp.async.wait_group 1;" ::: "memory");
        } else {
            asm volatile("cp.async.wait_group 0;" ::: "memory");
        }
        __syncthreads();

        const uint32_t kvb = sb + OFF_KV + (uint32_t)(kt & 1) * KVBUF;
        const uint32_t Kb = kvb + laneRow * STRB + laneCol;
        const uint32_t Qb = sb + OFF_Q + (w * 16 + laneRow) * STRB + laneCol;

        // ---- S = Q K^T ----
        float sacc[8][4];
#pragma unroll
        for (int nt = 0; nt < 8; nt++)
#pragma unroll
            for (int j = 0; j < 4; j++) sacc[nt][j] = 0.f;

#pragma unroll
        for (int ks = 0; ks < 8; ks++) {
            const uint32_t kb = ks * 32;
            uint32_t a[4], bK[8][2];
            LDMX4(a[0], a[1], a[2], a[3], Qb + kb);
#pragma unroll
            for (int j = 0; j < 4; j++) {
                uint32_t t0, t1, t2, t3;
                LDMX4(t0, t1, t2, t3, Kb + j * 16 * STRB + kb);
                bK[2 * j][0] = t0; bK[2 * j][1] = t2;
                bK[2 * j + 1][0] = t1; bK[2 * j + 1][1] = t3;
            }
#pragma unroll
            for (int nt = 0; nt < 8; nt++)
                mma_f16(sacc[nt], a, bK[nt]);
        }

        // ---- scale + causal mask ----
        const bool need_mask = (k0 + KT - 1) > iwmin;
#pragma unroll
        for (int nt = 0; nt < 8; nt++) {
#pragma unroll
            for (int j = 0; j < 4; j++) {
                float s = sacc[nt][j] * SM_SCALE;
                if (need_mask) {
                    int jj = k0 + nt * 8 + cq * 2 + (j & 1);
                    int ii = i0 + ((j >> 1) << 3);
                    if (jj > ii) s = -1e30f;
                }
                sacc[nt][j] = s;
            }
        }

        // ---- online softmax ----
        float mx0 = -INFINITY, mx1 = -INFINITY;
#pragma unroll
        for (int nt = 0; nt < 8; nt++) {
            mx0 = fmaxf(mx0, fmaxf(sacc[nt][0], sacc[nt][1]));
            mx1 = fmaxf(mx1, fmaxf(sacc[nt][2], sacc[nt][3]));
        }
        mx0 = fmaxf(mx0, __shfl_xor_sync(0xffffffffu, mx0, 1));
        mx0 = fmaxf(mx0, __shfl_xor_sync(0xffffffffu, mx0, 2));
        mx1 = fmaxf(mx1, __shfl_xor_sync(0xffffffffu, mx1, 1));
        mx1 = fmaxf(mx1, __shfl_xor_sync(0xffffffffu, mx1, 2));
        float mn0 = fmaxf(m0, mx0), mn1 = fmaxf(m1, mx1);
        float al0 = __expf(m0 - mn0), al1 = __expf(m1 - mn1);
        m0 = mn0; m1 = mn1;

        float ls0 = 0.f, ls1 = 0.f;
#pragma unroll
        for (int nt = 0; nt < 8; nt++) {
            float p0 = __expf(sacc[nt][0] - mn0);
            float p1 = __expf(sacc[nt][1] - mn0);
            float p2 = __expf(sacc[nt][2] - mn1);
            float p3 = __expf(sacc[nt][3] - mn1);
            ls0 += p0 + p1; ls1 += p2 + p3;
            sacc[nt][0] = p0; sacc[nt][1] = p1; sacc[nt][2] = p2; sacc[nt][3] = p3;
        }
        ls0 += __shfl_xor_sync(0xffffffffu, ls0, 1);
        ls0 += __shfl_xor_sync(0xffffffffu, ls0, 2);
        ls1 += __shfl_xor_sync(0xffffffffu, ls1, 1);
        ls1 += __shfl_xor_sync(0xffffffffu, ls1, 2);
        l0 = l0 * al0 + ls0;
        l1 = l1 * al1 + ls1;

#pragma unroll
        for (int nt = 0; nt < 16; nt++) {
            oacc[nt][0] *= al0; oacc[nt][1] *= al0;
            oacc[nt][2] *= al1; oacc[nt][3] *= al1;
        }

        // ---- O += P V ----
        const uint32_t Vb = kvb + KVT;
#pragma unroll
        for (int ks = 0; ks < 4; ks++) {
            uint32_t aP[4];
#pragma unroll
            for (int half = 0; half < 2; half++) {
                const float* p = sacc[2 * ks + half];
                aP[2 * half + 0] = packh(p[0], p[1]);
                aP[2 * half + 1] = packh(p[2], p[3]);
            }
            uint32_t bv[8][4];
#pragma unroll
            for (int ntp = 0; ntp < 8; ntp++) {
                const uint32_t va = Vb + (ks * 16 + (lid & 15)) * STRB
                                  + (ntp * 16 + ((lid >> 4) << 3)) * 2;
                LDMX4T(bv[ntp][0], bv[ntp][1], bv[ntp][2], bv[ntp][3], va);
            }
#pragma unroll
            for (int ntp = 0; ntp < 8; ntp++) {
                mma_f16(oacc[2 * ntp + 0], aP, &bv[ntp][0]);
                mma_f16(oacc[2 * ntp + 1], aP, &bv[ntp][2]);
            }
        }
    }

    // ---- normalize + store ----
    const float rl0 = 1.f / l0, rl1 = 1.f / l1;
    const size_t row0 = (size_t)(b * SEQ + q0 + w * 16 + rq);
#pragma unroll
    for (int nt = 0; nt < 16; nt++) {
        int col = h * HDIM + nt * 8 + cq * 2;
        *(__half2*)&O[row0 * HID + col] =
            __floats2half2_rn(oacc[nt][0] * rl0, oacc[nt][1] * rl0);
        *(__half2*)&O[(row0 + 8) * HID + col] =
            __floats2half2_rn(oacc[nt][2] * rl1, oacc[nt][3] * rl1);
    }
}

// ---------------------------------------------------------------------------
// Launch
// ---------------------------------------------------------------------------
extern "C" void kernel_launch(void* const* d_in, const int* in_sizes, int n_in,
                              void* d_out, int out_size)
{
    const float* x  = (const float*)d_in[0];
    const float* Wq = (const float*)d_in[2];
    const float* bq = (const float*)d_in[3];
    const float* Wk = (const float*)d_in[4];
    const float* bk = (const float*)d_in[5];
    const float* Wv = (const float*)d_in[6];
    const float* bv = (const float*)d_in[7];
    const float* Wo = (const float*)d_in[8];
    const float* bo = (const float*)d_in[9];
    float* out = (float*)d_out;

    __half *X, *Q, *K, *V, *AO, *WqT, *WkT, *WvT, *WoT;
    cudaGetSymbolAddress((void**)&X, g_X);
    cudaGetSymbolAddress((void**)&Q, g_Q);
    cudaGetSymbolAddress((void**)&K, g_K);
    cudaGetSymbolAddress((void**)&V, g_V);
    cudaGetSymbolAddress((void**)&AO, g_AO);
    cudaGetSymbolAddress((void**)&WqT, g_WqT);
    cudaGetSymbolAddress((void**)&WkT, g_WkT);
    cudaGetSymbolAddress((void**)&WvT, g_WvT);
    cudaGetSymbolAddress((void**)&WoT, g_WoT);

    cudaFuncSetAttribute(mma_gemm_qkv_kernel,
                         cudaFuncAttributeMaxDynamicSharedMemorySize, GEMM_SMEM);
    cudaFuncSetAttribute(mma_gemm_o_kernel,
                         cudaFuncAttributeMaxDynamicSharedMemorySize, GEMM_SMEM);
    cudaFuncSetAttribute(flash_mma_kernel,
                         cudaFuncAttributeMaxDynamicSharedMemorySize, FLASH_SMEM);

    // 1) prep (2 launches)
    convert_kernel<<<(MROWS * HID / 4 + 255) / 256, 256>>>(x, X, MROWS * HID / 4);
    transpose_all_kernel<<<dim3(HID / 32, HID / 32, 4), 256>>>(
        Wq, WqT, Wk, WkT, Wv, WvT, Wo, WoT);

    // 2) fused Q+K+V projection
    mma_gemm_qkv_kernel<<<dim3(24, MROWS / 128), 256, GEMM_SMEM>>>(
        X, WqT, bq, Q, WkT, bk, K, WvT, bv, V);

    // 3) attention (double-buffered KV, reversed qt)
    flash_mma_kernel<<<dim3(SEQ / QT, NHEADS, BATCH), 128, FLASH_SMEM>>>(
        Q, K, V, AO);

    // 4) output projection
    mma_gemm_o_kernel<<<dim3(HID / 128, MROWS / 128), 256, GEMM_SMEM>>>(
        AO, WoT, bo, out);
}

// round 14
// speedup vs baseline: 3.3372x; 1.2858x over previous
#include <cuda_runtime.h>
#include <cuda.h>
#include <cuda_fp16.h>
#include <math.h>
#include <stdint.h>

// Problem constants
constexpr int BATCH = 2, SEQ = 2048, HID = 2048;
constexpr int NHEADS = 16, GRP = 4, HDIM = 128;
constexpr int MROWS = BATCH * SEQ;        // 4096
constexpr int KVDIM = GRP * HDIM;         // 512

// ---------------------------------------------------------------------------
// Device-global scratch (pure fp16)
// ---------------------------------------------------------------------------
__device__ __align__(128) __half g_X[MROWS * HID];
__device__ __align__(128) __half g_Q[MROWS * HID];
__device__ __align__(128) __half g_K[MROWS * KVDIM];
__device__ __align__(128) __half g_V[MROWS * KVDIM];
__device__ __align__(128) __half g_AO[MROWS * HID];
// Transposed weights, [N][K] K-major
__device__ __align__(128) __half g_WqT[HID * HID];
__device__ __align__(128) __half g_WkT[KVDIM * HID];
__device__ __align__(128) __half g_WvT[KVDIM * HID];
__device__ __align__(128) __half g_WoT[HID * HID];

// ---------------------------------------------------------------------------
// Helpers
// ---------------------------------------------------------------------------
__device__ __forceinline__ uint32_t smem_u32(const void* p) {
    uint32_t a;
    asm("{ .reg .u64 t; cvta.to.shared.u64 t, %1; cvt.u32.u64 %0, t; }"
        : "=r"(a) : "l"(p));
    return a;
}
__device__ __forceinline__ void cp16(uint32_t saddr, const void* gaddr) {
    asm volatile("cp.async.cg.shared.global [%0], [%1], 16;"
                 :: "r"(saddr), "l"(gaddr));
}
__device__ __forceinline__ void mma_f16(float* c, const uint32_t* a, const uint32_t* b) {
    asm volatile("mma.sync.aligned.m16n8k16.row.col.f32.f16.f16.f32 "
                 "{%0,%1,%2,%3}, {%4,%5,%6,%7}, {%8,%9}, {%0,%1,%2,%3};"
                 : "+f"(c[0]), "+f"(c[1]), "+f"(c[2]), "+f"(c[3])
                 : "r"(a[0]), "r"(a[1]), "r"(a[2]), "r"(a[3]),
                   "r"(b[0]), "r"(b[1]));
}
#define LDMX4(r0, r1, r2, r3, addr) \
    asm volatile("ldmatrix.sync.aligned.m8n8.x4.shared.b16 {%0,%1,%2,%3}, [%4];" \
                 : "=r"(r0), "=r"(r1), "=r"(r2), "=r"(r3) : "r"(addr))
#define LDMX4T(r0, r1, r2, r3, addr) \
    asm volatile("ldmatrix.sync.aligned.m8n8.x4.trans.shared.b16 {%0,%1,%2,%3}, [%4];" \
                 : "=r"(r0), "=r"(r1), "=r"(r2), "=r"(r3) : "r"(addr))

__device__ __forceinline__ uint32_t packh(float x, float y) {
    __half2 t = __floats2half2_rn(x, y);
    return *(uint32_t*)&t;
}

#define MBAR_INIT(addr, cnt) \
    asm volatile("mbarrier.init.shared.b64 [%0], %1;" :: "r"(addr), "r"(cnt) : "memory")
#define EXPECT_TX(mbar, bytes) \
    asm volatile("mbarrier.arrive.expect_tx.shared.b64 _, [%0], %1;" \
                 :: "r"(mbar), "r"(bytes) : "memory")
#define MBAR_WAIT(addr, parity) do {                                            \
    uint32_t _m = (addr), _p = (parity), _d;                                    \
    asm volatile("{ .reg .pred p;"                                              \
        " mbarrier.try_wait.parity.acquire.cta.shared::cta.b64 p, [%1], %2;"    \
        " selp.b32 %0, 1, 0, p; }" : "=r"(_d) : "r"(_m), "r"(_p) : "memory");   \
    if (!_d) {                                                                  \
        asm volatile("{ .reg .pred P1;"                                         \
            "W%=: mbarrier.try_wait.parity.acquire.cta.shared::cta.b64 P1, [%0], %1, 0x989680;" \
            " @P1 bra.uni D%=; bra.uni W%=; D%=: }"                             \
            :: "r"(_m), "r"(_p) : "memory");                                    \
    }                                                                           \
} while (0)

__device__ __forceinline__ void tma2d(uint32_t saddr, const CUtensorMap* tm,
                                      int x, int y, uint32_t mbar) {
    asm volatile(
        "cp.async.bulk.tensor.2d.shared::cta.global.tile.mbarrier::complete_tx::bytes "
        "[%0], [%1, {%2, %3}], [%4];"
        :: "r"(saddr), "l"(tm), "r"(x), "r"(y), "r"(mbar) : "memory");
}

// ---------------------------------------------------------------------------
// Convert fp32 -> fp16
// ---------------------------------------------------------------------------
__global__ __launch_bounds__(256)
void convert_kernel(const float* __restrict__ x, __half* __restrict__ o, int n4)
{
    int i = blockIdx.x * blockDim.x + threadIdx.x;
    if (i >= n4) return;
    float4 v = ((const float4*)x)[i];
    ((__half2*)o)[i * 2 + 0] = __floats2half2_rn(v.x, v.y);
    ((__half2*)o)[i * 2 + 1] = __floats2half2_rn(v.z, v.w);
}

// ---------------------------------------------------------------------------
// Fused transpose of all 4 weights
// ---------------------------------------------------------------------------
__global__ __launch_bounds__(256)
void transpose_all_kernel(const float* __restrict__ Wq, __half* __restrict__ TQ,
                          const float* __restrict__ Wk, __half* __restrict__ TK,
                          const float* __restrict__ Wv, __half* __restrict__ TV,
                          const float* __restrict__ Wo, __half* __restrict__ TO)
{
    const int z = blockIdx.z;
    const int N = (z == 1 || z == 2) ? KVDIM : HID;
    if (blockIdx.x * 32 >= N) return;
    const float* W = (z == 0) ? Wq : (z == 1) ? Wk : (z == 2) ? Wv : Wo;
    __half* T = (z == 0) ? TQ : (z == 1) ? TK : (z == 2) ? TV : TO;
    const int K = HID;

    __shared__ float tile[32][33];
    int n0 = blockIdx.x * 32, k0 = blockIdx.y * 32;
    int tx = threadIdx.x & 31, ty = threadIdx.x >> 5;
    for (int j = ty; j < 32; j += 8)
        tile[j][tx] = W[(size_t)(k0 + j) * N + n0 + tx];
    __syncthreads();
    for (int j = ty; j < 32; j += 8)
        T[(size_t)(n0 + j) * K + k0 + tx] = __float2half_rn(tile[tx][j]);
}

// ---------------------------------------------------------------------------
// TMA GEMM body: C = A[M,K] @ B[N,K]^T + bias   (pure fp16, fp32 accum)
// 128x128 CTA tile, BK=64, SW128 swizzled smem, double-buffered TMA.
// ---------------------------------------------------------------------------
constexpr int TTILE = 128 * 128;            // 16384 B per tile (128 rows x 128B)
constexpr int OFF_BAR = 4 * TTILE;          // 65536
constexpr int GEMM_SMEM = OFF_BAR + 64;     // 65600

template <bool HALF_OUT>
__device__ __forceinline__ void gemm_body(
    const CUtensorMap* __restrict__ tmA, const CUtensorMap* __restrict__ tmB,
    const float* __restrict__ bias, float* __restrict__ C,
    __half* __restrict__ Ch,
    int bn, int N, char* smptr)
{
    const uint32_t sbase = smem_u32(smptr);
    const int tid = threadIdx.x;
    const int wid = tid >> 5, lid = tid & 31;
    const int wm = wid >> 2, wn = wid & 3;
    const int m0 = blockIdx.y * 128, n0 = bn * 128;
    const uint32_t mbar = sbase + OFF_BAR;

    if (tid == 0) {
        MBAR_INIT(mbar, 1);
        MBAR_INIT(mbar + 8, 1);
    }
    __syncthreads();

    // prologue: chunk 0 -> buf0, chunk 1 -> buf1
    if (tid == 0) {
        EXPECT_TX(mbar, 2 * TTILE);
        tma2d(sbase + 0 * TTILE, tmA, 0, m0, mbar);
        tma2d(sbase + 1 * TTILE, tmB, 0, n0, mbar);
        EXPECT_TX(mbar + 8, 2 * TTILE);
        tma2d(sbase + 2 * TTILE, tmA, 64, m0, mbar + 8);
        tma2d(sbase + 3 * TTILE, tmB, 64, n0, mbar + 8);
    }

    float acc[4][4][4];
#pragma unroll
    for (int mt = 0; mt < 4; mt++)
#pragma unroll
        for (int nt = 0; nt < 4; nt++)
#pragma unroll
            for (int j = 0; j < 4; j++) acc[mt][nt][j] = 0.f;

    const int laneRow = (lid & 7) + ((lid >> 3) & 1) * 8;
    const int cl = lid >> 4;                    // 0/1
    const uint32_t xorv = (uint32_t)(lid & 7) << 4;  // (R&7)<<4 for all frags

    uint32_t ph0 = 0, ph1 = 0;
    const int nch = HID / 64;                   // 32

    for (int ch = 0; ch < nch; ch++) {
        const int buf = ch & 1;
        if (buf == 0) { MBAR_WAIT(mbar, ph0); ph0 ^= 1; }
        else          { MBAR_WAIT(mbar + 8, ph1); ph1 ^= 1; }

        const uint32_t Ab = sbase + (uint32_t)(buf * 2 + 0) * TTILE
                          + (wm * 64 + laneRow) * 128;
        const uint32_t Bb = sbase + (uint32_t)(buf * 2 + 1) * TTILE
                          + (wn * 32 + laneRow) * 128;

#pragma unroll
        for (int ks = 0; ks < 4; ks++) {
            const uint32_t cb = ((uint32_t)(ks * 2 + cl) << 4) ^ xorv;
            uint32_t a[4][4], b[4][2];
#pragma unroll
            for (int mt = 0; mt < 4; mt++)
                LDMX4(a[mt][0], a[mt][1], a[mt][2], a[mt][3],
                      Ab + mt * 16 * 128 + cb);
#pragma unroll
            for (int j = 0; j < 2; j++) {
                uint32_t t0, t1, t2, t3;
                LDMX4(t0, t1, t2, t3, Bb + j * 16 * 128 + cb);
                b[2 * j][0] = t0; b[2 * j][1] = t2;
                b[2 * j + 1][0] = t1; b[2 * j + 1][1] = t3;
            }
#pragma unroll
            for (int mt = 0; mt < 4; mt++)
#pragma unroll
                for (int nt = 0; nt < 4; nt++)
                    mma_f16(acc[mt][nt], a[mt], b[nt]);
        }
        __syncthreads();                 // all reads of buf done
        if (ch + 2 < nch && tid == 0) {
            const uint32_t mb = (buf == 0) ? mbar : mbar + 8;
            EXPECT_TX(mb, 2 * TTILE);
            tma2d(sbase + (uint32_t)(buf * 2 + 0) * TTILE, tmA, (ch + 2) * 64, m0, mb);
            tma2d(sbase + (uint32_t)(buf * 2 + 1) * TTILE, tmB, (ch + 2) * 64, n0, mb);
        }
    }

    const int rbase = m0 + wm * 64 + (lid >> 2);
    const int cbase = n0 + wn * 32 + (lid & 3) * 2;
#pragma unroll
    for (int mt = 0; mt < 4; mt++) {
#pragma unroll
        for (int nt = 0; nt < 4; nt++) {
            int r = rbase + mt * 16;
            int c = cbase + nt * 8;
            float bx = __ldg(&bias[c]), by = __ldg(&bias[c + 1]);
            float v00 = acc[mt][nt][0] + bx, v01 = acc[mt][nt][1] + by;
            float v10 = acc[mt][nt][2] + bx, v11 = acc[mt][nt][3] + by;
            if (HALF_OUT) {
                *(__half2*)&Ch[(size_t)r * N + c] = __floats2half2_rn(v00, v01);
                *(__half2*)&Ch[(size_t)(r + 8) * N + c] = __floats2half2_rn(v10, v11);
            } else {
                *(float2*)&C[(size_t)r * N + c] = make_float2(v00, v01);
                *(float2*)&C[(size_t)(r + 8) * N + c] = make_float2(v10, v11);
            }
        }
    }
}

// Fused Q+K+V projection. bx 0..15 -> Q n-block, 16..19 -> K, 20..23 -> V.
__global__ __launch_bounds__(256, 2)
void mma_gemm_qkv_kernel(const __grid_constant__ CUtensorMap tmA,
                         const __grid_constant__ CUtensorMap tmBQ,
                         const __grid_constant__ CUtensorMap tmBK,
                         const __grid_constant__ CUtensorMap tmBV,
                         const float* __restrict__ biasQ, __half* __restrict__ QC,
                         const float* __restrict__ biasK, __half* __restrict__ KC,
                         const float* __restrict__ biasV, __half* __restrict__ VC)
{
    extern __shared__ char smg[];
    const int bx = blockIdx.x;
    if (bx < 16)
        gemm_body<true>(&tmA, &tmBQ, biasQ, nullptr, QC, bx, HID, smg);
    else if (bx < 20)
        gemm_body<true>(&tmA, &tmBK, biasK, nullptr, KC, bx - 16, KVDIM, smg);
    else
        gemm_body<true>(&tmA, &tmBV, biasV, nullptr, VC, bx - 20, KVDIM, smg);
}

// Output projection (fp32 C)
__global__ __launch_bounds__(256, 2)
void mma_gemm_o_kernel(const __grid_constant__ CUtensorMap tmA,
                       const __grid_constant__ CUtensorMap tmB,
                       const float* __restrict__ bias,
                       float* __restrict__ C)
{
    extern __shared__ char smg[];
    gemm_body<false>(&tmA, &tmB, bias, C, nullptr, blockIdx.x, HID, smg);
}

// ---------------------------------------------------------------------------
// HMMA flash attention (unchanged from round 13)
// ---------------------------------------------------------------------------
constexpr int QT = 64, KT = 64;
constexpr int STRB = 272;
constexpr int QTILE = QT * STRB;
constexpr int KVT = KT * STRB;
constexpr int OFF_Q = 0;
constexpr int OFF_KV = QTILE;
constexpr int KVBUF = 2 * KVT;
constexpr int FLASH_SMEM = OFF_KV + 2 * KVBUF;   // 87040
constexpr float SM_SCALE = 0.08838834764831845f;

__global__ __launch_bounds__(128, 2)
void flash_mma_kernel(const __half* __restrict__ Q,
                      const __half* __restrict__ K,
                      const __half* __restrict__ V,
                      __half* __restrict__ O)
{
    extern __shared__ __half shb[];
    const uint32_t sb = smem_u32(shb);
    const int tid = threadIdx.x;
    const int w = tid >> 5, lid = tid & 31;
    const int rq = lid >> 2, cq = lid & 3;
    const int qt = gridDim.x - 1 - blockIdx.x;
    const int h = blockIdx.y, b = blockIdx.z;
    const int g = h >> 2;
    const int q0 = qt * QT;

#pragma unroll
    for (int it = 0; it < 8; it++) {
        int idx = it * 128 + tid;
        int row = idx >> 4, seg = idx & 15;
        cp16(sb + OFF_Q + row * STRB + seg * 16,
             Q + (size_t)(b * SEQ + q0 + row) * HID + h * HDIM + seg * 8);
    }
    asm volatile("cp.async.commit_group;" ::: "memory");

    const int nkt = qt + 1;

    auto load_kv = [&](int kt) {
        const uint32_t bb = sb + OFF_KV + (uint32_t)(kt & 1) * KVBUF;
        const int k0 = kt * KT;
        const __half* srcs[2] = {K, V};
#pragma unroll
        for (int it = 0; it < 16; it++) {
            int idx = it * 128 + tid;
            int arr = idx >> 10, rem = idx & 1023;
            int row = rem >> 4, seg = rem & 15;
            cp16(bb + arr * KVT + row * STRB + seg * 16,
                 srcs[arr] + (size_t)(b * SEQ + k0 + row) * KVDIM
                           + g * HDIM + seg * 8);
        }
        asm volatile("cp.async.commit_group;" ::: "memory");
    };

    load_kv(0);

    float oacc[16][4];
#pragma unroll
    for (int nt = 0; nt < 16; nt++)
#pragma unroll
        for (int j = 0; j < 4; j++) oacc[nt][j] = 0.f;
    float m0 = -INFINITY, m1 = -INFINITY, l0 = 0.f, l1 = 0.f;

    const int iwmin = q0 + w * 16;
    const int i0 = iwmin + rq;
    const int laneRow = (lid & 7) + ((lid >> 3) & 1) * 8;
    const int laneCol = (lid >> 4) * 16;

    for (int kt = 0; kt < nkt; kt++) {
        const int k0 = kt * KT;
        __syncthreads();
        if (kt + 1 < nkt) {
            load_kv(kt + 1);
            asm volatile("cp.async.wait_group 1;" ::: "memory");
        } else {
            asm volatile("cp.async.wait_group 0;" ::: "memory");
        }
        __syncthreads();

        const uint32_t kvb = sb + OFF_KV + (uint32_t)(kt & 1) * KVBUF;
        const uint32_t Kb = kvb + laneRow * STRB + laneCol;
        const uint32_t Qb = sb + OFF_Q + (w * 16 + laneRow) * STRB + laneCol;

        float sacc[8][4];
#pragma unroll
        for (int nt = 0; nt < 8; nt++)
#pragma unroll
            for (int j = 0; j < 4; j++) sacc[nt][j] = 0.f;

#pragma unroll
        for (int ks = 0; ks < 8; ks++) {
            const uint32_t kb = ks * 32;
            uint32_t a[4], bK[8][2];
            LDMX4(a[0], a[1], a[2], a[3], Qb + kb);
#pragma unroll
            for (int j = 0; j < 4; j++) {
                uint32_t t0, t1, t2, t3;
                LDMX4(t0, t1, t2, t3, Kb + j * 16 * STRB + kb);
                bK[2 * j][0] = t0; bK[2 * j][1] = t2;
                bK[2 * j + 1][0] = t1; bK[2 * j + 1][1] = t3;
            }
#pragma unroll
            for (int nt = 0; nt < 8; nt++)
                mma_f16(sacc[nt], a, bK[nt]);
        }

        const bool need_mask = (k0 + KT - 1) > iwmin;
#pragma unroll
        for (int nt = 0; nt < 8; nt++) {
#pragma unroll
            for (int j = 0; j < 4; j++) {
                float s = sacc[nt][j] * SM_SCALE;
                if (need_mask) {
                    int jj = k0 + nt * 8 + cq * 2 + (j & 1);
                    int ii = i0 + ((j >> 1) << 3);
                    if (jj > ii) s = -1e30f;
                }
                sacc[nt][j] = s;
            }
        }

        float mx0 = -INFINITY, mx1 = -INFINITY;
#pragma unroll
        for (int nt = 0; nt < 8; nt++) {
            mx0 = fmaxf(mx0, fmaxf(sacc[nt][0], sacc[nt][1]));
            mx1 = fmaxf(mx1, fmaxf(sacc[nt][2], sacc[nt][3]));
        }
        mx0 = fmaxf(mx0, __shfl_xor_sync(0xffffffffu, mx0, 1));
        mx0 = fmaxf(mx0, __shfl_xor_sync(0xffffffffu, mx0, 2));
        mx1 = fmaxf(mx1, __shfl_xor_sync(0xffffffffu, mx1, 1));
        mx1 = fmaxf(mx1, __shfl_xor_sync(0xffffffffu, mx1, 2));
        float mn0 = fmaxf(m0, mx0), mn1 = fmaxf(m1, mx1);
        float al0 = __expf(m0 - mn0), al1 = __expf(m1 - mn1);
        m0 = mn0; m1 = mn1;

        float ls0 = 0.f, ls1 = 0.f;
#pragma unroll
        for (int nt = 0; nt < 8; nt++) {
            float p0 = __expf(sacc[nt][0] - mn0);
            float p1 = __expf(sacc[nt][1] - mn0);
            float p2 = __expf(sacc[nt][2] - mn1);
            float p3 = __expf(sacc[nt][3] - mn1);
            ls0 += p0 + p1; ls1 += p2 + p3;
            sacc[nt][0] = p0; sacc[nt][1] = p1; sacc[nt][2] = p2; sacc[nt][3] = p3;
        }
        ls0 += __shfl_xor_sync(0xffffffffu, ls0, 1);
        ls0 += __shfl_xor_sync(0xffffffffu, ls0, 2);
        ls1 += __shfl_xor_sync(0xffffffffu, ls1, 1);
        ls1 += __shfl_xor_sync(0xffffffffu, ls1, 2);
        l0 = l0 * al0 + ls0;
        l1 = l1 * al1 + ls1;

#pragma unroll
        for (int nt = 0; nt < 16; nt++) {
            oacc[nt][0] *= al0; oacc[nt][1] *= al0;
            oacc[nt][2] *= al1; oacc[nt][3] *= al1;
        }

        const uint32_t Vb = kvb + KVT;
#pragma unroll
        for (int ks = 0; ks < 4; ks++) {
            uint32_t aP[4];
#pragma unroll
            for (int half = 0; half < 2; half++) {
                const float* p = sacc[2 * ks + half];
                aP[2 * half + 0] = packh(p[0], p[1]);
                aP[2 * half + 1] = packh(p[2], p[3]);
            }
            uint32_t bv[8][4];
#pragma unroll
            for (int ntp = 0; ntp < 8; ntp++) {
                const uint32_t va = Vb + (ks * 16 + (lid & 15)) * STRB
                                  + (ntp * 16 + ((lid >> 4) << 3)) * 2;
                LDMX4T(bv[ntp][0], bv[ntp][1], bv[ntp][2], bv[ntp][3], va);
            }
#pragma unroll
            for (int ntp = 0; ntp < 8; ntp++) {
                mma_f16(oacc[2 * ntp + 0], aP, &bv[ntp][0]);
                mma_f16(oacc[2 * ntp + 1], aP, &bv[ntp][2]);
            }
        }
    }

    const float rl0 = 1.f / l0, rl1 = 1.f / l1;
    const size_t row0 = (size_t)(b * SEQ + q0 + w * 16 + rq);
#pragma unroll
    for (int nt = 0; nt < 16; nt++) {
        int col = h * HDIM + nt * 8 + cq * 2;
        *(__half2*)&O[row0 * HID + col] =
            __floats2half2_rn(oacc[nt][0] * rl0, oacc[nt][1] * rl0);
        *(__half2*)&O[(row0 + 8) * HID + col] =
            __floats2half2_rn(oacc[nt][2] * rl1, oacc[nt][3] * rl1);
    }
}

// ---------------------------------------------------------------------------
// Host: tensor map construction
// ---------------------------------------------------------------------------
typedef CUresult (*PFN_tmenc)(
    CUtensorMap*, CUtensorMapDataType, cuuint32_t, void*,
    const cuuint64_t*, const cuuint64_t*, const cuuint32_t*, const cuuint32_t*,
    CUtensorMapInterleave, CUtensorMapSwizzle, CUtensorMapL2promotion,
    CUtensorMapFloatOOBfill);

static void make_map(PFN_tmenc enc, CUtensorMap* tm, void* ptr,
                     unsigned long long inner, unsigned long long outer)
{
    cuuint64_t dims[2] = {inner, outer};
    cuuint64_t strides[1] = {inner * 2};
    cuuint32_t box[2] = {64, 128};
    cuuint32_t estr[2] = {1, 1};
    enc(tm, CU_TENSOR_MAP_DATA_TYPE_FLOAT16, 2, ptr, dims, strides, box, estr,
        CU_TENSOR_MAP_INTERLEAVE_NONE, CU_TENSOR_MAP_SWIZZLE_128B,
        CU_TENSOR_MAP_L2_PROMOTION_L2_128B, CU_TENSOR_MAP_FLOAT_OOB_FILL_NONE);
}

extern "C" void kernel_launch(void* const* d_in, const int* in_sizes, int n_in,
                              void* d_out, int out_size)
{
    const float* x  = (const float*)d_in[0];
    const float* Wq = (const float*)d_in[2];
    const float* bq = (const float*)d_in[3];
    const float* Wk = (const float*)d_in[4];
    const float* bk = (const float*)d_in[5];
    const float* Wv = (const float*)d_in[6];
    const float* bv = (const float*)d_in[7];
    const float* Wo = (const float*)d_in[8];
    const float* bo = (const float*)d_in[9];
    float* out = (float*)d_out;

    __half *X, *Q, *K, *V, *AO, *WqT, *WkT, *WvT, *WoT;
    cudaGetSymbolAddress((void**)&X, g_X);
    cudaGetSymbolAddress((void**)&Q, g_Q);
    cudaGetSymbolAddress((void**)&K, g_K);
    cudaGetSymbolAddress((void**)&V, g_V);
    cudaGetSymbolAddress((void**)&AO, g_AO);
    cudaGetSymbolAddress((void**)&WqT, g_WqT);
    cudaGetSymbolAddress((void**)&WkT, g_WkT);
    cudaGetSymbolAddress((void**)&WvT, g_WvT);
    cudaGetSymbolAddress((void**)&WoT, g_WoT);

    // Fetch driver encode function (no -lcuda needed)
    void* fn = nullptr;
    cudaDriverEntryPointQueryResult qr;
    cudaGetDriverEntryPoint("cuTensorMapEncodeTiled", &fn,
                            cudaEnableDefault, &qr);
    PFN_tmenc enc = (PFN_tmenc)fn;

    CUtensorMap tmX, tmWq, tmWk, tmWv, tmAO, tmWo;
    make_map(enc, &tmX,  X,   HID, MROWS);
    make_map(enc, &tmWq, WqT, HID, HID);
    make_map(enc, &tmWk, WkT, HID, KVDIM);
    make_map(enc, &tmWv, WvT, HID, KVDIM);
    make_map(enc, &tmAO, AO,  HID, MROWS);
    make_map(enc, &tmWo, WoT, HID, HID);

    cudaFuncSetAttribute(mma_gemm_qkv_kernel,
                         cudaFuncAttributeMaxDynamicSharedMemorySize, GEMM_SMEM);
    cudaFuncSetAttribute(mma_gemm_o_kernel,
                         cudaFuncAttributeMaxDynamicSharedMemorySize, GEMM_SMEM);
    cudaFuncSetAttribute(flash_mma_kernel,
                         cudaFuncAttributeMaxDynamicSharedMemorySize, FLASH_SMEM);

    // 1) prep
    convert_kernel<<<(MROWS * HID / 4 + 255) / 256, 256>>>(x, X, MROWS * HID / 4);
    transpose_all_kernel<<<dim3(HID / 32, HID / 32, 4), 256>>>(
        Wq, WqT, Wk, WkT, Wv, WvT, Wo, WoT);

    // 2) fused Q+K+V projection (TMA)
    mma_gemm_qkv_kernel<<<dim3(24, MROWS / 128), 256, GEMM_SMEM>>>(
        tmX, tmWq, tmWk, tmWv, bq, Q, bk, K, bv, V);

    // 3) attention
    flash_mma_kernel<<<dim3(SEQ / QT, NHEADS, BATCH), 128, FLASH_SMEM>>>(
        Q, K, V, AO);

    // 4) output projection (TMA)
    mma_gemm_o_kernel<<<dim3(HID / 128, MROWS / 128), 256, GEMM_SMEM>>>(
        tmAO, tmWo, bo, out);
}

// round 15
// speedup vs baseline: 3.6328x; 1.0886x over previous
#include <cuda_runtime.h>
#include <cuda.h>
#include <cuda_fp16.h>
#include <math.h>
#include <stdint.h>

// Problem constants
constexpr int BATCH = 2, SEQ = 2048, HID = 2048;
constexpr int NHEADS = 16, GRP = 4, HDIM = 128;
constexpr int MROWS = BATCH * SEQ;        // 4096
constexpr int KVDIM = GRP * HDIM;         // 512

// ---------------------------------------------------------------------------
// Device-global scratch (pure fp16)
// ---------------------------------------------------------------------------
__device__ __align__(128) __half g_X[MROWS * HID];
__device__ __align__(128) __half g_Q[MROWS * HID];
__device__ __align__(128) __half g_K[MROWS * KVDIM];
__device__ __align__(128) __half g_V[MROWS * KVDIM];
__device__ __align__(128) __half g_AO[MROWS * HID];
// Transposed weights, [N][K] K-major
__device__ __align__(128) __half g_WqT[HID * HID];
__device__ __align__(128) __half g_WkT[KVDIM * HID];
__device__ __align__(128) __half g_WvT[KVDIM * HID];
__device__ __align__(128) __half g_WoT[HID * HID];

// ---------------------------------------------------------------------------
// Helpers
// ---------------------------------------------------------------------------
__device__ __forceinline__ uint32_t smem_u32(const void* p) {
    uint32_t a;
    asm("{ .reg .u64 t; cvta.to.shared.u64 t, %1; cvt.u32.u64 %0, t; }"
        : "=r"(a) : "l"(p));
    return a;
}
__device__ __forceinline__ void mma_f16(float* c, const uint32_t* a, const uint32_t* b) {
    asm volatile("mma.sync.aligned.m16n8k16.row.col.f32.f16.f16.f32 "
                 "{%0,%1,%2,%3}, {%4,%5,%6,%7}, {%8,%9}, {%0,%1,%2,%3};"
                 : "+f"(c[0]), "+f"(c[1]), "+f"(c[2]), "+f"(c[3])
                 : "r"(a[0]), "r"(a[1]), "r"(a[2]), "r"(a[3]),
                   "r"(b[0]), "r"(b[1]));
}
#define LDMX4(r0, r1, r2, r3, addr) \
    asm volatile("ldmatrix.sync.aligned.m8n8.x4.shared.b16 {%0,%1,%2,%3}, [%4];" \
                 : "=r"(r0), "=r"(r1), "=r"(r2), "=r"(r3) : "r"(addr))
#define LDMX4T(r0, r1, r2, r3, addr) \
    asm volatile("ldmatrix.sync.aligned.m8n8.x4.trans.shared.b16 {%0,%1,%2,%3}, [%4];" \
                 : "=r"(r0), "=r"(r1), "=r"(r2), "=r"(r3) : "r"(addr))

__device__ __forceinline__ uint32_t packh(float x, float y) {
    __half2 t = __floats2half2_rn(x, y);
    return *(uint32_t*)&t;
}

#define MBAR_INIT(addr, cnt) \
    asm volatile("mbarrier.init.shared.b64 [%0], %1;" :: "r"(addr), "r"(cnt) : "memory")
#define EXPECT_TX(mbar, bytes) \
    asm volatile("mbarrier.arrive.expect_tx.shared.b64 _, [%0], %1;" \
                 :: "r"(mbar), "r"(bytes) : "memory")
#define MBAR_WAIT(addr, parity) do {                                            \
    uint32_t _m = (addr), _p = (parity), _d;                                    \
    asm volatile("{ .reg .pred p;"                                              \
        " mbarrier.try_wait.parity.acquire.cta.shared::cta.b64 p, [%1], %2;"    \
        " selp.b32 %0, 1, 0, p; }" : "=r"(_d) : "r"(_m), "r"(_p) : "memory");   \
    if (!_d) {                                                                  \
        asm volatile("{ .reg .pred P1;"                                         \
            "W%=: mbarrier.try_wait.parity.acquire.cta.shared::cta.b64 P1, [%0], %1, 0x989680;" \
            " @P1 bra.uni D%=; bra.uni W%=; D%=: }"                             \
            :: "r"(_m), "r"(_p) : "memory");                                    \
    }                                                                           \
} while (0)

__device__ __forceinline__ void tma2d(uint32_t saddr, const CUtensorMap* tm,
                                      int x, int y, uint32_t mbar) {
    asm volatile(
        "cp.async.bulk.tensor.2d.shared::cta.global.tile.mbarrier::complete_tx::bytes "
        "[%0], [%1, {%2, %3}], [%4];"
        :: "r"(saddr), "l"(tm), "r"(x), "r"(y), "r"(mbar) : "memory");
}

// ---------------------------------------------------------------------------
// Convert fp32 -> fp16
// ---------------------------------------------------------------------------
__global__ __launch_bounds__(256)
void convert_kernel(const float* __restrict__ x, __half* __restrict__ o, int n4)
{
    int i = blockIdx.x * blockDim.x + threadIdx.x;
    if (i >= n4) return;
    float4 v = ((const float4*)x)[i];
    ((__half2*)o)[i * 2 + 0] = __floats2half2_rn(v.x, v.y);
    ((__half2*)o)[i * 2 + 1] = __floats2half2_rn(v.z, v.w);
}

// ---------------------------------------------------------------------------
// Fused transpose of all 4 weights
// ---------------------------------------------------------------------------
__global__ __launch_bounds__(256)
void transpose_all_kernel(const float* __restrict__ Wq, __half* __restrict__ TQ,
                          const float* __restrict__ Wk, __half* __restrict__ TK,
                          const float* __restrict__ Wv, __half* __restrict__ TV,
                          const float* __restrict__ Wo, __half* __restrict__ TO)
{
    const int z = blockIdx.z;
    const int N = (z == 1 || z == 2) ? KVDIM : HID;
    if (blockIdx.x * 32 >= N) return;
    const float* W = (z == 0) ? Wq : (z == 1) ? Wk : (z == 2) ? Wv : Wo;
    __half* T = (z == 0) ? TQ : (z == 1) ? TK : (z == 2) ? TV : TO;
    const int K = HID;

    __shared__ float tile[32][33];
    int n0 = blockIdx.x * 32, k0 = blockIdx.y * 32;
    int tx = threadIdx.x & 31, ty = threadIdx.x >> 5;
    for (int j = ty; j < 32; j += 8)
        tile[j][tx] = W[(size_t)(k0 + j) * N + n0 + tx];
    __syncthreads();
    for (int j = ty; j < 32; j += 8)
        T[(size_t)(n0 + j) * K + k0 + tx] = __float2half_rn(tile[tx][j]);
}

// ---------------------------------------------------------------------------
// TMA GEMM body (unchanged from round 14)
// ---------------------------------------------------------------------------
constexpr int TTILE = 128 * 128;
constexpr int OFF_BAR = 4 * TTILE;
constexpr int GEMM_SMEM = OFF_BAR + 64;

template <bool HALF_OUT>
__device__ __forceinline__ void gemm_body(
    const CUtensorMap* __restrict__ tmA, const CUtensorMap* __restrict__ tmB,
    const float* __restrict__ bias, float* __restrict__ C,
    __half* __restrict__ Ch,
    int bn, int N, char* smptr)
{
    const uint32_t sbase = smem_u32(smptr);
    const int tid = threadIdx.x;
    const int wid = tid >> 5, lid = tid & 31;
    const int wm = wid >> 2, wn = wid & 3;
    const int m0 = blockIdx.y * 128, n0 = bn * 128;
    const uint32_t mbar = sbase + OFF_BAR;

    if (tid == 0) {
        MBAR_INIT(mbar, 1);
        MBAR_INIT(mbar + 8, 1);
    }
    __syncthreads();

    if (tid == 0) {
        EXPECT_TX(mbar, 2 * TTILE);
        tma2d(sbase + 0 * TTILE, tmA, 0, m0, mbar);
        tma2d(sbase + 1 * TTILE, tmB, 0, n0, mbar);
        EXPECT_TX(mbar + 8, 2 * TTILE);
        tma2d(sbase + 2 * TTILE, tmA, 64, m0, mbar + 8);
        tma2d(sbase + 3 * TTILE, tmB, 64, n0, mbar + 8);
    }

    float acc[4][4][4];
#pragma unroll
    for (int mt = 0; mt < 4; mt++)
#pragma unroll
        for (int nt = 0; nt < 4; nt++)
#pragma unroll
            for (int j = 0; j < 4; j++) acc[mt][nt][j] = 0.f;

    const int laneRow = (lid & 7) + ((lid >> 3) & 1) * 8;
    const int cl = lid >> 4;
    const uint32_t xorv = (uint32_t)(lid & 7) << 4;

    uint32_t ph0 = 0, ph1 = 0;
    const int nch = HID / 64;

    for (int ch = 0; ch < nch; ch++) {
        const int buf = ch & 1;
        if (buf == 0) { MBAR_WAIT(mbar, ph0); ph0 ^= 1; }
        else          { MBAR_WAIT(mbar + 8, ph1); ph1 ^= 1; }

        const uint32_t Ab = sbase + (uint32_t)(buf * 2 + 0) * TTILE
                          + (wm * 64 + laneRow) * 128;
        const uint32_t Bb = sbase + (uint32_t)(buf * 2 + 1) * TTILE
                          + (wn * 32 + laneRow) * 128;

#pragma unroll
        for (int ks = 0; ks < 4; ks++) {
            const uint32_t cb = ((uint32_t)(ks * 2 + cl) << 4) ^ xorv;
            uint32_t a[4][4], b[4][2];
#pragma unroll
            for (int mt = 0; mt < 4; mt++)
                LDMX4(a[mt][0], a[mt][1], a[mt][2], a[mt][3],
                      Ab + mt * 16 * 128 + cb);
#pragma unroll
            for (int j = 0; j < 2; j++) {
                uint32_t t0, t1, t2, t3;
                LDMX4(t0, t1, t2, t3, Bb + j * 16 * 128 + cb);
                b[2 * j][0] = t0; b[2 * j][1] = t2;
                b[2 * j + 1][0] = t1; b[2 * j + 1][1] = t3;
            }
#pragma unroll
            for (int mt = 0; mt < 4; mt++)
#pragma unroll
                for (int nt = 0; nt < 4; nt++)
                    mma_f16(acc[mt][nt], a[mt], b[nt]);
        }
        __syncthreads();
        if (ch + 2 < nch && tid == 0) {
            const uint32_t mb = (buf == 0) ? mbar : mbar + 8;
            EXPECT_TX(mb, 2 * TTILE);
            tma2d(sbase + (uint32_t)(buf * 2 + 0) * TTILE, tmA, (ch + 2) * 64, m0, mb);
            tma2d(sbase + (uint32_t)(buf * 2 + 1) * TTILE, tmB, (ch + 2) * 64, n0, mb);
        }
    }

    const int rbase = m0 + wm * 64 + (lid >> 2);
    const int cbase = n0 + wn * 32 + (lid & 3) * 2;
#pragma unroll
    for (int mt = 0; mt < 4; mt++) {
#pragma unroll
        for (int nt = 0; nt < 4; nt++) {
            int r = rbase + mt * 16;
            int c = cbase + nt * 8;
            float bx = __ldg(&bias[c]), by = __ldg(&bias[c + 1]);
            float v00 = acc[mt][nt][0] + bx, v01 = acc[mt][nt][1] + by;
            float v10 = acc[mt][nt][2] + bx, v11 = acc[mt][nt][3] + by;
            if (HALF_OUT) {
                *(__half2*)&Ch[(size_t)r * N + c] = __floats2half2_rn(v00, v01);
                *(__half2*)&Ch[(size_t)(r + 8) * N + c] = __floats2half2_rn(v10, v11);
            } else {
                *(float2*)&C[(size_t)r * N + c] = make_float2(v00, v01);
                *(float2*)&C[(size_t)(r + 8) * N + c] = make_float2(v10, v11);
            }
        }
    }
}

__global__ __launch_bounds__(256, 2)
void mma_gemm_qkv_kernel(const __grid_constant__ CUtensorMap tmA,
                         const __grid_constant__ CUtensorMap tmBQ,
                         const __grid_constant__ CUtensorMap tmBK,
                         const __grid_constant__ CUtensorMap tmBV,
                         const float* __restrict__ biasQ, __half* __restrict__ QC,
                         const float* __restrict__ biasK, __half* __restrict__ KC,
                         const float* __restrict__ biasV, __half* __restrict__ VC)
{
    extern __shared__ char smg[];
    const int bx = blockIdx.x;
    if (bx < 16)
        gemm_body<true>(&tmA, &tmBQ, biasQ, nullptr, QC, bx, HID, smg);
    else if (bx < 20)
        gemm_body<true>(&tmA, &tmBK, biasK, nullptr, KC, bx - 16, KVDIM, smg);
    else
        gemm_body<true>(&tmA, &tmBV, biasV, nullptr, VC, bx - 20, KVDIM, smg);
}

__global__ __launch_bounds__(256, 2)
void mma_gemm_o_kernel(const __grid_constant__ CUtensorMap tmA,
                       const __grid_constant__ CUtensorMap tmB,
                       const float* __restrict__ bias,
                       float* __restrict__ C)
{
    extern __shared__ char smg[];
    gemm_body<false>(&tmA, &tmB, bias, C, nullptr, blockIdx.x, HID, smg);
}

// ---------------------------------------------------------------------------
// TMA flash attention (causal GQA), pure fp16, double-buffered KV via TMA.
// CTA: 64 Q rows, 4 warps. Q/K/V tiles are 2 SW128 halves (64 rows x 128 B).
// ---------------------------------------------------------------------------
constexpr int FH = 8192;                      // half tile: 64 rows x 128 B
constexpr int F_OFF_Q  = 0;                   // 2 halves = 16384
constexpr int F_OFF_KV = 2 * FH;              // per buf: K0,K1,V0,V1 = 32768
constexpr int F_KVBUF  = 4 * FH;
constexpr int F_OFF_BAR = F_OFF_KV + 2 * F_KVBUF;   // 81920
constexpr int FLASH_SMEM = F_OFF_BAR + 64;          // 81984
constexpr float SM_SCALE = 0.08838834764831845f;

__global__ __launch_bounds__(128, 2)
void flash_mma_kernel(const __grid_constant__ CUtensorMap tmQ,
                      const __grid_constant__ CUtensorMap tmK,
                      const __grid_constant__ CUtensorMap tmV,
                      __half* __restrict__ O)
{
    extern __shared__ __half shb[];
    const uint32_t sb = smem_u32(shb);
    const int tid = threadIdx.x;
    const int w = tid >> 5, lid = tid & 31;
    const int rq = lid >> 2, cq = lid & 3;
    const int qt = gridDim.x - 1 - blockIdx.x;     // reversed: big work first
    const int h = blockIdx.y, b = blockIdx.z;
    const int g = h >> 2;
    const int q0 = qt * 64;
    const uint32_t qbar = sb + F_OFF_BAR;
    const uint32_t kbar = qbar + 16;               // two KV barriers at +16, +24

    if (tid == 0) {
        MBAR_INIT(qbar, 1);
        MBAR_INIT(kbar, 1);
        MBAR_INIT(kbar + 8, 1);
    }
    __syncthreads();

    const int nkt = qt + 1;

    auto issue_kv = [&](int kt) {
        const uint32_t bb = sb + F_OFF_KV + (uint32_t)(kt & 1) * F_KVBUF;
        const uint32_t mb = kbar + (uint32_t)(kt & 1) * 8;
        const int y = b * SEQ + kt * 64;
        EXPECT_TX(mb, 4 * FH);
        tma2d(bb + 0 * FH, &tmK, g * HDIM,      y, mb);
        tma2d(bb + 1 * FH, &tmK, g * HDIM + 64, y, mb);
        tma2d(bb + 2 * FH, &tmV, g * HDIM,      y, mb);
        tma2d(bb + 3 * FH, &tmV, g * HDIM + 64, y, mb);
    };

    if (tid == 0) {
        EXPECT_TX(qbar, 2 * FH);
        tma2d(sb + F_OFF_Q + 0 * FH, &tmQ, h * HDIM,      b * SEQ + q0, qbar);
        tma2d(sb + F_OFF_Q + 1 * FH, &tmQ, h * HDIM + 64, b * SEQ + q0, qbar);
        issue_kv(0);
        if (nkt > 1) issue_kv(1);
    }
    MBAR_WAIT(qbar, 0);

    float oacc[16][4];
#pragma unroll
    for (int nt = 0; nt < 16; nt++)
#pragma unroll
        for (int j = 0; j < 4; j++) oacc[nt][j] = 0.f;
    float m0 = -INFINITY, m1 = -INFINITY, l0 = 0.f, l1 = 0.f;

    const int iwmin = q0 + w * 16;
    const int i0 = iwmin + rq;
    const int laneRow = (lid & 7) + ((lid >> 3) & 1) * 8;
    const int cl = lid >> 4;
    const uint32_t xorv = (uint32_t)(lid & 7) << 4;

    uint32_t ph0 = 0, ph1 = 0;

    for (int kt = 0; kt < nkt; kt++) {
        const int k0 = kt * 64;
        if ((kt & 1) == 0) { MBAR_WAIT(kbar, ph0); ph0 ^= 1; }
        else               { MBAR_WAIT(kbar + 8, ph1); ph1 ^= 1; }

        const uint32_t kvb = sb + F_OFF_KV + (uint32_t)(kt & 1) * F_KVBUF;

        // ---- S = Q K^T ----
        float sacc[8][4];
#pragma unroll
        for (int nt = 0; nt < 8; nt++)
#pragma unroll
            for (int j = 0; j < 4; j++) sacc[nt][j] = 0.f;

#pragma unroll
        for (int ks = 0; ks < 8; ks++) {
            const uint32_t hk = (uint32_t)(ks >> 2) * FH;
            const uint32_t cb = (((uint32_t)(ks & 3) * 32 + cl * 16)) ^ xorv;
            uint32_t a[4], bK[8][2];
            LDMX4(a[0], a[1], a[2], a[3],
                  sb + F_OFF_Q + hk + (w * 16 + laneRow) * 128 + cb);
#pragma unroll
            for (int j = 0; j < 4; j++) {
                uint32_t t0, t1, t2, t3;
                LDMX4(t0, t1, t2, t3,
                      kvb + hk + (j * 16 + laneRow) * 128 + cb);
                bK[2 * j][0] = t0; bK[2 * j][1] = t2;
                bK[2 * j + 1][0] = t1; bK[2 * j + 1][1] = t3;
            }
#pragma unroll
            for (int nt = 0; nt < 8; nt++)
                mma_f16(sacc[nt], a, bK[nt]);
        }

        // ---- scale + causal mask ----
        const bool need_mask = (k0 + 63) > iwmin;
#pragma unroll
        for (int nt = 0; nt < 8; nt++) {
#pragma unroll
            for (int j = 0; j < 4; j++) {
                float s = sacc[nt][j] * SM_SCALE;
                if (need_mask) {
                    int jj = k0 + nt * 8 + cq * 2 + (j & 1);
                    int ii = i0 + ((j >> 1) << 3);
                    if (jj > ii) s = -1e30f;
                }
                sacc[nt][j] = s;
            }
        }

        // ---- online softmax ----
        float mx0 = -INFINITY, mx1 = -INFINITY;
#pragma unroll
        for (int nt = 0; nt < 8; nt++) {
            mx0 = fmaxf(mx0, fmaxf(sacc[nt][0], sacc[nt][1]));
            mx1 = fmaxf(mx1, fmaxf(sacc[nt][2], sacc[nt][3]));
        }
        mx0 = fmaxf(mx0, __shfl_xor_sync(0xffffffffu, mx0, 1));
        mx0 = fmaxf(mx0, __shfl_xor_sync(0xffffffffu, mx0, 2));
        mx1 = fmaxf(mx1, __shfl_xor_sync(0xffffffffu, mx1, 1));
        mx1 = fmaxf(mx1, __shfl_xor_sync(0xffffffffu, mx1, 2));
        float mn0 = fmaxf(m0, mx0), mn1 = fmaxf(m1, mx1);
        float al0 = __expf(m0 - mn0), al1 = __expf(m1 - mn1);
        m0 = mn0; m1 = mn1;

        float ls0 = 0.f, ls1 = 0.f;
#pragma unroll
        for (int nt = 0; nt < 8; nt++) {
            float p0 = __expf(sacc[nt][0] - mn0);
            float p1 = __expf(sacc[nt][1] - mn0);
            float p2 = __expf(sacc[nt][2] - mn1);
            float p3 = __expf(sacc[nt][3] - mn1);
            ls0 += p0 + p1; ls1 += p2 + p3;
            sacc[nt][0] = p0; sacc[nt][1] = p1; sacc[nt][2] = p2; sacc[nt][3] = p3;
        }
        ls0 += __shfl_xor_sync(0xffffffffu, ls0, 1);
        ls0 += __shfl_xor_sync(0xffffffffu, ls0, 2);
        ls1 += __shfl_xor_sync(0xffffffffu, ls1, 1);
        ls1 += __shfl_xor_sync(0xffffffffu, ls1, 2);
        l0 = l0 * al0 + ls0;
        l1 = l1 * al1 + ls1;

#pragma unroll
        for (int nt = 0; nt < 16; nt++) {
            oacc[nt][0] *= al0; oacc[nt][1] *= al0;
            oacc[nt][2] *= al1; oacc[nt][3] *= al1;
        }

        // ---- O += P V ----
        const uint32_t Vb = kvb + 2 * FH;
#pragma unroll
        for (int ks = 0; ks < 4; ks++) {
            uint32_t aP[4];
#pragma unroll
            for (int half = 0; half < 2; half++) {
                const float* p = sacc[2 * ks + half];
                aP[2 * half + 0] = packh(p[0], p[1]);
                aP[2 * half + 1] = packh(p[2], p[3]);
            }
            uint32_t bv[8][4];
#pragma unroll
            for (int ntp = 0; ntp < 8; ntp++) {
                const uint32_t hv = (uint32_t)(ntp >> 2) * FH;
                const uint32_t cb2 = (((uint32_t)(ntp & 3) * 32 + cl * 16)) ^ xorv;
                const uint32_t va = Vb + hv + (ks * 16 + (lid & 15)) * 128 + cb2;
                LDMX4T(bv[ntp][0], bv[ntp][1], bv[ntp][2], bv[ntp][3], va);
            }
#pragma unroll
            for (int ntp = 0; ntp < 8; ntp++) {
                mma_f16(oacc[2 * ntp + 0], aP, &bv[ntp][0]);
                mma_f16(oacc[2 * ntp + 1], aP, &bv[ntp][2]);
            }
        }

        __syncthreads();                 // all reads of this buf done
        if (kt + 2 < nkt && tid == 0)
            issue_kv(kt + 2);
    }

    // ---- normalize + store ----
    const float rl0 = 1.f / l0, rl1 = 1.f / l1;
    const size_t row0 = (size_t)(b * SEQ + q0 + w * 16 + rq);
#pragma unroll
    for (int nt = 0; nt < 16; nt++) {
        int col = h * HDIM + nt * 8 + cq * 2;
        *(__half2*)&O[row0 * HID + col] =
            __floats2half2_rn(oacc[nt][0] * rl0, oacc[nt][1] * rl0);
        *(__half2*)&O[(row0 + 8) * HID + col] =
            __floats2half2_rn(oacc[nt][2] * rl1, oacc[nt][3] * rl1);
    }
}

// ---------------------------------------------------------------------------
// Host: tensor map construction
// ---------------------------------------------------------------------------
typedef CUresult (*PFN_tmenc)(
    CUtensorMap*, CUtensorMapDataType, cuuint32_t, void*,
    const cuuint64_t*, const cuuint64_t*, const cuuint32_t*, const cuuint32_t*,
    CUtensorMapInterleave, CUtensorMapSwizzle, CUtensorMapL2promotion,
    CUtensorMapFloatOOBfill);

static void make_map(PFN_tmenc enc, CUtensorMap* tm, void* ptr,
                     unsigned long long inner, unsigned long long outer,
                     unsigned boxOuter)
{
    cuuint64_t dims[2] = {inner, outer};
    cuuint64_t strides[1] = {inner * 2};
    cuuint32_t box[2] = {64, boxOuter};
    cuuint32_t estr[2] = {1, 1};
    enc(tm, CU_TENSOR_MAP_DATA_TYPE_FLOAT16, 2, ptr, dims, strides, box, estr,
        CU_TENSOR_MAP_INTERLEAVE_NONE, CU_TENSOR_MAP_SWIZZLE_128B,
        CU_TENSOR_MAP_L2_PROMOTION_L2_128B, CU_TENSOR_MAP_FLOAT_OOB_FILL_NONE);
}

extern "C" void kernel_launch(void* const* d_in, const int* in_sizes, int n_in,
                              void* d_out, int out_size)
{
    const float* x  = (const float*)d_in[0];
    const float* Wq = (const float*)d_in[2];
    const float* bq = (const float*)d_in[3];
    const float* Wk = (const float*)d_in[4];
    const float* bk = (const float*)d_in[5];
    const float* Wv = (const float*)d_in[6];
    const float* bv = (const float*)d_in[7];
    const float* Wo = (const float*)d_in[8];
    const float* bo = (const float*)d_in[9];
    float* out = (float*)d_out;

    __half *X, *Q, *K, *V, *AO, *WqT, *WkT, *WvT, *WoT;
    cudaGetSymbolAddress((void**)&X, g_X);
    cudaGetSymbolAddress((void**)&Q, g_Q);
    cudaGetSymbolAddress((void**)&K, g_K);
    cudaGetSymbolAddress((void**)&V, g_V);
    cudaGetSymbolAddress((void**)&AO, g_AO);
    cudaGetSymbolAddress((void**)&WqT, g_WqT);
    cudaGetSymbolAddress((void**)&WkT, g_WkT);
    cudaGetSymbolAddress((void**)&WvT, g_WvT);
    cudaGetSymbolAddress((void**)&WoT, g_WoT);

    void* fn = nullptr;
    cudaDriverEntryPointQueryResult qr;
    cudaGetDriverEntryPoint("cuTensorMapEncodeTiled", &fn,
                            cudaEnableDefault, &qr);
    PFN_tmenc enc = (PFN_tmenc)fn;

    CUtensorMap tmX, tmWq, tmWk, tmWv, tmAO, tmWo, tmQf, tmKf, tmVf;
    make_map(enc, &tmX,  X,   HID, MROWS, 128);
    make_map(enc, &tmWq, WqT, HID, HID,   128);
    make_map(enc, &tmWk, WkT, HID, KVDIM, 128);
    make_map(enc, &tmWv, WvT, HID, KVDIM, 128);
    make_map(enc, &tmAO, AO,  HID, MROWS, 128);
    make_map(enc, &tmWo, WoT, HID, HID,   128);
    make_map(enc, &tmQf, Q,   HID,   MROWS, 64);
    make_map(enc, &tmKf, K,   KVDIM, MROWS, 64);
    make_map(enc, &tmVf, V,   KVDIM, MROWS, 64);

    cudaFuncSetAttribute(mma_gemm_qkv_kernel,
                         cudaFuncAttributeMaxDynamicSharedMemorySize, GEMM_SMEM);
    cudaFuncSetAttribute(mma_gemm_o_kernel,
                         cudaFuncAttributeMaxDynamicSharedMemorySize, GEMM_SMEM);
    cudaFuncSetAttribute(flash_mma_kernel,
                         cudaFuncAttributeMaxDynamicSharedMemorySize, FLASH_SMEM);

    // 1) prep
    convert_kernel<<<(MROWS * HID / 4 + 255) / 256, 256>>>(x, X, MROWS * HID / 4);
    transpose_all_kernel<<<dim3(HID / 32, HID / 32, 4), 256>>>(
        Wq, WqT, Wk, WkT, Wv, WvT, Wo, WoT);

    // 2) fused Q+K+V projection (TMA)
    mma_gemm_qkv_kernel<<<dim3(24, MROWS / 128), 256, GEMM_SMEM>>>(
        tmX, tmWq, tmWk, tmWv, bq, Q, bk, K, bv, V);

    // 3) attention (TMA)
    flash_mma_kernel<<<dim3(SEQ / 64, NHEADS, BATCH), 128, FLASH_SMEM>>>(
        tmQf, tmKf, tmVf, AO);

    // 4) output projection (TMA)
    mma_gemm_o_kernel<<<dim3(HID / 128, MROWS / 128), 256, GEMM_SMEM>>>(
        tmAO, tmWo, bo, out);
}